// round 10
// baseline (speedup 1.0000x reference)
#include <cuda_runtime.h>
#include <cuda_bf16.h>
#include <cstdint>

// ---------------------------------------------------------------------------
// Problem constants
// ---------------------------------------------------------------------------
#define H 64
#define NNODES 40000
#define NE 60000
#define NC5 30000
#define NC6 25000
#define E_ROWS (2 * NE)      // 120000
#define C5_ROWS (5 * NC5)    // 150000
#define C6_ROWS (6 * NC6)    // 150000
#define EPS 1e-5f

#define PAD_N  40064
#define PAD_R  30080
#define PAD_F  150016

#define EPI_PLAIN 0
#define EPI_STATS 1
#define LD_PLAIN 0
#define LD_CYC   1
#define LD_EDGE  2

// ---------------------------------------------------------------------------
// Device scratch
// ---------------------------------------------------------------------------
__device__ float g_node64[NNODES * 66];   // node64 | cnt5 | cnt6
__device__ float g_n128_5[NNODES * 128];
__device__ float g_n128_6[NNODES * 128];
__device__ float g_b2_5[NC5 * 128];
__device__ float g_b2_6[NC6 * 128];
__device__ float g_nodeS[NNODES * 320];
__device__ float g_B[PAD_N * 128];
__device__ float g_Bm[PAD_N * 128];
__device__ float g_P[PAD_N * 128];
__device__ float g_R[PAD_R * 128];
__device__ float g_F[PAD_F * 128];
__device__ float g_z[PAD_F * 64];
__device__ float g_wE1[704 * 128];        // fragment-permuted tf32
__device__ float g_wE2[128 * 64];
__device__ float g_wC1[320 * 128];
__device__ float g_wC2[128 * 64];
__device__ float g_stats[256];
__device__ float g_scale1[128];
__device__ float g_shift1[128];
__device__ float g_scale2[64];
__device__ float g_shift2[64];

// ---------------------------------------------------------------------------
// Helpers
// ---------------------------------------------------------------------------
__device__ __forceinline__ uint32_t smem_u32(const void* p) {
    uint32_t a;
    asm("{ .reg .u64 t; cvta.to.shared.u64 t, %1; cvt.u32.u64 %0, t; }"
        : "=r"(a) : "l"(p));
    return a;
}

__device__ __forceinline__ float f2tf(float x) {
    uint32_t r;
    asm("cvt.rna.tf32.f32 %0, %1;" : "=r"(r) : "f"(x));
    return __uint_as_float(r);
}

__device__ __forceinline__ uint32_t f2tf_u(float x) {
    uint32_t r;
    asm("cvt.rna.tf32.f32 %0, %1;" : "=r"(r) : "f"(x));
    return r;
}

__device__ __forceinline__ void cp16(uint32_t dst, const void* src, int nbytes) {
    asm volatile("cp.async.ca.shared.global [%0], [%1], 16, %2;"
                 :: "r"(dst), "l"(src), "r"(nbytes) : "memory");
}
__device__ __forceinline__ void cp_commit() {
    asm volatile("cp.async.commit_group;" ::: "memory");
}
__device__ __forceinline__ void cp_wait1() {
    asm volatile("cp.async.wait_group 1;" ::: "memory");
}

__device__ __forceinline__ void mma_tf32(float* d, const uint32_t* a,
                                         const uint32_t* b) {
    asm volatile(
        "mma.sync.aligned.m16n8k8.row.col.f32.tf32.tf32.f32 "
        "{%0,%1,%2,%3}, {%4,%5,%6,%7}, {%8,%9}, {%0,%1,%2,%3};"
        : "+f"(d[0]), "+f"(d[1]), "+f"(d[2]), "+f"(d[3])
        : "r"(a[0]), "r"(a[1]), "r"(a[2]), "r"(a[3]), "r"(b[0]), "r"(b[1]));
}

// ---------------------------------------------------------------------------
// Weight permutation to HMMA fragment order (tf32-rounded).
// ---------------------------------------------------------------------------
__global__ void permute_w(const float* __restrict__ W, float* __restrict__ wp,
                          int K, int N) {
    int idx = blockIdx.x * blockDim.x + threadIdx.x;
    if (idx >= K * N) return;
    int pair = idx & 63;
    int lane = pair >> 1, c = pair & 1;
    int rest = idx >> 6;
    int jn = rest % (N >> 3);
    int ks = rest / (N >> 3);
    int k = ks * 8 + (lane & 3) + 4 * c;
    int n = jn * 8 + (lane >> 2);
    wp[idx] = f2tf(W[(size_t)k * N + n]);
}

// ---------------------------------------------------------------------------
// tf32 mma.sync GEMM. BM=128, 256 threads, 8 warps (4Mx2N).
// B fragments loaded directly from permuted weights (register dbuf).
// LOADER = LD_PLAIN : A via cp.async (double-buffered smem)
//          LD_CYC   : A composed on the fly: A1[r] + T1[atoms[r]] + T2[r/G]
//          LD_EDGE  : A1[r] + T1[self] + T2[a0] + T2[a1]
// Composed loaders: each thread owns 4 row-slices (row = (tid>>3) + 32j),
// register prefetch -> smem stage (double-buffered).
// APPLY_IN: BN+ReLU on A at fragment load. EPI_STATS: col stats of valid rows.
// ---------------------------------------------------------------------------
template <int BN, bool APPLY_IN, int EPI, int LOADER, int G = 1>
__global__ void __launch_bounds__(256)
gemm_mma(const float* __restrict__ A1, const float* __restrict__ Wp,
         float* __restrict__ C, int M, int K,
         const float* __restrict__ inScale,
         const float* __restrict__ inShift,
         const int* __restrict__ atoms,
         const float* __restrict__ T1, const float* __restrict__ T2,
         float* __restrict__ stats) {
    constexpr int BM = 128, BK = 32, APAD = 36;
    constexpr int ASZ = BM * APAD;
    constexpr int SOFF = 256;
    constexpr int NT = BN / 16;
    constexpr int KSF = 2 * NT * 64;

    extern __shared__ float sm[];
    const int tid = threadIdx.x;
    const int warp = tid >> 5, lane = tid & 31;
    const int qr = lane >> 2, ql = lane & 3;
    const int wm = warp >> 1, wn = warp & 1;
    const int mBase = blockIdx.x * BM;
    const uint32_t smBase = smem_u32(sm);

    if (APPLY_IN && tid < 128) {
        sm[tid] = tid < K ? inScale[tid] : 0.f;
        sm[128 + tid] = tid < K ? inShift[tid] : 0.f;
    }

    auto issueA = [&](int s, int k0) {  // LD_PLAIN only
        const int so = SOFF + s * ASZ;
#pragma unroll
        for (int j = 0; j < 4; j++) {
            int i = tid + 256 * j;
            int row = i >> 3, ch = i & 7;
            int gr = mBase + row;
            bool ok = gr < M;
            const float* src = A1 + (size_t)(ok ? gr : 0) * K + k0 + ch * 4;
            uint32_t dst = smBase + (uint32_t)(so + row * APAD + ch * 4) * 4;
            cp16(dst, src, ok ? 16 : 0);
        }
    };

    // ---- composed-loader state: 4 row-slices per thread ----
    const int lrow0 = tid >> 3;            // base row (0..31)
    const int lch = (tid & 7) * 4;         // 4 floats within 32-col chunk
    int lidx[4];                           // clamped global row per slice
    int i1[4], i2[4], i3[4];               // gather indices per slice
    if (LOADER != LD_PLAIN) {
#pragma unroll
        for (int j = 0; j < 4; j++) {
            int gr = mBase + lrow0 + 32 * j;
            int rc = gr < M ? gr : 0;
            lidx[j] = rc;
            if (LOADER == LD_CYC) {
                i1[j] = atoms[rc];
                i2[j] = rc / G;
            } else if (LOADER == LD_EDGE) {
                int e = rc >> 1;
                int a0 = atoms[2 * e], a1 = atoms[2 * e + 1];
                i1[j] = (rc & 1) ? a1 : a0;
                i2[j] = a0;
                i3[j] = a1;
            }
        }
    }

    float4 lreg[4];
    auto gatherA = [&](int k0) {
#pragma unroll
        for (int j = 0; j < 4; j++) {
            float4 v = *reinterpret_cast<const float4*>(
                A1 + (size_t)lidx[j] * K + k0 + lch);
            float4 w1 = *reinterpret_cast<const float4*>(
                T1 + (size_t)i1[j] * K + k0 + lch);
            float4 w2 = *reinterpret_cast<const float4*>(
                T2 + (size_t)i2[j] * K + k0 + lch);
            v.x += w1.x + w2.x; v.y += w1.y + w2.y;
            v.z += w1.z + w2.z; v.w += w1.w + w2.w;
            if (LOADER == LD_EDGE) {
                float4 w3 = *reinterpret_cast<const float4*>(
                    T2 + (size_t)i3[j] * K + k0 + lch);
                v.x += w3.x; v.y += w3.y; v.z += w3.z; v.w += w3.w;
            }
            lreg[j] = v;
        }
    };
    auto storeA = [&](int s) {
#pragma unroll
        for (int j = 0; j < 4; j++) {
            float* dst =
                sm + SOFF + s * ASZ + (lrow0 + 32 * j) * APAD + lch;
            dst[0] = lreg[j].x; dst[1] = lreg[j].y;
            dst[2] = lreg[j].z; dst[3] = lreg[j].w;
        }
    };

    const float* wbase = Wp + (wn * NT) * 64 + lane * 2;
    float2 bf[2][NT];
    auto loadB = [&](int buf, int ksg) {
#pragma unroll
        for (int j = 0; j < NT; j++)
            bf[buf][j] = *reinterpret_cast<const float2*>(
                wbase + (size_t)ksg * KSF + j * 64);
    };

    float acc[2][NT][4];
#pragma unroll
    for (int t = 0; t < 2; t++)
#pragma unroll
        for (int j = 0; j < NT; j++)
#pragma unroll
            for (int r = 0; r < 4; r++) acc[t][j][r] = 0.f;

    const int nCh = K / BK;
    const int nKs = K / 8;
    if (LOADER == LD_PLAIN) {
        issueA(0, 0);
        cp_commit();
    } else {
        gatherA(0);
    }
    loadB(0, 0);

    for (int c = 0; c < nCh; c++) {
        if (LOADER == LD_PLAIN) {
            if (c + 1 < nCh) issueA((c + 1) & 1, (c + 1) * BK);
            cp_commit();
            cp_wait1();
            __syncthreads();
        } else {
            storeA(c & 1);
            __syncthreads();
            if (c + 1 < nCh) gatherA((c + 1) * BK);
        }

        const float* Asm = sm + SOFF + (c & 1) * ASZ;
#pragma unroll
        for (int ks = 0; ks < 4; ks++) {
            const int ksg = c * 4 + ks;
            if (ksg + 1 < nKs) loadB((ksg + 1) & 1, ksg + 1);
            const int k = ks * 8;
            float s0 = 1.f, h0 = 0.f, s4 = 1.f, h4 = 0.f;
            if (APPLY_IN) {
                int kc = c * 32 + k + ql;
                s0 = sm[kc];
                h0 = sm[128 + kc];
                s4 = sm[kc + 4];
                h4 = sm[128 + kc + 4];
            }
            uint32_t a[2][4];
#pragma unroll
            for (int t = 0; t < 2; t++) {
                const float* p = Asm + (wm * 32 + t * 16 + qr) * APAD + k + ql;
                float v0 = p[0], v1 = p[8 * APAD], v2 = p[4],
                      v3 = p[8 * APAD + 4];
                if (APPLY_IN) {
                    v0 = fmaxf(fmaf(v0, s0, h0), 0.f);
                    v1 = fmaxf(fmaf(v1, s0, h0), 0.f);
                    v2 = fmaxf(fmaf(v2, s4, h4), 0.f);
                    v3 = fmaxf(fmaf(v3, s4, h4), 0.f);
                }
                a[t][0] = f2tf_u(v0);
                a[t][1] = f2tf_u(v1);
                a[t][2] = f2tf_u(v2);
                a[t][3] = f2tf_u(v3);
            }
            const float2* bc = bf[ksg & 1];
#pragma unroll
            for (int t = 0; t < 2; t++)
#pragma unroll
                for (int j = 0; j < NT; j++) {
                    uint32_t b2r[2] = {__float_as_uint(bc[j].x),
                                       __float_as_uint(bc[j].y)};
                    mma_tf32(acc[t][j], a[t], b2r);
                }
        }
        __syncthreads();
    }

    // ------------------ epilogue ------------------
    float ps[2 * NT], pq[2 * NT];
    if (EPI == EPI_STATS) {
#pragma unroll
        for (int i = 0; i < 2 * NT; i++) { ps[i] = 0.f; pq[i] = 0.f; }
    }

#pragma unroll
    for (int t = 0; t < 2; t++) {
#pragma unroll
        for (int rr = 0; rr < 2; rr++) {
            int row = mBase + wm * 32 + t * 16 + 8 * rr + qr;
            bool valid = row < M;
#pragma unroll
            for (int j = 0; j < NT; j++) {
                int n0 = wn * (BN / 2) + j * 8 + 2 * ql;
                float v0 = acc[t][j][2 * rr];
                float v1 = acc[t][j][2 * rr + 1];
                *reinterpret_cast<float2*>(&C[(size_t)row * BN + n0]) =
                    make_float2(v0, v1);
                if (EPI == EPI_STATS && valid) {
                    ps[2 * j] += v0;
                    pq[2 * j] += v0 * v0;
                    ps[2 * j + 1] += v1;
                    pq[2 * j + 1] += v1 * v1;
                }
            }
        }
    }

    if (EPI == EPI_STATS) {
        __syncthreads();
        for (int i = tid; i < 2 * BN; i += 256) sm[i] = 0.f;
        __syncthreads();
#pragma unroll
        for (int j = 0; j < NT; j++) {
            int n0 = wn * (BN / 2) + j * 8 + 2 * ql;
            atomicAdd(&sm[n0], ps[2 * j]);
            atomicAdd(&sm[n0 + 1], ps[2 * j + 1]);
            atomicAdd(&sm[BN + n0], pq[2 * j]);
            atomicAdd(&sm[BN + n0 + 1], pq[2 * j + 1]);
        }
        __syncthreads();
        if (tid < BN) {
            atomicAdd(&stats[tid], sm[tid]);
            atomicAdd(&stats[128 + tid], sm[BN + tid]);
        }
    }
}

// ---------------------------------------------------------------------------
// Memory-phase kernels
// ---------------------------------------------------------------------------
__global__ void zero_kernel(float* __restrict__ p, size_t n) {
    size_t i = (size_t)blockIdx.x * blockDim.x + threadIdx.x;
    if (i < n) p[i] = 0.f;
}

__global__ void count_atoms(const int* __restrict__ atoms,
                            float* __restrict__ cnt, int rows) {
    int i = blockIdx.x * blockDim.x + threadIdx.x;
    if (i < rows) atomicAdd(&cnt[atoms[i]], 1.f);
}

__global__ void scatter_add4(const float* __restrict__ src,
                             const int* __restrict__ atoms,
                             float* __restrict__ node, int rows, int C) {
    int C4 = C >> 2;
    int idx = blockIdx.x * blockDim.x + threadIdx.x;
    if (idx >= rows * C4) return;
    int r = idx / C4;
    int c = (idx - r * C4) << 2;
    float4 v = *reinterpret_cast<const float4*>(&src[(size_t)r * C + c]);
    float* dst = &node[(size_t)atoms[r] * C + c];
    atomicAdd(dst + 0, v.x);
    atomicAdd(dst + 1, v.y);
    atomicAdd(dst + 2, v.z);
    atomicAdd(dst + 3, v.w);
}

template <int G>
__global__ void bc_gather(const float* __restrict__ node,
                          const int* __restrict__ atoms,
                          float* __restrict__ out, int nCyc, int C) {
    int idx = blockIdx.x * blockDim.x + threadIdx.x;
    if (idx >= nCyc * C) return;
    int i = idx / C;
    int c = idx - i * C;
    float s = 0.f;
#pragma unroll
    for (int k = 0; k < G; k++) s += node[(size_t)atoms[i * G + k] * C + c];
    out[(size_t)i * C + c] = s;
}

// fused bc + scatter for b1
template <int G>
__global__ void bc_scatter(const float* __restrict__ node64,
                           const int* __restrict__ atoms,
                           float* __restrict__ n128, int nCyc) {
    int idx = blockIdx.x * blockDim.x + threadIdx.x;
    if (idx >= nCyc * 64) return;
    int i = idx >> 6;
    int c = idx & 63;
    int a[G];
    float s = 0.f;
#pragma unroll
    for (int k = 0; k < G; k++) {
        a[k] = atoms[i * G + k];
        s += node64[(size_t)a[k] * 64 + c];
    }
#pragma unroll
    for (int k = 0; k < G; k++)
        atomicAdd(&n128[(size_t)a[k] * 128 + 64 + c], s);
}

__global__ void init_node128(const float* __restrict__ node64,
                             const float* __restrict__ cnt,
                             float* __restrict__ node128) {
    int idx = blockIdx.x * blockDim.x + threadIdx.x;
    if (idx >= NNODES * 64) return;
    int a = idx >> 6, c = idx & 63;
    float s = cnt[a];
    node128[(size_t)a * 128 + c] = s * node64[(size_t)a * 64 + c];
    node128[(size_t)a * 128 + 64 + c] = 0.f;
}

__global__ void init_nodeS(const float* __restrict__ n5,
                           const float* __restrict__ n6,
                           const float* __restrict__ c5,
                           const float* __restrict__ c6,
                           float* __restrict__ nodeS) {
    int idx = blockIdx.x * blockDim.x + threadIdx.x;
    if (idx >= NNODES * 320) return;
    int a = idx / 320, c = idx - a * 320;
    float v = 0.f;
    if (c < 128)
        v = c5[a] * n5[(size_t)a * 128 + c] + c6[a] * n6[(size_t)a * 128 + c];
    nodeS[idx] = v;
}

template <int G>
__global__ void scatter_grp4(const float* __restrict__ src,
                             const int* __restrict__ atoms,
                             float* __restrict__ dst, int rows, int C,
                             int pitch, int off) {
    int C4 = C >> 2;
    int idx = blockIdx.x * blockDim.x + threadIdx.x;
    if (idx >= rows * C4) return;
    int r = idx / C4;
    int c = (idx - r * C4) << 2;
    float4 v =
        *reinterpret_cast<const float4*>(&src[(size_t)(r / G) * C + c]);
    float* d = &dst[(size_t)atoms[r] * pitch + off + c];
    atomicAdd(d + 0, v.x);
    atomicAdd(d + 1, v.y);
    atomicAdd(d + 2, v.z);
    atomicAdd(d + 3, v.w);
}

// stats-only composes (no h write)
__global__ void stats_edge(const float* __restrict__ F,
                           const float* __restrict__ B,
                           const float* __restrict__ Bm,
                           const int* __restrict__ atoms,
                           float* __restrict__ stats) {
    int c = threadIdx.x;  // 128
    float s = 0.f, q = 0.f;
    for (int r = blockIdx.x; r < E_ROWS; r += gridDim.x) {
        int e = r >> 1;
        int a0 = atoms[2 * e], a1 = atoms[2 * e + 1];
        int self = (r & 1) ? a1 : a0;
        float v = F[(size_t)r * 128 + c] + B[(size_t)self * 128 + c] +
                  Bm[(size_t)a0 * 128 + c] + Bm[(size_t)a1 * 128 + c];
        s += v;
        q += v * v;
    }
    atomicAdd(&stats[c], s);
    atomicAdd(&stats[128 + c], q);
}

template <int G>
__global__ void stats_cyc(const float* __restrict__ F,
                          const float* __restrict__ P,
                          const float* __restrict__ R,
                          const int* __restrict__ atoms, int rows,
                          float* __restrict__ stats) {
    int c = threadIdx.x;  // 128
    float s = 0.f, q = 0.f;
    for (int r = blockIdx.x; r < rows; r += gridDim.x) {
        float v = F[(size_t)r * 128 + c] + P[(size_t)atoms[r] * 128 + c] +
                  R[(size_t)(r / G) * 128 + c];
        s += v;
        q += v * v;
    }
    atomicAdd(&stats[c], s);
    atomicAdd(&stats[128 + c], q);
}

__global__ void make_scaleshift(const float* __restrict__ stats,
                                const float* __restrict__ g,
                                const float* __restrict__ b,
                                float* __restrict__ scale,
                                float* __restrict__ shift, int C, float invM) {
    int j = blockIdx.x * blockDim.x + threadIdx.x;
    if (j >= C) return;
    float m = stats[j] * invM;
    float v = stats[128 + j] * invM - m * m;
    v = fmaxf(v, 0.f);
    float s = g[j] * rsqrtf(v + EPS);
    scale[j] = s;
    shift[j] = b[j] - m * s;
}

__global__ void bn_relu_out(const float* __restrict__ z,
                            const float* __restrict__ scale,
                            const float* __restrict__ shift,
                            float* __restrict__ out, size_t n, int C) {
    size_t idx = (size_t)blockIdx.x * blockDim.x + threadIdx.x;
    if (idx >= n) return;
    int c = (int)(idx % C);
    out[idx] = fmaxf(z[idx] * scale[c] + shift[c], 0.f);
}

// ---------------------------------------------------------------------------
// Host orchestration
// ---------------------------------------------------------------------------
static inline int cdiv(int a, int b) { return (a + b - 1) / b; }

static float* sym_addr(const void* s) {
    void* p = nullptr;
    cudaGetSymbolAddress(&p, s);
    return (float*)p;
}

static const int SMEM_G = (256 + 2 * 128 * 36) * 4;  // 37888 B

extern "C" void kernel_launch(void* const* d_in, const int* in_sizes, int n_in,
                              void* d_out, int out_size) {
    const float* edge_feats = (const float*)d_in[0];
    const float* c5_feats = (const float*)d_in[1];
    const float* c6_feats = (const float*)d_in[2];
    const int* e_atoms = (const int*)d_in[3];
    const int* c5_atoms = (const int*)d_in[4];
    const int* c6_atoms = (const int*)d_in[5];
    const float* eW1 = (const float*)d_in[6];
    const float* eg1 = (const float*)d_in[7];
    const float* eb1 = (const float*)d_in[8];
    const float* eW2 = (const float*)d_in[9];
    const float* eg2 = (const float*)d_in[10];
    const float* eb2 = (const float*)d_in[11];
    const float* cW1 = (const float*)d_in[12];
    const float* cg1 = (const float*)d_in[13];
    const float* cb1 = (const float*)d_in[14];
    const float* cW2 = (const float*)d_in[15];
    const float* cg2 = (const float*)d_in[16];
    const float* cb2 = (const float*)d_in[17];

    float* out_edge = (float*)d_out;
    float* out_c5 = out_edge + (size_t)E_ROWS * H;
    float* out_c6 = out_c5 + (size_t)C5_ROWS * H;

    float* node64 = sym_addr(g_node64);
    float* cnt5 = node64 + NNODES * 64;
    float* cnt6 = node64 + NNODES * 65;
    float* n128_5 = sym_addr(g_n128_5);
    float* n128_6 = sym_addr(g_n128_6);
    float* b2_5 = sym_addr(g_b2_5);
    float* b2_6 = sym_addr(g_b2_6);
    float* nodeS = sym_addr(g_nodeS);
    float* Bt = sym_addr(g_B);
    float* Bm = sym_addr(g_Bm);
    float* P = sym_addr(g_P);
    float* R = sym_addr(g_R);
    float* F = sym_addr(g_F);
    float* z = sym_addr(g_z);
    float* wE1 = sym_addr(g_wE1);
    float* wE2 = sym_addr(g_wE2);
    float* wC1 = sym_addr(g_wC1);
    float* wC2 = sym_addr(g_wC2);
    float* stats = sym_addr(g_stats);
    float* sc1 = sym_addr(g_scale1);
    float* sh1 = sym_addr(g_shift1);
    float* sc2 = sym_addr(g_scale2);
    float* sh2 = sym_addr(g_shift2);

    const int TB = 256;

    // #1-3 weight permutes; #4 = edge F GEMM (profiled)
    permute_w<<<cdiv(704 * 128, TB), TB>>>(eW1, wE1, 704, 128);
    permute_w<<<cdiv(320 * 128, TB), TB>>>(cW1, wC1, 320, 128);
    permute_w<<<cdiv(128 * 64, TB), TB>>>(eW2, wE2, 128, 64);
    gemm_mma<128, false, EPI_PLAIN, LD_PLAIN><<<cdiv(E_ROWS, 128), 256,
                                                SMEM_G>>>(
        edge_feats, wE1, F, E_ROWS, 64, nullptr, nullptr, nullptr, nullptr,
        nullptr, nullptr);
    permute_w<<<cdiv(128 * 64, TB), TB>>>(cW2, wC2, 128, 64);

    // ---- scatter chain ----
    zero_kernel<<<cdiv(NNODES * 66, TB), TB>>>(node64, (size_t)NNODES * 66);
    scatter_add4<<<cdiv(E_ROWS * 16, TB), TB>>>(edge_feats, e_atoms, node64,
                                                E_ROWS, 64);
    count_atoms<<<cdiv(C5_ROWS, TB), TB>>>(c5_atoms, cnt5, C5_ROWS);
    count_atoms<<<cdiv(C6_ROWS, TB), TB>>>(c6_atoms, cnt6, C6_ROWS);

    init_node128<<<cdiv(NNODES * 64, TB), TB>>>(node64, cnt5, n128_5);
    init_node128<<<cdiv(NNODES * 64, TB), TB>>>(node64, cnt6, n128_6);
    bc_scatter<5><<<cdiv(NC5 * 64, TB), TB>>>(node64, c5_atoms, n128_5, NC5);
    bc_scatter<6><<<cdiv(NC6 * 64, TB), TB>>>(node64, c6_atoms, n128_6, NC6);

    bc_gather<5><<<cdiv(NC5 * 128, TB), TB>>>(n128_5, c5_atoms, b2_5, NC5, 128);
    bc_gather<6><<<cdiv(NC6 * 128, TB), TB>>>(n128_6, c6_atoms, b2_6, NC6, 128);

    init_nodeS<<<cdiv(NNODES * 320, TB), TB>>>(n128_5, n128_6, cnt5, cnt6,
                                               nodeS);
    scatter_grp4<5><<<cdiv(C5_ROWS * 32, TB), TB>>>(b2_5, c5_atoms, nodeS,
                                                    C5_ROWS, 128, 320, 128);
    scatter_grp4<6><<<cdiv(C6_ROWS * 32, TB), TB>>>(b2_6, c6_atoms, nodeS,
                                                    C6_ROWS, 128, 320, 128);
    scatter_grp4<1><<<cdiv(C5_ROWS * 16, TB), TB>>>(c5_feats, c5_atoms, nodeS,
                                                    C5_ROWS, 64, 320, 256);
    scatter_grp4<1><<<cdiv(C6_ROWS * 16, TB), TB>>>(c6_feats, c6_atoms, nodeS,
                                                    C6_ROWS, 64, 320, 256);

    // ================= EDGE MLP =================
    gemm_mma<128, false, EPI_PLAIN, LD_PLAIN><<<cdiv(NNODES, 128), 256,
                                                SMEM_G>>>(
        nodeS, wE1 + 64 * 128, Bt, NNODES, 320, nullptr, nullptr, nullptr,
        nullptr, nullptr, nullptr);
    gemm_mma<128, false, EPI_PLAIN, LD_PLAIN><<<cdiv(NNODES, 128), 256,
                                                SMEM_G>>>(
        nodeS, wE1 + 384 * 128, Bm, NNODES, 320, nullptr, nullptr, nullptr,
        nullptr, nullptr, nullptr);
    zero_kernel<<<1, 256>>>(stats, 256);
    stats_edge<<<2048, 128>>>(F, Bt, Bm, e_atoms, stats);
    make_scaleshift<<<1, 128>>>(stats, eg1, eb1, sc1, sh1, 128, 1.f / E_ROWS);
    zero_kernel<<<1, 256>>>(stats, 256);
    gemm_mma<64, true, EPI_STATS, LD_EDGE><<<cdiv(E_ROWS, 128), 256, SMEM_G>>>(
        F, wE2, z, E_ROWS, 128, sc1, sh1, e_atoms, Bt, Bm, stats);
    make_scaleshift<<<1, 64>>>(stats, eg2, eb2, sc2, sh2, 64, 1.f / E_ROWS);
    bn_relu_out<<<cdiv(E_ROWS * 64, TB), TB>>>(z, sc2, sh2, out_edge,
                                               (size_t)E_ROWS * 64, 64);

    // ================= CYCLE5 MLP =================
    gemm_mma<128, false, EPI_PLAIN, LD_PLAIN><<<cdiv(C5_ROWS, 128), 256,
                                                SMEM_G>>>(
        c5_feats, wC1 + 256 * 128, F, C5_ROWS, 64, nullptr, nullptr, nullptr,
        nullptr, nullptr, nullptr);
    gemm_mma<128, false, EPI_PLAIN, LD_PLAIN><<<cdiv(NNODES, 128), 256,
                                                SMEM_G>>>(
        n128_5, wC1, P, NNODES, 128, nullptr, nullptr, nullptr, nullptr,
        nullptr, nullptr);
    gemm_mma<128, false, EPI_PLAIN, LD_PLAIN><<<cdiv(NC5, 128), 256, SMEM_G>>>(
        b2_5, wC1 + 128 * 128, R, NC5, 128, nullptr, nullptr, nullptr,
        nullptr, nullptr, nullptr);
    zero_kernel<<<1, 256>>>(stats, 256);
    stats_cyc<5><<<2048, 128>>>(F, P, R, c5_atoms, C5_ROWS, stats);
    make_scaleshift<<<1, 128>>>(stats, cg1, cb1, sc1, sh1, 128, 1.f / C5_ROWS);
    zero_kernel<<<1, 256>>>(stats, 256);
    gemm_mma<64, true, EPI_STATS, LD_CYC, 5><<<cdiv(C5_ROWS, 128), 256,
                                               SMEM_G>>>(
        F, wC2, z, C5_ROWS, 128, sc1, sh1, c5_atoms, P, R, stats);
    make_scaleshift<<<1, 64>>>(stats, cg2, cb2, sc2, sh2, 64, 1.f / C5_ROWS);
    bn_relu_out<<<cdiv(C5_ROWS * 64, TB), TB>>>(z, sc2, sh2, out_c5,
                                                (size_t)C5_ROWS * 64, 64);

    // ================= CYCLE6 MLP =================
    gemm_mma<128, false, EPI_PLAIN, LD_PLAIN><<<cdiv(C6_ROWS, 128), 256,
                                                SMEM_G>>>(
        c6_feats, wC1 + 256 * 128, F, C6_ROWS, 64, nullptr, nullptr, nullptr,
        nullptr, nullptr, nullptr);
    gemm_mma<128, false, EPI_PLAIN, LD_PLAIN><<<cdiv(NNODES, 128), 256,
                                                SMEM_G>>>(
        n128_6, wC1, P, NNODES, 128, nullptr, nullptr, nullptr, nullptr,
        nullptr, nullptr);
    gemm_mma<128, false, EPI_PLAIN, LD_PLAIN><<<cdiv(NC6, 128), 256, SMEM_G>>>(
        b2_6, wC1 + 128 * 128, R, NC6, 128, nullptr, nullptr, nullptr,
        nullptr, nullptr, nullptr);
    zero_kernel<<<1, 256>>>(stats, 256);
    stats_cyc<6><<<2048, 128>>>(F, P, R, c6_atoms, C6_ROWS, stats);
    make_scaleshift<<<1, 128>>>(stats, cg1, cb1, sc1, sh1, 128, 1.f / C6_ROWS);
    zero_kernel<<<1, 256>>>(stats, 256);
    gemm_mma<64, true, EPI_STATS, LD_CYC, 6><<<cdiv(C6_ROWS, 128), 256,
                                               SMEM_G>>>(
        F, wC2, z, C6_ROWS, 128, sc1, sh1, c6_atoms, P, R, stats);
    make_scaleshift<<<1, 64>>>(stats, cg2, cb2, sc2, sh2, 64, 1.f / C6_ROWS);
    bn_relu_out<<<cdiv(C6_ROWS * 64, TB), TB>>>(z, sc2, sh2, out_c6,
                                                (size_t)C6_ROWS * 64, 64);

    (void)in_sizes;
    (void)n_in;
    (void)out_size;
}

// round 11
// speedup vs baseline: 1.0601x; 1.0601x over previous
#include <cuda_runtime.h>
#include <cuda_bf16.h>
#include <cstdint>

// ---------------------------------------------------------------------------
// Problem constants
// ---------------------------------------------------------------------------
#define H 64
#define NNODES 40000
#define NE 60000
#define NC5 30000
#define NC6 25000
#define E_ROWS (2 * NE)      // 120000
#define C5_ROWS (5 * NC5)    // 150000
#define C6_ROWS (6 * NC6)    // 150000
#define EPS 1e-5f

#define PAD_N  40064
#define PAD_R  30080
#define PAD_F  150016

// ---------------------------------------------------------------------------
// Device scratch
// ---------------------------------------------------------------------------
__device__ float g_node64[NNODES * 66];   // node64 | cnt5 | cnt6
__device__ float g_n128_5[NNODES * 128];
__device__ float g_n128_6[NNODES * 128];
__device__ float g_b2_5[NC5 * 128];
__device__ float g_b2_6[NC6 * 128];
__device__ float g_nodeS[NNODES * 320];
__device__ float g_B[PAD_N * 128];
__device__ float g_Bm[PAD_N * 128];
__device__ float g_P[PAD_N * 128];
__device__ float g_R[PAD_R * 128];
__device__ float g_F[PAD_F * 128];
__device__ float g_h[PAD_F * 128];
__device__ float g_z[PAD_F * 64];
__device__ float g_wE1[704 * 128];        // tf32-rounded weights
__device__ float g_wE2[128 * 64];
__device__ float g_wC1[320 * 128];
__device__ float g_wC2[128 * 64];
__device__ float g_stats[256];            // [0:128) sum, [128:256) sumsq
__device__ float g_scale1[128];
__device__ float g_shift1[128];
__device__ float g_scale2[64];
__device__ float g_shift2[64];

// ---------------------------------------------------------------------------
// Helpers
// ---------------------------------------------------------------------------
__device__ __forceinline__ uint32_t smem_u32(const void* p) {
    uint32_t a;
    asm("{ .reg .u64 t; cvta.to.shared.u64 t, %1; cvt.u32.u64 %0, t; }"
        : "=r"(a) : "l"(p));
    return a;
}

__device__ __forceinline__ float f2tf(float x) {
    uint32_t r;
    asm("cvt.rna.tf32.f32 %0, %1;" : "=r"(r) : "f"(x));
    return __uint_as_float(r);
}

__device__ __forceinline__ uint32_t f2tf_u(float x) {
    uint32_t r;
    asm("cvt.rna.tf32.f32 %0, %1;" : "=r"(r) : "f"(x));
    return r;
}

__device__ __forceinline__ void cp16(uint32_t dst, const void* src, int nbytes) {
    asm volatile("cp.async.ca.shared.global [%0], [%1], 16, %2;"
                 :: "r"(dst), "l"(src), "r"(nbytes) : "memory");
}
__device__ __forceinline__ void cp_commit() {
    asm volatile("cp.async.commit_group;" ::: "memory");
}
__device__ __forceinline__ void cp_wait1() {
    asm volatile("cp.async.wait_group 1;" ::: "memory");
}

__device__ __forceinline__ void mma_tf32(float* d, const uint32_t* a,
                                         const uint32_t* b) {
    asm volatile(
        "mma.sync.aligned.m16n8k8.row.col.f32.tf32.tf32.f32 "
        "{%0,%1,%2,%3}, {%4,%5,%6,%7}, {%8,%9}, {%0,%1,%2,%3};"
        : "+f"(d[0]), "+f"(d[1]), "+f"(d[2]), "+f"(d[3])
        : "r"(a[0]), "r"(a[1]), "r"(a[2]), "r"(a[3]), "r"(b[0]), "r"(b[1]));
}

// ---------------------------------------------------------------------------
// tf32 mma.sync GEMM, cp.async double-buffered (round-5 / 973us config).
// A:[M,K] raw fp32 (tf32-rounded in-register at fragment load),
// B:[K,BN] pre-rounded fp32, C:[Mpad,BN]. K % 32 == 0.
// 256 threads, 8 warps (4 M x 2 N), BM=128, warp tile 32 x BN/2.
// APPLY_IN: a' = relu(a*inScale[k]+inShift[k]) fused (K<=128).
// ---------------------------------------------------------------------------
template <int BN, bool APPLY_IN>
__global__ void __launch_bounds__(256)
gemm_mma(const float* __restrict__ A, const float* __restrict__ B,
         float* __restrict__ C, int M, int K,
         const float* __restrict__ inScale,
         const float* __restrict__ inShift) {
    constexpr int BM = 128, BK = 32;
    constexpr int APAD = 36;
    constexpr int BPAD = BN + 8;
    constexpr int ASZ = BM * APAD;
    constexpr int BSZ = BK * BPAD;
    constexpr int STG = ASZ + BSZ;
    constexpr int SOFF = 256;
    constexpr int NT = BN / 16;

    extern __shared__ float sm[];
    const int tid = threadIdx.x;
    const int warp = tid >> 5, lane = tid & 31;
    const int qr = lane >> 2, ql = lane & 3;
    const int wm = warp >> 1, wn = warp & 1;
    const int mBase = blockIdx.x * BM;
    const uint32_t smBase = smem_u32(sm);

    if (APPLY_IN && tid < 128) {
        sm[tid] = tid < K ? inScale[tid] : 0.f;
        sm[128 + tid] = tid < K ? inShift[tid] : 0.f;
    }

    auto issue = [&](int s, int k0) {
        const int so = SOFF + s * STG;
#pragma unroll
        for (int j = 0; j < 4; j++) {
            int i = tid + 256 * j;
            int row = i >> 3, ch = i & 7;
            int gr = mBase + row;
            bool ok = gr < M;
            const float* src = A + (size_t)(ok ? gr : 0) * K + k0 + ch * 4;
            uint32_t dst = smBase + (uint32_t)(so + row * APAD + ch * 4) * 4;
            cp16(dst, src, ok ? 16 : 0);
        }
#pragma unroll
        for (int j = 0; j < BK * BN / 4 / 256; j++) {
            int i = tid + 256 * j;
            int row = i / (BN / 4), c = i % (BN / 4);
            const float* src = B + (size_t)(k0 + row) * BN + c * 4;
            uint32_t dst =
                smBase + (uint32_t)(so + ASZ + row * BPAD + c * 4) * 4;
            cp16(dst, src, 16);
        }
    };

    float acc[2][NT][4];
#pragma unroll
    for (int t = 0; t < 2; t++)
#pragma unroll
        for (int j = 0; j < NT; j++)
#pragma unroll
            for (int r = 0; r < 4; r++) acc[t][j][r] = 0.f;

    const int nCh = K / BK;
    issue(0, 0);
    cp_commit();

    for (int c = 0; c < nCh; c++) {
        if (c + 1 < nCh) issue((c + 1) & 1, (c + 1) * BK);
        cp_commit();
        cp_wait1();
        __syncthreads();

        const float* Asm = sm + SOFF + (c & 1) * STG;
        const uint32_t* Bsm = reinterpret_cast<const uint32_t*>(Asm) + ASZ;
#pragma unroll
        for (int ks = 0; ks < 4; ks++) {
            const int k = ks * 8;
            float s0 = 1.f, h0 = 0.f, s4 = 1.f, h4 = 0.f;
            if (APPLY_IN) {
                int kc = c * 32 + k + ql;
                s0 = sm[kc];
                h0 = sm[128 + kc];
                s4 = sm[kc + 4];
                h4 = sm[128 + kc + 4];
            }
            uint32_t a[2][4];
#pragma unroll
            for (int t = 0; t < 2; t++) {
                const float* p = Asm + (wm * 32 + t * 16 + qr) * APAD + k + ql;
                float v0 = p[0], v1 = p[8 * APAD], v2 = p[4],
                      v3 = p[8 * APAD + 4];
                if (APPLY_IN) {
                    v0 = fmaxf(fmaf(v0, s0, h0), 0.f);
                    v1 = fmaxf(fmaf(v1, s0, h0), 0.f);
                    v2 = fmaxf(fmaf(v2, s4, h4), 0.f);
                    v3 = fmaxf(fmaf(v3, s4, h4), 0.f);
                }
                a[t][0] = f2tf_u(v0);
                a[t][1] = f2tf_u(v1);
                a[t][2] = f2tf_u(v2);
                a[t][3] = f2tf_u(v3);
            }
            uint32_t b[NT][2];
#pragma unroll
            for (int j = 0; j < NT; j++) {
                const uint32_t* p =
                    Bsm + (k + ql) * BPAD + wn * (BN / 2) + j * 8 + qr;
                b[j][0] = p[0];
                b[j][1] = p[4 * BPAD];
            }
#pragma unroll
            for (int t = 0; t < 2; t++)
#pragma unroll
                for (int j = 0; j < NT; j++) mma_tf32(acc[t][j], a[t], b[j]);
        }
        __syncthreads();
    }

#pragma unroll
    for (int t = 0; t < 2; t++) {
        int r0 = mBase + wm * 32 + t * 16 + qr;
#pragma unroll
        for (int j = 0; j < NT; j++) {
            int n0 = wn * (BN / 2) + j * 8 + 2 * ql;
            *reinterpret_cast<float2*>(&C[(size_t)r0 * BN + n0]) =
                make_float2(acc[t][j][0], acc[t][j][1]);
            *reinterpret_cast<float2*>(&C[(size_t)(r0 + 8) * BN + n0]) =
                make_float2(acc[t][j][2], acc[t][j][3]);
        }
    }
}

// ---------------------------------------------------------------------------
// Memory-phase kernels
// ---------------------------------------------------------------------------
__global__ void zero_kernel(float* __restrict__ p, size_t n) {
    size_t i = (size_t)blockIdx.x * blockDim.x + threadIdx.x;
    if (i < n) p[i] = 0.f;
}

__global__ void count_atoms(const int* __restrict__ atoms,
                            float* __restrict__ cnt, int rows) {
    int i = blockIdx.x * blockDim.x + threadIdx.x;
    if (i < rows) atomicAdd(&cnt[atoms[i]], 1.f);
}

__global__ void scatter_add4(const float* __restrict__ src,
                             const int* __restrict__ atoms,
                             float* __restrict__ node, int rows, int C) {
    int C4 = C >> 2;
    int idx = blockIdx.x * blockDim.x + threadIdx.x;
    if (idx >= rows * C4) return;
    int r = idx / C4;
    int c = (idx - r * C4) << 2;
    float4 v = *reinterpret_cast<const float4*>(&src[(size_t)r * C + c]);
    float* dst = &node[(size_t)atoms[r] * C + c];
    atomicAdd(dst + 0, v.x);
    atomicAdd(dst + 1, v.y);
    atomicAdd(dst + 2, v.z);
    atomicAdd(dst + 3, v.w);
}

template <int G>
__global__ void bc_gather(const float* __restrict__ node,
                          const int* __restrict__ atoms,
                          float* __restrict__ out, int nCyc, int C) {
    int idx = blockIdx.x * blockDim.x + threadIdx.x;
    if (idx >= nCyc * C) return;
    int i = idx / C;
    int c = idx - i * C;
    float s = 0.f;
#pragma unroll
    for (int k = 0; k < G; k++) s += node[(size_t)atoms[i * G + k] * C + c];
    out[(size_t)i * C + c] = s;
}

// fused bc + scatter for b1 (verified in round 10)
template <int G>
__global__ void bc_scatter(const float* __restrict__ node64,
                           const int* __restrict__ atoms,
                           float* __restrict__ n128, int nCyc) {
    int idx = blockIdx.x * blockDim.x + threadIdx.x;
    if (idx >= nCyc * 64) return;
    int i = idx >> 6;
    int c = idx & 63;
    int a[G];
    float s = 0.f;
#pragma unroll
    for (int k = 0; k < G; k++) {
        a[k] = atoms[i * G + k];
        s += node64[(size_t)a[k] * 64 + c];
    }
#pragma unroll
    for (int k = 0; k < G; k++)
        atomicAdd(&n128[(size_t)a[k] * 128 + 64 + c], s);
}

__global__ void init_node128(const float* __restrict__ node64,
                             const float* __restrict__ cnt,
                             float* __restrict__ node128) {
    int idx = blockIdx.x * blockDim.x + threadIdx.x;
    if (idx >= NNODES * 64) return;
    int a = idx >> 6, c = idx & 63;
    float s = cnt[a];
    node128[(size_t)a * 128 + c] = s * node64[(size_t)a * 64 + c];
    node128[(size_t)a * 128 + 64 + c] = 0.f;
}

__global__ void init_nodeS(const float* __restrict__ n5,
                           const float* __restrict__ n6,
                           const float* __restrict__ c5,
                           const float* __restrict__ c6,
                           float* __restrict__ nodeS) {
    int idx = blockIdx.x * blockDim.x + threadIdx.x;
    if (idx >= NNODES * 320) return;
    int a = idx / 320, c = idx - a * 320;
    float v = 0.f;
    if (c < 128)
        v = c5[a] * n5[(size_t)a * 128 + c] + c6[a] * n6[(size_t)a * 128 + c];
    nodeS[idx] = v;
}

template <int G>
__global__ void scatter_grp4(const float* __restrict__ src,
                             const int* __restrict__ atoms,
                             float* __restrict__ dst, int rows, int C,
                             int pitch, int off) {
    int C4 = C >> 2;
    int idx = blockIdx.x * blockDim.x + threadIdx.x;
    if (idx >= rows * C4) return;
    int r = idx / C4;
    int c = (idx - r * C4) << 2;
    float4 v =
        *reinterpret_cast<const float4*>(&src[(size_t)(r / G) * C + c]);
    float* d = &dst[(size_t)atoms[r] * pitch + off + c];
    atomicAdd(d + 0, v.x);
    atomicAdd(d + 1, v.y);
    atomicAdd(d + 2, v.z);
    atomicAdd(d + 3, v.w);
}

__global__ void round_tf32(const float* __restrict__ src,
                           float* __restrict__ dst, int n) {
    int i = blockIdx.x * blockDim.x + threadIdx.x;
    if (i < n) dst[i] = f2tf(src[i]);
}

// edge compose: h[r] = F[r] + B[self] + Bm[a0] + Bm[a1]; fused stats
__global__ void compose_edge(const float* __restrict__ F,
                             const float* __restrict__ B,
                             const float* __restrict__ Bm,
                             const int* __restrict__ atoms,
                             float* __restrict__ h,
                             float* __restrict__ stats) {
    int c = threadIdx.x;  // 128
    float s = 0.f, q = 0.f;
    for (int r = blockIdx.x; r < E_ROWS; r += gridDim.x) {
        int e = r >> 1;
        int a0 = atoms[2 * e], a1 = atoms[2 * e + 1];
        int self = (r & 1) ? a1 : a0;
        float v = F[(size_t)r * 128 + c] + B[(size_t)self * 128 + c] +
                  Bm[(size_t)a0 * 128 + c] + Bm[(size_t)a1 * 128 + c];
        h[(size_t)r * 128 + c] = v;
        s += v;
        q += v * v;
    }
    atomicAdd(&stats[c], s);
    atomicAdd(&stats[128 + c], q);
}

// cycle compose: h[r] = F[r] + P[atoms[r]] + R[r/G]; fused stats
template <int G>
__global__ void compose_cyc(const float* __restrict__ F,
                            const float* __restrict__ P,
                            const float* __restrict__ R,
                            const int* __restrict__ atoms,
                            float* __restrict__ h, int rows,
                            float* __restrict__ stats) {
    int c = threadIdx.x;  // 128
    float s = 0.f, q = 0.f;
    for (int r = blockIdx.x; r < rows; r += gridDim.x) {
        int a = atoms[r];
        float v = F[(size_t)r * 128 + c] + P[(size_t)a * 128 + c] +
                  R[(size_t)(r / G) * 128 + c];
        h[(size_t)r * 128 + c] = v;
        s += v;
        q += v * v;
    }
    atomicAdd(&stats[c], s);
    atomicAdd(&stats[128 + c], q);
}

__global__ void colstats(const float* __restrict__ Z, int M, int N,
                         float* __restrict__ stats) {
    int c = threadIdx.x;
    float s = 0.f, q = 0.f;
    for (int r = blockIdx.x; r < M; r += gridDim.x) {
        float v = Z[(size_t)r * N + c];
        s += v;
        q += v * v;
    }
    atomicAdd(&stats[c], s);
    atomicAdd(&stats[128 + c], q);
}

__global__ void make_scaleshift(const float* __restrict__ stats,
                                const float* __restrict__ g,
                                const float* __restrict__ b,
                                float* __restrict__ scale,
                                float* __restrict__ shift, int C, float invM) {
    int j = blockIdx.x * blockDim.x + threadIdx.x;
    if (j >= C) return;
    float m = stats[j] * invM;
    float v = stats[128 + j] * invM - m * m;
    v = fmaxf(v, 0.f);
    float s = g[j] * rsqrtf(v + EPS);
    scale[j] = s;
    shift[j] = b[j] - m * s;
}

__global__ void bn_relu_out(const float* __restrict__ z,
                            const float* __restrict__ scale,
                            const float* __restrict__ shift,
                            float* __restrict__ out, size_t n, int C) {
    size_t idx = (size_t)blockIdx.x * blockDim.x + threadIdx.x;
    if (idx >= n) return;
    int c = (int)(idx % C);
    out[idx] = fmaxf(z[idx] * scale[c] + shift[c], 0.f);
}

// ---------------------------------------------------------------------------
// Host orchestration
// ---------------------------------------------------------------------------
static inline int cdiv(int a, int b) { return (a + b - 1) / b; }

static float* sym_addr(const void* s) {
    void* p = nullptr;
    cudaGetSymbolAddress(&p, s);
    return (float*)p;
}

static const int SMEM_G128 = (256 + 2 * (128 * 36 + 32 * 136)) * 4;  // 72704
static const int SMEM_G64 = (256 + 2 * (128 * 36 + 32 * 72)) * 4;    // 56320

extern "C" void kernel_launch(void* const* d_in, const int* in_sizes, int n_in,
                              void* d_out, int out_size) {
    static bool attr_done = false;
    if (!attr_done) {
        cudaFuncSetAttribute(gemm_mma<128, false>,
                             cudaFuncAttributeMaxDynamicSharedMemorySize,
                             SMEM_G128);
        cudaFuncSetAttribute(gemm_mma<64, true>,
                             cudaFuncAttributeMaxDynamicSharedMemorySize,
                             SMEM_G64);
        attr_done = true;
    }

    const float* edge_feats = (const float*)d_in[0];
    const float* c5_feats = (const float*)d_in[1];
    const float* c6_feats = (const float*)d_in[2];
    const int* e_atoms = (const int*)d_in[3];
    const int* c5_atoms = (const int*)d_in[4];
    const int* c6_atoms = (const int*)d_in[5];
    const float* eW1 = (const float*)d_in[6];
    const float* eg1 = (const float*)d_in[7];
    const float* eb1 = (const float*)d_in[8];
    const float* eW2 = (const float*)d_in[9];
    const float* eg2 = (const float*)d_in[10];
    const float* eb2 = (const float*)d_in[11];
    const float* cW1 = (const float*)d_in[12];
    const float* cg1 = (const float*)d_in[13];
    const float* cb1 = (const float*)d_in[14];
    const float* cW2 = (const float*)d_in[15];
    const float* cg2 = (const float*)d_in[16];
    const float* cb2 = (const float*)d_in[17];

    float* out_edge = (float*)d_out;
    float* out_c5 = out_edge + (size_t)E_ROWS * H;
    float* out_c6 = out_c5 + (size_t)C5_ROWS * H;

    float* node64 = sym_addr(g_node64);
    float* cnt5 = node64 + NNODES * 64;
    float* cnt6 = node64 + NNODES * 65;
    float* n128_5 = sym_addr(g_n128_5);
    float* n128_6 = sym_addr(g_n128_6);
    float* b2_5 = sym_addr(g_b2_5);
    float* b2_6 = sym_addr(g_b2_6);
    float* nodeS = sym_addr(g_nodeS);
    float* Bt = sym_addr(g_B);
    float* Bm = sym_addr(g_Bm);
    float* P = sym_addr(g_P);
    float* R = sym_addr(g_R);
    float* F = sym_addr(g_F);
    float* h = sym_addr(g_h);
    float* z = sym_addr(g_z);
    float* wE1 = sym_addr(g_wE1);
    float* wE2 = sym_addr(g_wE2);
    float* wC1 = sym_addr(g_wC1);
    float* wC2 = sym_addr(g_wC2);
    float* stats = sym_addr(g_stats);
    float* sc1 = sym_addr(g_scale1);
    float* sh1 = sym_addr(g_shift1);
    float* sc2 = sym_addr(g_scale2);
    float* sh2 = sym_addr(g_shift2);

    const int TB = 256;

    // #1-3: weight rounding; #4: edge F GEMM (profiled launch)
    round_tf32<<<cdiv(704 * 128, TB), TB>>>(eW1, wE1, 704 * 128);
    round_tf32<<<cdiv(320 * 128, TB), TB>>>(cW1, wC1, 320 * 128);
    round_tf32<<<cdiv(128 * 64, TB), TB>>>(eW2, wE2, 128 * 64);
    gemm_mma<128, false><<<cdiv(E_ROWS, 128), 256, SMEM_G128>>>(
        edge_feats, wE1, F, E_ROWS, 64, nullptr, nullptr);
    round_tf32<<<cdiv(128 * 64, TB), TB>>>(cW2, wC2, 128 * 64);

    // ---- scatter chain (fp32 exact; round-10-verified) ----
    zero_kernel<<<cdiv(NNODES * 66, TB), TB>>>(node64, (size_t)NNODES * 66);
    scatter_add4<<<cdiv(E_ROWS * 16, TB), TB>>>(edge_feats, e_atoms, node64,
                                                E_ROWS, 64);
    count_atoms<<<cdiv(C5_ROWS, TB), TB>>>(c5_atoms, cnt5, C5_ROWS);
    count_atoms<<<cdiv(C6_ROWS, TB), TB>>>(c6_atoms, cnt6, C6_ROWS);

    init_node128<<<cdiv(NNODES * 64, TB), TB>>>(node64, cnt5, n128_5);
    init_node128<<<cdiv(NNODES * 64, TB), TB>>>(node64, cnt6, n128_6);
    bc_scatter<5><<<cdiv(NC5 * 64, TB), TB>>>(node64, c5_atoms, n128_5, NC5);
    bc_scatter<6><<<cdiv(NC6 * 64, TB), TB>>>(node64, c6_atoms, n128_6, NC6);

    bc_gather<5><<<cdiv(NC5 * 128, TB), TB>>>(n128_5, c5_atoms, b2_5, NC5, 128);
    bc_gather<6><<<cdiv(NC6 * 128, TB), TB>>>(n128_6, c6_atoms, b2_6, NC6, 128);

    init_nodeS<<<cdiv(NNODES * 320, TB), TB>>>(n128_5, n128_6, cnt5, cnt6,
                                               nodeS);
    scatter_grp4<5><<<cdiv(C5_ROWS * 32, TB), TB>>>(b2_5, c5_atoms, nodeS,
                                                    C5_ROWS, 128, 320, 128);
    scatter_grp4<6><<<cdiv(C6_ROWS * 32, TB), TB>>>(b2_6, c6_atoms, nodeS,
                                                    C6_ROWS, 128, 320, 128);
    scatter_grp4<1><<<cdiv(C5_ROWS * 16, TB), TB>>>(c5_feats, c5_atoms, nodeS,
                                                    C5_ROWS, 64, 320, 256);
    scatter_grp4<1><<<cdiv(C6_ROWS * 16, TB), TB>>>(c6_feats, c6_atoms, nodeS,
                                                    C6_ROWS, 64, 320, 256);

    // ================= EDGE MLP =================
    gemm_mma<128, false><<<cdiv(NNODES, 128), 256, SMEM_G128>>>(
        nodeS, wE1 + 64 * 128, Bt, NNODES, 320, nullptr, nullptr);
    gemm_mma<128, false><<<cdiv(NNODES, 128), 256, SMEM_G128>>>(
        nodeS, wE1 + 384 * 128, Bm, NNODES, 320, nullptr, nullptr);
    zero_kernel<<<1, 256>>>(stats, 256);
    compose_edge<<<2048, 128>>>(F, Bt, Bm, e_atoms, h, stats);
    make_scaleshift<<<1, 128>>>(stats, eg1, eb1, sc1, sh1, 128, 1.f / E_ROWS);
    gemm_mma<64, true><<<cdiv(E_ROWS, 128), 256, SMEM_G64>>>(
        h, wE2, z, E_ROWS, 128, sc1, sh1);
    zero_kernel<<<1, 256>>>(stats, 256);
    colstats<<<1024, 64>>>(z, E_ROWS, 64, stats);
    make_scaleshift<<<1, 64>>>(stats, eg2, eb2, sc2, sh2, 64, 1.f / E_ROWS);
    bn_relu_out<<<cdiv(E_ROWS * 64, TB), TB>>>(z, sc2, sh2, out_edge,
                                               (size_t)E_ROWS * 64, 64);

    // ================= CYCLE5 MLP =================
    gemm_mma<128, false><<<cdiv(C5_ROWS, 128), 256, SMEM_G128>>>(
        c5_feats, wC1 + 256 * 128, F, C5_ROWS, 64, nullptr, nullptr);
    gemm_mma<128, false><<<cdiv(NNODES, 128), 256, SMEM_G128>>>(
        n128_5, wC1, P, NNODES, 128, nullptr, nullptr);
    gemm_mma<128, false><<<cdiv(NC5, 128), 256, SMEM_G128>>>(
        b2_5, wC1 + 128 * 128, R, NC5, 128, nullptr, nullptr);
    zero_kernel<<<1, 256>>>(stats, 256);
    compose_cyc<5><<<2048, 128>>>(F, P, R, c5_atoms, h, C5_ROWS, stats);
    make_scaleshift<<<1, 128>>>(stats, cg1, cb1, sc1, sh1, 128, 1.f / C5_ROWS);
    gemm_mma<64, true><<<cdiv(C5_ROWS, 128), 256, SMEM_G64>>>(
        h, wC2, z, C5_ROWS, 128, sc1, sh1);
    zero_kernel<<<1, 256>>>(stats, 256);
    colstats<<<1024, 64>>>(z, C5_ROWS, 64, stats);
    make_scaleshift<<<1, 64>>>(stats, cg2, cb2, sc2, sh2, 64, 1.f / C5_ROWS);
    bn_relu_out<<<cdiv(C5_ROWS * 64, TB), TB>>>(z, sc2, sh2, out_c5,
                                                (size_t)C5_ROWS * 64, 64);

    // ================= CYCLE6 MLP =================
    gemm_mma<128, false><<<cdiv(C6_ROWS, 128), 256, SMEM_G128>>>(
        c6_feats, wC1 + 256 * 128, F, C6_ROWS, 64, nullptr, nullptr);
    gemm_mma<128, false><<<cdiv(NNODES, 128), 256, SMEM_G128>>>(
        n128_6, wC1, P, NNODES, 128, nullptr, nullptr);
    gemm_mma<128, false><<<cdiv(NC6, 128), 256, SMEM_G128>>>(
        b2_6, wC1 + 128 * 128, R, NC6, 128, nullptr, nullptr);
    zero_kernel<<<1, 256>>>(stats, 256);
    compose_cyc<6><<<2048, 128>>>(F, P, R, c6_atoms, h, C6_ROWS, stats);
    make_scaleshift<<<1, 128>>>(stats, cg1, cb1, sc1, sh1, 128, 1.f / C6_ROWS);
    gemm_mma<64, true><<<cdiv(C6_ROWS, 128), 256, SMEM_G64>>>(
        h, wC2, z, C6_ROWS, 128, sc1, sh1);
    zero_kernel<<<1, 256>>>(stats, 256);
    colstats<<<1024, 64>>>(z, C6_ROWS, 64, stats);
    make_scaleshift<<<1, 64>>>(stats, cg2, cb2, sc2, sh2, 64, 1.f / C6_ROWS);
    bn_relu_out<<<cdiv(C6_ROWS * 64, TB), TB>>>(z, sc2, sh2, out_c6,
                                                (size_t)C6_ROWS * 64, 64);

    (void)in_sizes;
    (void)n_in;
    (void)out_size;
}

// round 12
// speedup vs baseline: 1.0955x; 1.0334x over previous
#include <cuda_runtime.h>
#include <cuda_bf16.h>
#include <cstdint>

// ---------------------------------------------------------------------------
// Problem constants
// ---------------------------------------------------------------------------
#define H 64
#define NNODES 40000
#define NE 60000
#define NC5 30000
#define NC6 25000
#define E_ROWS (2 * NE)      // 120000
#define C5_ROWS (5 * NC5)    // 150000
#define C6_ROWS (6 * NC6)    // 150000
#define EPS 1e-5f

#define PAD_N  40064
#define PAD_R  30080
#define PAD_F  150016

// ---------------------------------------------------------------------------
// Device scratch
// ---------------------------------------------------------------------------
__device__ float g_node64[NNODES * 66];   // node64 | cnt5 | cnt6
__device__ float g_n128_5[NNODES * 128];
__device__ float g_n128_6[NNODES * 128];
__device__ float g_b2_5[NC5 * 128];
__device__ float g_b2_6[NC6 * 128];
__device__ float g_nodeS[NNODES * 320];
__device__ float g_B[PAD_N * 128];
__device__ float g_Bm[PAD_N * 128];
__device__ float g_P[PAD_N * 128];
__device__ float g_R[PAD_R * 128];
__device__ float g_F[PAD_F * 128];
__device__ float g_h[PAD_F * 128];
__device__ float g_z[PAD_F * 64];
__device__ float g_wE1[704 * 128];        // tf32-rounded weights
__device__ float g_wE2[128 * 64];
__device__ float g_wC1[320 * 128];
__device__ float g_wC2[128 * 64];
__device__ float g_stats[6 * 256];        // 6 buffers: [0:128) sum, [128:256) sq

// ---------------------------------------------------------------------------
// Helpers
// ---------------------------------------------------------------------------
__device__ __forceinline__ uint32_t smem_u32(const void* p) {
    uint32_t a;
    asm("{ .reg .u64 t; cvta.to.shared.u64 t, %1; cvt.u32.u64 %0, t; }"
        : "=r"(a) : "l"(p));
    return a;
}

__device__ __forceinline__ float f2tf(float x) {
    uint32_t r;
    asm("cvt.rna.tf32.f32 %0, %1;" : "=r"(r) : "f"(x));
    return __uint_as_float(r);
}

__device__ __forceinline__ uint32_t f2tf_u(float x) {
    uint32_t r;
    asm("cvt.rna.tf32.f32 %0, %1;" : "=r"(r) : "f"(x));
    return r;
}

__device__ __forceinline__ void cp16(uint32_t dst, const void* src, int nbytes) {
    asm volatile("cp.async.ca.shared.global [%0], [%1], 16, %2;"
                 :: "r"(dst), "l"(src), "r"(nbytes) : "memory");
}
__device__ __forceinline__ void cp_commit() {
    asm volatile("cp.async.commit_group;" ::: "memory");
}
__device__ __forceinline__ void cp_wait1() {
    asm volatile("cp.async.wait_group 1;" ::: "memory");
}

__device__ __forceinline__ void mma_tf32(float* d, const uint32_t* a,
                                         const uint32_t* b) {
    asm volatile(
        "mma.sync.aligned.m16n8k8.row.col.f32.tf32.tf32.f32 "
        "{%0,%1,%2,%3}, {%4,%5,%6,%7}, {%8,%9}, {%0,%1,%2,%3};"
        : "+f"(d[0]), "+f"(d[1]), "+f"(d[2]), "+f"(d[3])
        : "r"(a[0]), "r"(a[1]), "r"(a[2]), "r"(a[3]), "r"(b[0]), "r"(b[1]));
}

// ---------------------------------------------------------------------------
// tf32 mma.sync GEMM, cp.async double-buffered (round-11 / 950us geometry).
// A:[M,K] raw fp32 (tf32-rounded in-register), B:[K,BN] pre-rounded,
// C:[Mpad,BN]. K % 32 == 0. 256 threads, 8 warps (4Mx2N), BM=128.
// APPLY_IN: BN1 scale/shift computed INLINE from raw statsIn + g1/b1
//           (a' = relu(a*scale[k]+shift[k]) fused, K<=128).
// EPI_STATS: column sum/sumsq of valid C rows -> statsOut (pre-zeroed).
// ---------------------------------------------------------------------------
template <int BN, bool APPLY_IN, bool EPI_STATS>
__global__ void __launch_bounds__(256)
gemm_mma(const float* __restrict__ A, const float* __restrict__ B,
         float* __restrict__ C, int M, int K,
         const float* __restrict__ statsIn, const float* __restrict__ g1,
         const float* __restrict__ b1, float invM,
         float* __restrict__ statsOut) {
    constexpr int BM = 128, BK = 32;
    constexpr int APAD = 36;
    constexpr int BPAD = BN + 8;
    constexpr int ASZ = BM * APAD;
    constexpr int BSZ = BK * BPAD;
    constexpr int STG = ASZ + BSZ;
    constexpr int SOFF = 256;
    constexpr int NT = BN / 16;

    extern __shared__ float sm[];
    const int tid = threadIdx.x;
    const int warp = tid >> 5, lane = tid & 31;
    const int qr = lane >> 2, ql = lane & 3;
    const int wm = warp >> 1, wn = warp & 1;
    const int mBase = blockIdx.x * BM;
    const uint32_t smBase = smem_u32(sm);

    if (APPLY_IN && tid < 128) {
        float scale = 1.f, shift = 0.f;
        if (tid < K) {
            float m = statsIn[tid] * invM;
            float v = statsIn[128 + tid] * invM - m * m;
            v = fmaxf(v, 0.f);
            float s = g1[tid] * rsqrtf(v + EPS);
            scale = s;
            shift = b1[tid] - m * s;
        }
        sm[tid] = scale;
        sm[128 + tid] = shift;
    }

    auto issue = [&](int s, int k0) {
        const int so = SOFF + s * STG;
#pragma unroll
        for (int j = 0; j < 4; j++) {
            int i = tid + 256 * j;
            int row = i >> 3, ch = i & 7;
            int gr = mBase + row;
            bool ok = gr < M;
            const float* src = A + (size_t)(ok ? gr : 0) * K + k0 + ch * 4;
            uint32_t dst = smBase + (uint32_t)(so + row * APAD + ch * 4) * 4;
            cp16(dst, src, ok ? 16 : 0);
        }
#pragma unroll
        for (int j = 0; j < BK * BN / 4 / 256; j++) {
            int i = tid + 256 * j;
            int row = i / (BN / 4), c = i % (BN / 4);
            const float* src = B + (size_t)(k0 + row) * BN + c * 4;
            uint32_t dst =
                smBase + (uint32_t)(so + ASZ + row * BPAD + c * 4) * 4;
            cp16(dst, src, 16);
        }
    };

    float acc[2][NT][4];
#pragma unroll
    for (int t = 0; t < 2; t++)
#pragma unroll
        for (int j = 0; j < NT; j++)
#pragma unroll
            for (int r = 0; r < 4; r++) acc[t][j][r] = 0.f;

    const int nCh = K / BK;
    issue(0, 0);
    cp_commit();

    for (int c = 0; c < nCh; c++) {
        if (c + 1 < nCh) issue((c + 1) & 1, (c + 1) * BK);
        cp_commit();
        cp_wait1();
        __syncthreads();

        const float* Asm = sm + SOFF + (c & 1) * STG;
        const uint32_t* Bsm = reinterpret_cast<const uint32_t*>(Asm) + ASZ;
#pragma unroll
        for (int ks = 0; ks < 4; ks++) {
            const int k = ks * 8;
            float s0 = 1.f, h0 = 0.f, s4 = 1.f, h4 = 0.f;
            if (APPLY_IN) {
                int kc = c * 32 + k + ql;
                s0 = sm[kc];
                h0 = sm[128 + kc];
                s4 = sm[kc + 4];
                h4 = sm[128 + kc + 4];
            }
            uint32_t a[2][4];
#pragma unroll
            for (int t = 0; t < 2; t++) {
                const float* p = Asm + (wm * 32 + t * 16 + qr) * APAD + k + ql;
                float v0 = p[0], v1 = p[8 * APAD], v2 = p[4],
                      v3 = p[8 * APAD + 4];
                if (APPLY_IN) {
                    v0 = fmaxf(fmaf(v0, s0, h0), 0.f);
                    v1 = fmaxf(fmaf(v1, s0, h0), 0.f);
                    v2 = fmaxf(fmaf(v2, s4, h4), 0.f);
                    v3 = fmaxf(fmaf(v3, s4, h4), 0.f);
                }
                a[t][0] = f2tf_u(v0);
                a[t][1] = f2tf_u(v1);
                a[t][2] = f2tf_u(v2);
                a[t][3] = f2tf_u(v3);
            }
            uint32_t b[NT][2];
#pragma unroll
            for (int j = 0; j < NT; j++) {
                const uint32_t* p =
                    Bsm + (k + ql) * BPAD + wn * (BN / 2) + j * 8 + qr;
                b[j][0] = p[0];
                b[j][1] = p[4 * BPAD];
            }
#pragma unroll
            for (int t = 0; t < 2; t++)
#pragma unroll
                for (int j = 0; j < NT; j++) mma_tf32(acc[t][j], a[t], b[j]);
        }
        __syncthreads();
    }

    // ------------------ epilogue ------------------
    float ps[2 * NT], pq[2 * NT];
    if (EPI_STATS) {
#pragma unroll
        for (int i = 0; i < 2 * NT; i++) { ps[i] = 0.f; pq[i] = 0.f; }
    }

#pragma unroll
    for (int t = 0; t < 2; t++) {
#pragma unroll
        for (int rr = 0; rr < 2; rr++) {
            int row = mBase + wm * 32 + t * 16 + 8 * rr + qr;
            bool valid = row < M;
#pragma unroll
            for (int j = 0; j < NT; j++) {
                int n0 = wn * (BN / 2) + j * 8 + 2 * ql;
                float v0 = acc[t][j][2 * rr];
                float v1 = acc[t][j][2 * rr + 1];
                *reinterpret_cast<float2*>(&C[(size_t)row * BN + n0]) =
                    make_float2(v0, v1);
                if (EPI_STATS && valid) {
                    ps[2 * j] += v0;
                    pq[2 * j] += v0 * v0;
                    ps[2 * j + 1] += v1;
                    pq[2 * j + 1] += v1 * v1;
                }
            }
        }
    }

    if (EPI_STATS) {
        __syncthreads();
        for (int i = tid; i < 2 * BN; i += 256) sm[i] = 0.f;
        __syncthreads();
#pragma unroll
        for (int j = 0; j < NT; j++) {
            int n0 = wn * (BN / 2) + j * 8 + 2 * ql;
            atomicAdd(&sm[n0], ps[2 * j]);
            atomicAdd(&sm[n0 + 1], ps[2 * j + 1]);
            atomicAdd(&sm[BN + n0], pq[2 * j]);
            atomicAdd(&sm[BN + n0 + 1], pq[2 * j + 1]);
        }
        __syncthreads();
        if (tid < BN) {
            atomicAdd(&statsOut[tid], sm[tid]);
            atomicAdd(&statsOut[128 + tid], sm[BN + tid]);
        }
    }
}

// ---------------------------------------------------------------------------
// Memory-phase kernels
// ---------------------------------------------------------------------------
__global__ void zero_kernel(float* __restrict__ p, size_t n) {
    size_t i = (size_t)blockIdx.x * blockDim.x + threadIdx.x;
    if (i < n) p[i] = 0.f;
}

__global__ void count_atoms(const int* __restrict__ atoms,
                            float* __restrict__ cnt, int rows) {
    int i = blockIdx.x * blockDim.x + threadIdx.x;
    if (i < rows) atomicAdd(&cnt[atoms[i]], 1.f);
}

__global__ void scatter_add4(const float* __restrict__ src,
                             const int* __restrict__ atoms,
                             float* __restrict__ node, int rows, int C) {
    int C4 = C >> 2;
    int idx = blockIdx.x * blockDim.x + threadIdx.x;
    if (idx >= rows * C4) return;
    int r = idx / C4;
    int c = (idx - r * C4) << 2;
    float4 v = *reinterpret_cast<const float4*>(&src[(size_t)r * C + c]);
    float* dst = &node[(size_t)atoms[r] * C + c];
    atomicAdd(dst + 0, v.x);
    atomicAdd(dst + 1, v.y);
    atomicAdd(dst + 2, v.z);
    atomicAdd(dst + 3, v.w);
}

template <int G>
__global__ void bc_gather(const float* __restrict__ node,
                          const int* __restrict__ atoms,
                          float* __restrict__ out, int nCyc, int C) {
    int idx = blockIdx.x * blockDim.x + threadIdx.x;
    if (idx >= nCyc * C) return;
    int i = idx / C;
    int c = idx - i * C;
    float s = 0.f;
#pragma unroll
    for (int k = 0; k < G; k++) s += node[(size_t)atoms[i * G + k] * C + c];
    out[(size_t)i * C + c] = s;
}

template <int G>
__global__ void bc_scatter(const float* __restrict__ node64,
                           const int* __restrict__ atoms,
                           float* __restrict__ n128, int nCyc) {
    int idx = blockIdx.x * blockDim.x + threadIdx.x;
    if (idx >= nCyc * 64) return;
    int i = idx >> 6;
    int c = idx & 63;
    int a[G];
    float s = 0.f;
#pragma unroll
    for (int k = 0; k < G; k++) {
        a[k] = atoms[i * G + k];
        s += node64[(size_t)a[k] * 64 + c];
    }
#pragma unroll
    for (int k = 0; k < G; k++)
        atomicAdd(&n128[(size_t)a[k] * 128 + 64 + c], s);
}

__global__ void init_node128(const float* __restrict__ node64,
                             const float* __restrict__ cnt,
                             float* __restrict__ node128) {
    int idx = blockIdx.x * blockDim.x + threadIdx.x;
    if (idx >= NNODES * 64) return;
    int a = idx >> 6, c = idx & 63;
    float s = cnt[a];
    node128[(size_t)a * 128 + c] = s * node64[(size_t)a * 64 + c];
    node128[(size_t)a * 128 + 64 + c] = 0.f;
}

__global__ void init_nodeS(const float* __restrict__ n5,
                           const float* __restrict__ n6,
                           const float* __restrict__ c5,
                           const float* __restrict__ c6,
                           float* __restrict__ nodeS) {
    int idx = blockIdx.x * blockDim.x + threadIdx.x;
    if (idx >= NNODES * 320) return;
    int a = idx / 320, c = idx - a * 320;
    float v = 0.f;
    if (c < 128)
        v = c5[a] * n5[(size_t)a * 128 + c] + c6[a] * n6[(size_t)a * 128 + c];
    nodeS[idx] = v;
}

template <int G>
__global__ void scatter_grp4(const float* __restrict__ src,
                             const int* __restrict__ atoms,
                             float* __restrict__ dst, int rows, int C,
                             int pitch, int off) {
    int C4 = C >> 2;
    int idx = blockIdx.x * blockDim.x + threadIdx.x;
    if (idx >= rows * C4) return;
    int r = idx / C4;
    int c = (idx - r * C4) << 2;
    float4 v =
        *reinterpret_cast<const float4*>(&src[(size_t)(r / G) * C + c]);
    float* d = &dst[(size_t)atoms[r] * pitch + off + c];
    atomicAdd(d + 0, v.x);
    atomicAdd(d + 1, v.y);
    atomicAdd(d + 2, v.z);
    atomicAdd(d + 3, v.w);
}

__global__ void round_tf32(const float* __restrict__ src,
                           float* __restrict__ dst, int n) {
    int i = blockIdx.x * blockDim.x + threadIdx.x;
    if (i < n) dst[i] = f2tf(src[i]);
}

// edge compose: h[r] = F[r] + B[self] + Bm[a0] + Bm[a1]; fused stats
__global__ void compose_edge(const float* __restrict__ F,
                             const float* __restrict__ B,
                             const float* __restrict__ Bm,
                             const int* __restrict__ atoms,
                             float* __restrict__ h,
                             float* __restrict__ stats) {
    int c = threadIdx.x;  // 128
    float s = 0.f, q = 0.f;
    for (int r = blockIdx.x; r < E_ROWS; r += gridDim.x) {
        int e = r >> 1;
        int a0 = atoms[2 * e], a1 = atoms[2 * e + 1];
        int self = (r & 1) ? a1 : a0;
        float v = F[(size_t)r * 128 + c] + B[(size_t)self * 128 + c] +
                  Bm[(size_t)a0 * 128 + c] + Bm[(size_t)a1 * 128 + c];
        h[(size_t)r * 128 + c] = v;
        s += v;
        q += v * v;
    }
    atomicAdd(&stats[c], s);
    atomicAdd(&stats[128 + c], q);
}

// cycle compose: h[r] = F[r] + P[atoms[r]] + R[r/G]; fused stats
template <int G>
__global__ void compose_cyc(const float* __restrict__ F,
                            const float* __restrict__ P,
                            const float* __restrict__ R,
                            const int* __restrict__ atoms,
                            float* __restrict__ h, int rows,
                            float* __restrict__ stats) {
    int c = threadIdx.x;  // 128
    float s = 0.f, q = 0.f;
    for (int r = blockIdx.x; r < rows; r += gridDim.x) {
        int a = atoms[r];
        float v = F[(size_t)r * 128 + c] + P[(size_t)a * 128 + c] +
                  R[(size_t)(r / G) * 128 + c];
        h[(size_t)r * 128 + c] = v;
        s += v;
        q += v * v;
    }
    atomicAdd(&stats[c], s);
    atomicAdd(&stats[128 + c], q);
}

// BN2 + ReLU with inline scale/shift from raw stats (per-block smem compute)
__global__ void bn_relu_out(const float* __restrict__ z,
                            const float* __restrict__ stats,
                            const float* __restrict__ g,
                            const float* __restrict__ b, float invM,
                            float* __restrict__ out, size_t n) {
    __shared__ float ss[128];  // [0:64) scale, [64:128) shift
    int tid = threadIdx.x;
    if (tid < 64) {
        float m = stats[tid] * invM;
        float v = stats[128 + tid] * invM - m * m;
        v = fmaxf(v, 0.f);
        float s = g[tid] * rsqrtf(v + EPS);
        ss[tid] = s;
        ss[64 + tid] = b[tid] - m * s;
    }
    __syncthreads();
    size_t idx = (size_t)blockIdx.x * blockDim.x + tid;
    if (idx >= n) return;
    int c = (int)(idx & 63);
    out[idx] = fmaxf(z[idx] * ss[c] + ss[64 + c], 0.f);
}

// ---------------------------------------------------------------------------
// Host orchestration
// ---------------------------------------------------------------------------
static inline int cdiv(int a, int b) { return (a + b - 1) / b; }

static float* sym_addr(const void* s) {
    void* p = nullptr;
    cudaGetSymbolAddress(&p, s);
    return (float*)p;
}

static const int SMEM_G128 = (256 + 2 * (128 * 36 + 32 * 136)) * 4;  // 72704
static const int SMEM_G64 = (256 + 2 * (128 * 36 + 32 * 72)) * 4;    // 56320

extern "C" void kernel_launch(void* const* d_in, const int* in_sizes, int n_in,
                              void* d_out, int out_size) {
    static bool attr_done = false;
    if (!attr_done) {
        cudaFuncSetAttribute(gemm_mma<128, false, false>,
                             cudaFuncAttributeMaxDynamicSharedMemorySize,
                             SMEM_G128);
        cudaFuncSetAttribute(gemm_mma<64, true, true>,
                             cudaFuncAttributeMaxDynamicSharedMemorySize,
                             SMEM_G64);
        attr_done = true;
    }

    const float* edge_feats = (const float*)d_in[0];
    const float* c5_feats = (const float*)d_in[1];
    const float* c6_feats = (const float*)d_in[2];
    const int* e_atoms = (const int*)d_in[3];
    const int* c5_atoms = (const int*)d_in[4];
    const int* c6_atoms = (const int*)d_in[5];
    const float* eW1 = (const float*)d_in[6];
    const float* eg1 = (const float*)d_in[7];
    const float* eb1 = (const float*)d_in[8];
    const float* eW2 = (const float*)d_in[9];
    const float* eg2 = (const float*)d_in[10];
    const float* eb2 = (const float*)d_in[11];
    const float* cW1 = (const float*)d_in[12];
    const float* cg1 = (const float*)d_in[13];
    const float* cb1 = (const float*)d_in[14];
    const float* cW2 = (const float*)d_in[15];
    const float* cg2 = (const float*)d_in[16];
    const float* cb2 = (const float*)d_in[17];

    float* out_edge = (float*)d_out;
    float* out_c5 = out_edge + (size_t)E_ROWS * H;
    float* out_c6 = out_c5 + (size_t)C5_ROWS * H;

    float* node64 = sym_addr(g_node64);
    float* cnt5 = node64 + NNODES * 64;
    float* cnt6 = node64 + NNODES * 65;
    float* n128_5 = sym_addr(g_n128_5);
    float* n128_6 = sym_addr(g_n128_6);
    float* b2_5 = sym_addr(g_b2_5);
    float* b2_6 = sym_addr(g_b2_6);
    float* nodeS = sym_addr(g_nodeS);
    float* Bt = sym_addr(g_B);
    float* Bm = sym_addr(g_Bm);
    float* P = sym_addr(g_P);
    float* R = sym_addr(g_R);
    float* F = sym_addr(g_F);
    float* h = sym_addr(g_h);
    float* z = sym_addr(g_z);
    float* wE1 = sym_addr(g_wE1);
    float* wE2 = sym_addr(g_wE2);
    float* wC1 = sym_addr(g_wC1);
    float* wC2 = sym_addr(g_wC2);
    float* stats = sym_addr(g_stats);
    float* stE1 = stats;              // edge BN1
    float* stE2 = stats + 256;        // edge BN2
    float* st51 = stats + 512;        // c5 BN1
    float* st52 = stats + 768;        // c5 BN2
    float* st61 = stats + 1024;       // c6 BN1
    float* st62 = stats + 1280;       // c6 BN2

    const int TB = 256;

    // #1-3: weight rounding; #4: edge F GEMM (profiled launch)
    round_tf32<<<cdiv(704 * 128, TB), TB>>>(eW1, wE1, 704 * 128);
    round_tf32<<<cdiv(320 * 128, TB), TB>>>(cW1, wC1, 320 * 128);
    round_tf32<<<cdiv(128 * 64, TB), TB>>>(eW2, wE2, 128 * 64);
    gemm_mma<128, false, false><<<cdiv(E_ROWS, 128), 256, SMEM_G128>>>(
        edge_feats, wE1, F, E_ROWS, 64, nullptr, nullptr, nullptr, 0.f,
        nullptr);
    round_tf32<<<cdiv(128 * 64, TB), TB>>>(cW2, wC2, 128 * 64);
    // zero all 6 stats buffers at once
    zero_kernel<<<cdiv(6 * 256, TB), TB>>>(stats, 6 * 256);

    // ---- scatter chain (fp32 exact) ----
    zero_kernel<<<cdiv(NNODES * 66, TB), TB>>>(node64, (size_t)NNODES * 66);
    scatter_add4<<<cdiv(E_ROWS * 16, TB), TB>>>(edge_feats, e_atoms, node64,
                                                E_ROWS, 64);
    count_atoms<<<cdiv(C5_ROWS, TB), TB>>>(c5_atoms, cnt5, C5_ROWS);
    count_atoms<<<cdiv(C6_ROWS, TB), TB>>>(c6_atoms, cnt6, C6_ROWS);

    init_node128<<<cdiv(NNODES * 64, TB), TB>>>(node64, cnt5, n128_5);
    init_node128<<<cdiv(NNODES * 64, TB), TB>>>(node64, cnt6, n128_6);
    bc_scatter<5><<<cdiv(NC5 * 64, TB), TB>>>(node64, c5_atoms, n128_5, NC5);
    bc_scatter<6><<<cdiv(NC6 * 64, TB), TB>>>(node64, c6_atoms, n128_6, NC6);

    bc_gather<5><<<cdiv(NC5 * 128, TB), TB>>>(n128_5, c5_atoms, b2_5, NC5, 128);
    bc_gather<6><<<cdiv(NC6 * 128, TB), TB>>>(n128_6, c6_atoms, b2_6, NC6, 128);

    init_nodeS<<<cdiv(NNODES * 320, TB), TB>>>(n128_5, n128_6, cnt5, cnt6,
                                               nodeS);
    scatter_grp4<5><<<cdiv(C5_ROWS * 32, TB), TB>>>(b2_5, c5_atoms, nodeS,
                                                    C5_ROWS, 128, 320, 128);
    scatter_grp4<6><<<cdiv(C6_ROWS * 32, TB), TB>>>(b2_6, c6_atoms, nodeS,
                                                    C6_ROWS, 128, 320, 128);
    scatter_grp4<1><<<cdiv(C5_ROWS * 16, TB), TB>>>(c5_feats, c5_atoms, nodeS,
                                                    C5_ROWS, 64, 320, 256);
    scatter_grp4<1><<<cdiv(C6_ROWS * 16, TB), TB>>>(c6_feats, c6_atoms, nodeS,
                                                    C6_ROWS, 64, 320, 256);

    // ================= EDGE MLP =================
    gemm_mma<128, false, false><<<cdiv(NNODES, 128), 256, SMEM_G128>>>(
        nodeS, wE1 + 64 * 128, Bt, NNODES, 320, nullptr, nullptr, nullptr,
        0.f, nullptr);
    gemm_mma<128, false, false><<<cdiv(NNODES, 128), 256, SMEM_G128>>>(
        nodeS, wE1 + 384 * 128, Bm, NNODES, 320, nullptr, nullptr, nullptr,
        0.f, nullptr);
    compose_edge<<<2048, 128>>>(F, Bt, Bm, e_atoms, h, stE1);
    gemm_mma<64, true, true><<<cdiv(E_ROWS, 128), 256, SMEM_G64>>>(
        h, wE2, z, E_ROWS, 128, stE1, eg1, eb1, 1.f / E_ROWS, stE2);
    bn_relu_out<<<cdiv(E_ROWS * 64, TB), TB>>>(z, stE2, eg2, eb2,
                                               1.f / E_ROWS, out_edge,
                                               (size_t)E_ROWS * 64);

    // ================= CYCLE5 MLP =================
    gemm_mma<128, false, false><<<cdiv(C5_ROWS, 128), 256, SMEM_G128>>>(
        c5_feats, wC1 + 256 * 128, F, C5_ROWS, 64, nullptr, nullptr, nullptr,
        0.f, nullptr);
    gemm_mma<128, false, false><<<cdiv(NNODES, 128), 256, SMEM_G128>>>(
        n128_5, wC1, P, NNODES, 128, nullptr, nullptr, nullptr, 0.f, nullptr);
    gemm_mma<128, false, false><<<cdiv(NC5, 128), 256, SMEM_G128>>>(
        b2_5, wC1 + 128 * 128, R, NC5, 128, nullptr, nullptr, nullptr, 0.f,
        nullptr);
    compose_cyc<5><<<2048, 128>>>(F, P, R, c5_atoms, h, C5_ROWS, st51);
    gemm_mma<64, true, true><<<cdiv(C5_ROWS, 128), 256, SMEM_G64>>>(
        h, wC2, z, C5_ROWS, 128, st51, cg1, cb1, 1.f / C5_ROWS, st52);
    bn_relu_out<<<cdiv(C5_ROWS * 64, TB), TB>>>(z, st52, cg2, cb2,
                                                1.f / C5_ROWS, out_c5,
                                                (size_t)C5_ROWS * 64);

    // ================= CYCLE6 MLP =================
    gemm_mma<128, false, false><<<cdiv(C6_ROWS, 128), 256, SMEM_G128>>>(
        c6_feats, wC1 + 256 * 128, F, C6_ROWS, 64, nullptr, nullptr, nullptr,
        0.f, nullptr);
    gemm_mma<128, false, false><<<cdiv(NNODES, 128), 256, SMEM_G128>>>(
        n128_6, wC1, P, NNODES, 128, nullptr, nullptr, nullptr, 0.f, nullptr);
    gemm_mma<128, false, false><<<cdiv(NC6, 128), 256, SMEM_G128>>>(
        b2_6, wC1 + 128 * 128, R, NC6, 128, nullptr, nullptr, nullptr, 0.f,
        nullptr);
    compose_cyc<6><<<2048, 128>>>(F, P, R, c6_atoms, h, C6_ROWS, st61);
    gemm_mma<64, true, true><<<cdiv(C6_ROWS, 128), 256, SMEM_G64>>>(
        h, wC2, z, C6_ROWS, 128, st61, cg1, cb1, 1.f / C6_ROWS, st62);
    bn_relu_out<<<cdiv(C6_ROWS * 64, TB), TB>>>(z, st62, cg2, cb2,
                                                1.f / C6_ROWS, out_c6,
                                                (size_t)C6_ROWS * 64);

    (void)in_sizes;
    (void)n_in;
    (void)out_size;
}

// round 13
// speedup vs baseline: 1.1222x; 1.0243x over previous
#include <cuda_runtime.h>
#include <cuda_fp16.h>
#include <cstdint>

// ---------------------------------------------------------------------------
// Problem constants
// ---------------------------------------------------------------------------
#define H 64
#define NNODES 40000
#define NE 60000
#define NC5 30000
#define NC6 25000
#define E_ROWS (2 * NE)      // 120000
#define C5_ROWS (5 * NC5)    // 150000
#define C6_ROWS (6 * NC6)    // 150000
#define EPS 1e-5f

#define PAD_N  40064
#define PAD_R  30080
#define PAD_F  150016

// ---------------------------------------------------------------------------
// Device scratch
// ---------------------------------------------------------------------------
__device__ float g_node64[NNODES * 66];   // node64 | cnt5 | cnt6
__device__ float g_n128_5[NNODES * 128];
__device__ float g_n128_6[NNODES * 128];
__device__ float g_b2_5[NC5 * 128];
__device__ float g_b2_6[NC6 * 128];
__device__ float g_nodeS[NNODES * 320];
__device__ float g_B[PAD_N * 128];
__device__ float g_Bm[PAD_N * 128];
__device__ float g_P[PAD_N * 128];
__device__ float g_R[PAD_R * 128];
__device__ __half g_F[PAD_F * 128];       // fp16 intermediates
__device__ __half g_h[PAD_F * 128];
__device__ __half g_z[PAD_F * 64];
__device__ float g_wE1[704 * 128];        // tf32-rounded weights
__device__ float g_wE2[128 * 64];
__device__ float g_wC1[320 * 128];
__device__ float g_wC2[128 * 64];
__device__ float g_stats[6 * 256];        // 6 buffers: sum | sumsq

// ---------------------------------------------------------------------------
// Helpers
// ---------------------------------------------------------------------------
__device__ __forceinline__ uint32_t smem_u32(const void* p) {
    uint32_t a;
    asm("{ .reg .u64 t; cvta.to.shared.u64 t, %1; cvt.u32.u64 %0, t; }"
        : "=r"(a) : "l"(p));
    return a;
}

__device__ __forceinline__ float f2tf(float x) {
    uint32_t r;
    asm("cvt.rna.tf32.f32 %0, %1;" : "=r"(r) : "f"(x));
    return __uint_as_float(r);
}

__device__ __forceinline__ uint32_t f2tf_u(float x) {
    uint32_t r;
    asm("cvt.rna.tf32.f32 %0, %1;" : "=r"(r) : "f"(x));
    return r;
}

__device__ __forceinline__ void cp16(uint32_t dst, const void* src, int nbytes) {
    asm volatile("cp.async.ca.shared.global [%0], [%1], 16, %2;"
                 :: "r"(dst), "l"(src), "r"(nbytes) : "memory");
}
__device__ __forceinline__ void cp_commit() {
    asm volatile("cp.async.commit_group;" ::: "memory");
}
__device__ __forceinline__ void cp_wait1() {
    asm volatile("cp.async.wait_group 1;" ::: "memory");
}

__device__ __forceinline__ void mma_tf32(float* d, const uint32_t* a,
                                         const uint32_t* b) {
    asm volatile(
        "mma.sync.aligned.m16n8k8.row.col.f32.tf32.tf32.f32 "
        "{%0,%1,%2,%3}, {%4,%5,%6,%7}, {%8,%9}, {%0,%1,%2,%3};"
        : "+f"(d[0]), "+f"(d[1]), "+f"(d[2]), "+f"(d[3])
        : "r"(a[0]), "r"(a[1]), "r"(a[2]), "r"(a[3]), "r"(b[0]), "r"(b[1]));
}

// ---------------------------------------------------------------------------
// tf32 mma.sync GEMM (round-12 / 919us geometry + dtype flags).
// A:[M,K] fp32 or fp16 (A_HALF), tf32-rounded in-register at fragment load.
// B:[K,BN] pre-rounded fp32. C:[Mpad,BN] fp32 or fp16 (C_HALF).
// 256 threads, 8 warps (4Mx2N), BM=128, K%32==0, cp.async double-buffered.
// APPLY_IN: BN1 scale/shift computed inline from raw statsIn+g1/b1; then ReLU.
// EPI_STATS: column sum/sumsq of valid C rows (fp32 acc) -> statsOut.
// ---------------------------------------------------------------------------
template <int BN, bool APPLY_IN, bool EPI_STATS, bool A_HALF, bool C_HALF>
__global__ void __launch_bounds__(256)
gemm_mma(const void* __restrict__ Av, const float* __restrict__ B,
         void* __restrict__ Cv, int M, int K,
         const float* __restrict__ statsIn, const float* __restrict__ g1,
         const float* __restrict__ b1, float invM,
         float* __restrict__ statsOut) {
    constexpr int BM = 128, BK = 32;
    constexpr int A_ROWB = A_HALF ? 80 : 144;   // bytes/row (incl pad)
    constexpr int ASZB = BM * A_ROWB;
    constexpr int BSZB = BK * (BN + 8) * 4;
    constexpr int STGB = ASZB + BSZB;
    constexpr int SOFFB = 1024;                 // 256 floats scale/shift
    constexpr int NT = BN / 16;

    extern __shared__ float sm[];
    const int tid = threadIdx.x;
    const int warp = tid >> 5, lane = tid & 31;
    const int qr = lane >> 2, ql = lane & 3;
    const int wm = warp >> 1, wn = warp & 1;
    const int mBase = blockIdx.x * BM;
    const uint32_t smBase = smem_u32(sm);

    if (APPLY_IN && tid < 128) {
        float scale = 1.f, shift = 0.f;
        if (tid < K) {
            float m = statsIn[tid] * invM;
            float v = statsIn[128 + tid] * invM - m * m;
            v = fmaxf(v, 0.f);
            float s = g1[tid] * rsqrtf(v + EPS);
            scale = s;
            shift = b1[tid] - m * s;
        }
        sm[tid] = scale;
        sm[128 + tid] = shift;
    }

    auto issue = [&](int s, int k0) {
        const int so = SOFFB + s * STGB;
        if (A_HALF) {
            const __half* A = (const __half*)Av;
#pragma unroll
            for (int j = 0; j < 2; j++) {
                int i = tid + 256 * j;
                int row = i >> 2, ch = i & 3;   // ch: 8-half unit
                int gr = mBase + row;
                bool ok = gr < M;
                const __half* src =
                    A + (size_t)(ok ? gr : 0) * K + k0 + ch * 8;
                uint32_t dst = smBase + (uint32_t)(so + row * 80 + ch * 16);
                cp16(dst, src, ok ? 16 : 0);
            }
        } else {
            const float* A = (const float*)Av;
#pragma unroll
            for (int j = 0; j < 4; j++) {
                int i = tid + 256 * j;
                int row = i >> 3, ch = i & 7;
                int gr = mBase + row;
                bool ok = gr < M;
                const float* src =
                    A + (size_t)(ok ? gr : 0) * K + k0 + ch * 4;
                uint32_t dst = smBase + (uint32_t)(so + row * 144 + ch * 16);
                cp16(dst, src, ok ? 16 : 0);
            }
        }
#pragma unroll
        for (int j = 0; j < BK * BN / 4 / 256; j++) {
            int i = tid + 256 * j;
            int row = i / (BN / 4), c = i % (BN / 4);
            const float* src = B + (size_t)(k0 + row) * BN + c * 4;
            uint32_t dst = smBase +
                           (uint32_t)(so + ASZB + (row * (BN + 8) + c * 4) * 4);
            cp16(dst, src, 16);
        }
    };

    float acc[2][NT][4];
#pragma unroll
    for (int t = 0; t < 2; t++)
#pragma unroll
        for (int j = 0; j < NT; j++)
#pragma unroll
            for (int r = 0; r < 4; r++) acc[t][j][r] = 0.f;

    const int nCh = K / BK;
    issue(0, 0);
    cp_commit();

    for (int c = 0; c < nCh; c++) {
        if (c + 1 < nCh) issue((c + 1) & 1, (c + 1) * BK);
        cp_commit();
        cp_wait1();
        __syncthreads();

        const char* AsmB =
            (const char*)sm + SOFFB + (c & 1) * STGB;
        const uint32_t* Bsm = (const uint32_t*)(AsmB + ASZB);
#pragma unroll
        for (int ks = 0; ks < 4; ks++) {
            const int k = ks * 8;
            float s0 = 1.f, h0 = 0.f, s4 = 1.f, h4 = 0.f;
            if (APPLY_IN) {
                int kc = c * 32 + k + ql;
                s0 = sm[kc];
                h0 = sm[128 + kc];
                s4 = sm[kc + 4];
                h4 = sm[128 + kc + 4];
            }
            uint32_t a[2][4];
#pragma unroll
            for (int t = 0; t < 2; t++) {
                float v0, v1, v2, v3;
                int rbase = wm * 32 + t * 16 + qr;
                if (A_HALF) {
                    const __half* p =
                        (const __half*)AsmB + rbase * 40 + k + ql;
                    v0 = __half2float(p[0]);
                    v1 = __half2float(p[8 * 40]);
                    v2 = __half2float(p[4]);
                    v3 = __half2float(p[8 * 40 + 4]);
                } else {
                    const float* p = (const float*)AsmB + rbase * 36 + k + ql;
                    v0 = p[0];
                    v1 = p[8 * 36];
                    v2 = p[4];
                    v3 = p[8 * 36 + 4];
                }
                if (APPLY_IN) {
                    v0 = fmaxf(fmaf(v0, s0, h0), 0.f);
                    v1 = fmaxf(fmaf(v1, s0, h0), 0.f);
                    v2 = fmaxf(fmaf(v2, s4, h4), 0.f);
                    v3 = fmaxf(fmaf(v3, s4, h4), 0.f);
                }
                a[t][0] = f2tf_u(v0);
                a[t][1] = f2tf_u(v1);
                a[t][2] = f2tf_u(v2);
                a[t][3] = f2tf_u(v3);
            }
            uint32_t b[NT][2];
#pragma unroll
            for (int j = 0; j < NT; j++) {
                const uint32_t* p =
                    Bsm + (k + ql) * (BN + 8) + wn * (BN / 2) + j * 8 + qr;
                b[j][0] = p[0];
                b[j][1] = p[4 * (BN + 8)];
            }
#pragma unroll
            for (int t = 0; t < 2; t++)
#pragma unroll
                for (int j = 0; j < NT; j++) mma_tf32(acc[t][j], a[t], b[j]);
        }
        __syncthreads();
    }

    // ------------------ epilogue ------------------
    float ps[2 * NT], pq[2 * NT];
    if (EPI_STATS) {
#pragma unroll
        for (int i = 0; i < 2 * NT; i++) { ps[i] = 0.f; pq[i] = 0.f; }
    }

#pragma unroll
    for (int t = 0; t < 2; t++) {
#pragma unroll
        for (int rr = 0; rr < 2; rr++) {
            int row = mBase + wm * 32 + t * 16 + 8 * rr + qr;
            bool valid = row < M;
#pragma unroll
            for (int j = 0; j < NT; j++) {
                int n0 = wn * (BN / 2) + j * 8 + 2 * ql;
                float v0 = acc[t][j][2 * rr];
                float v1 = acc[t][j][2 * rr + 1];
                if (C_HALF) {
                    *reinterpret_cast<__half2*>(
                        (__half*)Cv + (size_t)row * BN + n0) =
                        __floats2half2_rn(v0, v1);
                } else {
                    *reinterpret_cast<float2*>(
                        (float*)Cv + (size_t)row * BN + n0) =
                        make_float2(v0, v1);
                }
                if (EPI_STATS && valid) {
                    ps[2 * j] += v0;
                    pq[2 * j] += v0 * v0;
                    ps[2 * j + 1] += v1;
                    pq[2 * j + 1] += v1 * v1;
                }
            }
        }
    }

    if (EPI_STATS) {
        __syncthreads();
        for (int i = tid; i < 2 * BN; i += 256) sm[i] = 0.f;
        __syncthreads();
#pragma unroll
        for (int j = 0; j < NT; j++) {
            int n0 = wn * (BN / 2) + j * 8 + 2 * ql;
            atomicAdd(&sm[n0], ps[2 * j]);
            atomicAdd(&sm[n0 + 1], ps[2 * j + 1]);
            atomicAdd(&sm[BN + n0], pq[2 * j]);
            atomicAdd(&sm[BN + n0 + 1], pq[2 * j + 1]);
        }
        __syncthreads();
        if (tid < BN) {
            atomicAdd(&statsOut[tid], sm[tid]);
            atomicAdd(&statsOut[128 + tid], sm[BN + tid]);
        }
    }
}

// ---------------------------------------------------------------------------
// Memory-phase kernels
// ---------------------------------------------------------------------------
__global__ void zero_kernel(float* __restrict__ p, size_t n) {
    size_t i = (size_t)blockIdx.x * blockDim.x + threadIdx.x;
    if (i < n) p[i] = 0.f;
}

__global__ void count_atoms(const int* __restrict__ atoms,
                            float* __restrict__ cnt, int rows) {
    int i = blockIdx.x * blockDim.x + threadIdx.x;
    if (i < rows) atomicAdd(&cnt[atoms[i]], 1.f);
}

__global__ void scatter_add4(const float* __restrict__ src,
                             const int* __restrict__ atoms,
                             float* __restrict__ node, int rows, int C) {
    int C4 = C >> 2;
    int idx = blockIdx.x * blockDim.x + threadIdx.x;
    if (idx >= rows * C4) return;
    int r = idx / C4;
    int c = (idx - r * C4) << 2;
    float4 v = *reinterpret_cast<const float4*>(&src[(size_t)r * C + c]);
    float* dst = &node[(size_t)atoms[r] * C + c];
    atomicAdd(dst + 0, v.x);
    atomicAdd(dst + 1, v.y);
    atomicAdd(dst + 2, v.z);
    atomicAdd(dst + 3, v.w);
}

template <int G>
__global__ void bc_gather(const float* __restrict__ node,
                          const int* __restrict__ atoms,
                          float* __restrict__ out, int nCyc, int C) {
    int idx = blockIdx.x * blockDim.x + threadIdx.x;
    if (idx >= nCyc * C) return;
    int i = idx / C;
    int c = idx - i * C;
    float s = 0.f;
#pragma unroll
    for (int k = 0; k < G; k++) s += node[(size_t)atoms[i * G + k] * C + c];
    out[(size_t)i * C + c] = s;
}

template <int G>
__global__ void bc_scatter(const float* __restrict__ node64,
                           const int* __restrict__ atoms,
                           float* __restrict__ n128, int nCyc) {
    int idx = blockIdx.x * blockDim.x + threadIdx.x;
    if (idx >= nCyc * 64) return;
    int i = idx >> 6;
    int c = idx & 63;
    int a[G];
    float s = 0.f;
#pragma unroll
    for (int k = 0; k < G; k++) {
        a[k] = atoms[i * G + k];
        s += node64[(size_t)a[k] * 64 + c];
    }
#pragma unroll
    for (int k = 0; k < G; k++)
        atomicAdd(&n128[(size_t)a[k] * 128 + 64 + c], s);
}

__global__ void init_node128(const float* __restrict__ node64,
                             const float* __restrict__ cnt,
                             float* __restrict__ node128) {
    int idx = blockIdx.x * blockDim.x + threadIdx.x;
    if (idx >= NNODES * 64) return;
    int a = idx >> 6, c = idx & 63;
    float s = cnt[a];
    node128[(size_t)a * 128 + c] = s * node64[(size_t)a * 64 + c];
    node128[(size_t)a * 128 + 64 + c] = 0.f;
}

__global__ void init_nodeS(const float* __restrict__ n5,
                           const float* __restrict__ n6,
                           const float* __restrict__ c5,
                           const float* __restrict__ c6,
                           float* __restrict__ nodeS) {
    int idx = blockIdx.x * blockDim.x + threadIdx.x;
    if (idx >= NNODES * 320) return;
    int a = idx / 320, c = idx - a * 320;
    float v = 0.f;
    if (c < 128)
        v = c5[a] * n5[(size_t)a * 128 + c] + c6[a] * n6[(size_t)a * 128 + c];
    nodeS[idx] = v;
}

template <int G>
__global__ void scatter_grp4(const float* __restrict__ src,
                             const int* __restrict__ atoms,
                             float* __restrict__ dst, int rows, int C,
                             int pitch, int off) {
    int C4 = C >> 2;
    int idx = blockIdx.x * blockDim.x + threadIdx.x;
    if (idx >= rows * C4) return;
    int r = idx / C4;
    int c = (idx - r * C4) << 2;
    float4 v =
        *reinterpret_cast<const float4*>(&src[(size_t)(r / G) * C + c]);
    float* d = &dst[(size_t)atoms[r] * pitch + off + c];
    atomicAdd(d + 0, v.x);
    atomicAdd(d + 1, v.y);
    atomicAdd(d + 2, v.z);
    atomicAdd(d + 3, v.w);
}

__global__ void round_tf32(const float* __restrict__ src,
                           float* __restrict__ dst, int n) {
    int i = blockIdx.x * blockDim.x + threadIdx.x;
    if (i < n) dst[i] = f2tf(src[i]);
}

// edge compose: h[r] = F[r] + B[self] + Bm[a0] + Bm[a1] (fp16 out + stats)
__global__ void compose_edge(const __half* __restrict__ F,
                             const float* __restrict__ B,
                             const float* __restrict__ Bm,
                             const int* __restrict__ atoms,
                             __half* __restrict__ h,
                             float* __restrict__ stats) {
    int c = threadIdx.x;  // 128
    float s = 0.f, q = 0.f;
    for (int r = blockIdx.x; r < E_ROWS; r += gridDim.x) {
        int e = r >> 1;
        int a0 = atoms[2 * e], a1 = atoms[2 * e + 1];
        int self = (r & 1) ? a1 : a0;
        float v = __half2float(F[(size_t)r * 128 + c]) +
                  B[(size_t)self * 128 + c] + Bm[(size_t)a0 * 128 + c] +
                  Bm[(size_t)a1 * 128 + c];
        __half hv = __float2half_rn(v);
        h[(size_t)r * 128 + c] = hv;
        float vr = __half2float(hv);
        s += vr;
        q += vr * vr;
    }
    atomicAdd(&stats[c], s);
    atomicAdd(&stats[128 + c], q);
}

// cycle compose: h[r] = F[r] + P[atoms[r]] + R[r/G] (fp16 out + stats)
template <int G>
__global__ void compose_cyc(const __half* __restrict__ F,
                            const float* __restrict__ P,
                            const float* __restrict__ R,
                            const int* __restrict__ atoms,
                            __half* __restrict__ h, int rows,
                            float* __restrict__ stats) {
    int c = threadIdx.x;  // 128
    float s = 0.f, q = 0.f;
    for (int r = blockIdx.x; r < rows; r += gridDim.x) {
        int a = atoms[r];
        float v = __half2float(F[(size_t)r * 128 + c]) +
                  P[(size_t)a * 128 + c] + R[(size_t)(r / G) * 128 + c];
        __half hv = __float2half_rn(v);
        h[(size_t)r * 128 + c] = hv;
        float vr = __half2float(hv);
        s += vr;
        q += vr * vr;
    }
    atomicAdd(&stats[c], s);
    atomicAdd(&stats[128 + c], q);
}

// BN2 + ReLU, inline scale/shift, fp16 z input
__global__ void bn_relu_out(const __half* __restrict__ z,
                            const float* __restrict__ stats,
                            const float* __restrict__ g,
                            const float* __restrict__ b, float invM,
                            float* __restrict__ out, size_t n) {
    __shared__ float ss[128];
    int tid = threadIdx.x;
    if (tid < 64) {
        float m = stats[tid] * invM;
        float v = stats[128 + tid] * invM - m * m;
        v = fmaxf(v, 0.f);
        float s = g[tid] * rsqrtf(v + EPS);
        ss[tid] = s;
        ss[64 + tid] = b[tid] - m * s;
    }
    __syncthreads();
    size_t idx = (size_t)blockIdx.x * blockDim.x + tid;
    if (idx >= n) return;
    int c = (int)(idx & 63);
    out[idx] = fmaxf(__half2float(z[idx]) * ss[c] + ss[64 + c], 0.f);
}

// ---------------------------------------------------------------------------
// Host orchestration
// ---------------------------------------------------------------------------
static inline int cdiv(int a, int b) { return (a + b - 1) / b; }

static void* sym_addr(const void* s) {
    void* p = nullptr;
    cudaGetSymbolAddress(&p, s);
    return p;
}

// smem bytes: 1024 + 2*(A + B)
static const int SMEM_F32_128 = 1024 + 2 * (128 * 144 + 32 * 136 * 4);  // 72704
static const int SMEM_F16_64 = 1024 + 2 * (128 * 80 + 32 * 72 * 4);     // 39936

extern "C" void kernel_launch(void* const* d_in, const int* in_sizes, int n_in,
                              void* d_out, int out_size) {
    static bool attr_done = false;
    if (!attr_done) {
        cudaFuncSetAttribute(gemm_mma<128, false, false, false, true>,
                             cudaFuncAttributeMaxDynamicSharedMemorySize,
                             SMEM_F32_128);
        cudaFuncSetAttribute(gemm_mma<128, false, false, false, false>,
                             cudaFuncAttributeMaxDynamicSharedMemorySize,
                             SMEM_F32_128);
        cudaFuncSetAttribute(gemm_mma<64, true, true, true, true>,
                             cudaFuncAttributeMaxDynamicSharedMemorySize,
                             SMEM_F16_64);
        attr_done = true;
    }

    const float* edge_feats = (const float*)d_in[0];
    const float* c5_feats = (const float*)d_in[1];
    const float* c6_feats = (const float*)d_in[2];
    const int* e_atoms = (const int*)d_in[3];
    const int* c5_atoms = (const int*)d_in[4];
    const int* c6_atoms = (const int*)d_in[5];
    const float* eW1 = (const float*)d_in[6];
    const float* eg1 = (const float*)d_in[7];
    const float* eb1 = (const float*)d_in[8];
    const float* eW2 = (const float*)d_in[9];
    const float* eg2 = (const float*)d_in[10];
    const float* eb2 = (const float*)d_in[11];
    const float* cW1 = (const float*)d_in[12];
    const float* cg1 = (const float*)d_in[13];
    const float* cb1 = (const float*)d_in[14];
    const float* cW2 = (const float*)d_in[15];
    const float* cg2 = (const float*)d_in[16];
    const float* cb2 = (const float*)d_in[17];

    float* out_edge = (float*)d_out;
    float* out_c5 = out_edge + (size_t)E_ROWS * H;
    float* out_c6 = out_c5 + (size_t)C5_ROWS * H;

    float* node64 = (float*)sym_addr(g_node64);
    float* cnt5 = node64 + NNODES * 64;
    float* cnt6 = node64 + NNODES * 65;
    float* n128_5 = (float*)sym_addr(g_n128_5);
    float* n128_6 = (float*)sym_addr(g_n128_6);
    float* b2_5 = (float*)sym_addr(g_b2_5);
    float* b2_6 = (float*)sym_addr(g_b2_6);
    float* nodeS = (float*)sym_addr(g_nodeS);
    float* Bt = (float*)sym_addr(g_B);
    float* Bm = (float*)sym_addr(g_Bm);
    float* P = (float*)sym_addr(g_P);
    float* R = (float*)sym_addr(g_R);
    __half* F = (__half*)sym_addr(g_F);
    __half* h = (__half*)sym_addr(g_h);
    __half* z = (__half*)sym_addr(g_z);
    float* wE1 = (float*)sym_addr(g_wE1);
    float* wE2 = (float*)sym_addr(g_wE2);
    float* wC1 = (float*)sym_addr(g_wC1);
    float* wC2 = (float*)sym_addr(g_wC2);
    float* stats = (float*)sym_addr(g_stats);
    float* stE1 = stats;
    float* stE2 = stats + 256;
    float* st51 = stats + 512;
    float* st52 = stats + 768;
    float* st61 = stats + 1024;
    float* st62 = stats + 1280;

    const int TB = 256;

    // #1-3: weight rounding; #4: edge F GEMM (profiled launch)
    round_tf32<<<cdiv(704 * 128, TB), TB>>>(eW1, wE1, 704 * 128);
    round_tf32<<<cdiv(320 * 128, TB), TB>>>(cW1, wC1, 320 * 128);
    round_tf32<<<cdiv(128 * 64, TB), TB>>>(eW2, wE2, 128 * 64);
    gemm_mma<128, false, false, false, true>
        <<<cdiv(E_ROWS, 128), 256, SMEM_F32_128>>>(
            edge_feats, wE1, F, E_ROWS, 64, nullptr, nullptr, nullptr, 0.f,
            nullptr);
    round_tf32<<<cdiv(128 * 64, TB), TB>>>(cW2, wC2, 128 * 64);
    zero_kernel<<<cdiv(6 * 256, TB), TB>>>(stats, 6 * 256);

    // ---- scatter chain (fp32 exact) ----
    zero_kernel<<<cdiv(NNODES * 66, TB), TB>>>(node64, (size_t)NNODES * 66);
    scatter_add4<<<cdiv(E_ROWS * 16, TB), TB>>>(edge_feats, e_atoms, node64,
                                                E_ROWS, 64);
    count_atoms<<<cdiv(C5_ROWS, TB), TB>>>(c5_atoms, cnt5, C5_ROWS);
    count_atoms<<<cdiv(C6_ROWS, TB), TB>>>(c6_atoms, cnt6, C6_ROWS);

    init_node128<<<cdiv(NNODES * 64, TB), TB>>>(node64, cnt5, n128_5);
    init_node128<<<cdiv(NNODES * 64, TB), TB>>>(node64, cnt6, n128_6);
    bc_scatter<5><<<cdiv(NC5 * 64, TB), TB>>>(node64, c5_atoms, n128_5, NC5);
    bc_scatter<6><<<cdiv(NC6 * 64, TB), TB>>>(node64, c6_atoms, n128_6, NC6);

    bc_gather<5><<<cdiv(NC5 * 128, TB), TB>>>(n128_5, c5_atoms, b2_5, NC5, 128);
    bc_gather<6><<<cdiv(NC6 * 128, TB), TB>>>(n128_6, c6_atoms, b2_6, NC6, 128);

    init_nodeS<<<cdiv(NNODES * 320, TB), TB>>>(n128_5, n128_6, cnt5, cnt6,
                                               nodeS);
    scatter_grp4<5><<<cdiv(C5_ROWS * 32, TB), TB>>>(b2_5, c5_atoms, nodeS,
                                                    C5_ROWS, 128, 320, 128);
    scatter_grp4<6><<<cdiv(C6_ROWS * 32, TB), TB>>>(b2_6, c6_atoms, nodeS,
                                                    C6_ROWS, 128, 320, 128);
    scatter_grp4<1><<<cdiv(C5_ROWS * 16, TB), TB>>>(c5_feats, c5_atoms, nodeS,
                                                    C5_ROWS, 64, 320, 256);
    scatter_grp4<1><<<cdiv(C6_ROWS * 16, TB), TB>>>(c6_feats, c6_atoms, nodeS,
                                                    C6_ROWS, 64, 320, 256);

    // ================= EDGE MLP =================
    gemm_mma<128, false, false, false, false>
        <<<cdiv(NNODES, 128), 256, SMEM_F32_128>>>(
            nodeS, wE1 + 64 * 128, Bt, NNODES, 320, nullptr, nullptr, nullptr,
            0.f, nullptr);
    gemm_mma<128, false, false, false, false>
        <<<cdiv(NNODES, 128), 256, SMEM_F32_128>>>(
            nodeS, wE1 + 384 * 128, Bm, NNODES, 320, nullptr, nullptr,
            nullptr, 0.f, nullptr);
    compose_edge<<<2048, 128>>>(F, Bt, Bm, e_atoms, h, stE1);
    gemm_mma<64, true, true, true, true>
        <<<cdiv(E_ROWS, 128), 256, SMEM_F16_64>>>(
            h, wE2, z, E_ROWS, 128, stE1, eg1, eb1, 1.f / E_ROWS, stE2);
    bn_relu_out<<<cdiv(E_ROWS * 64, TB), TB>>>(z, stE2, eg2, eb2,
                                               1.f / E_ROWS, out_edge,
                                               (size_t)E_ROWS * 64);

    // ================= CYCLE5 MLP =================
    gemm_mma<128, false, false, false, true>
        <<<cdiv(C5_ROWS, 128), 256, SMEM_F32_128>>>(
            c5_feats, wC1 + 256 * 128, F, C5_ROWS, 64, nullptr, nullptr,
            nullptr, 0.f, nullptr);
    gemm_mma<128, false, false, false, false>
        <<<cdiv(NNODES, 128), 256, SMEM_F32_128>>>(
            n128_5, wC1, P, NNODES, 128, nullptr, nullptr, nullptr, 0.f,
            nullptr);
    gemm_mma<128, false, false, false, false>
        <<<cdiv(NC5, 128), 256, SMEM_F32_128>>>(
            b2_5, wC1 + 128 * 128, R, NC5, 128, nullptr, nullptr, nullptr,
            0.f, nullptr);
    compose_cyc<5><<<2048, 128>>>(F, P, R, c5_atoms, h, C5_ROWS, st51);
    gemm_mma<64, true, true, true, true>
        <<<cdiv(C5_ROWS, 128), 256, SMEM_F16_64>>>(
            h, wC2, z, C5_ROWS, 128, st51, cg1, cb1, 1.f / C5_ROWS, st52);
    bn_relu_out<<<cdiv(C5_ROWS * 64, TB), TB>>>(z, st52, cg2, cb2,
                                                1.f / C5_ROWS, out_c5,
                                                (size_t)C5_ROWS * 64);

    // ================= CYCLE6 MLP =================
    gemm_mma<128, false, false, false, true>
        <<<cdiv(C6_ROWS, 128), 256, SMEM_F32_128>>>(
            c6_feats, wC1 + 256 * 128, F, C6_ROWS, 64, nullptr, nullptr,
            nullptr, 0.f, nullptr);
    gemm_mma<128, false, false, false, false>
        <<<cdiv(NNODES, 128), 256, SMEM_F32_128>>>(
            n128_6, wC1, P, NNODES, 128, nullptr, nullptr, nullptr, 0.f,
            nullptr);
    gemm_mma<128, false, false, false, false>
        <<<cdiv(NC6, 128), 256, SMEM_F32_128>>>(
            b2_6, wC1 + 128 * 128, R, NC6, 128, nullptr, nullptr, nullptr,
            0.f, nullptr);
    compose_cyc<6><<<2048, 128>>>(F, P, R, c6_atoms, h, C6_ROWS, st61);
    gemm_mma<64, true, true, true, true>
        <<<cdiv(C6_ROWS, 128), 256, SMEM_F16_64>>>(
            h, wC2, z, C6_ROWS, 128, st61, cg1, cb1, 1.f / C6_ROWS, st62);
    bn_relu_out<<<cdiv(C6_ROWS * 64, TB), TB>>>(z, st62, cg2, cb2,
                                                1.f / C6_ROWS, out_c6,
                                                (size_t)C6_ROWS * 64);

    (void)in_sizes;
    (void)n_in;
    (void)out_size;
}

// round 14
// speedup vs baseline: 1.2206x; 1.0877x over previous
#include <cuda_runtime.h>
#include <cuda_fp16.h>
#include <cstdint>

// ---------------------------------------------------------------------------
// Problem constants
// ---------------------------------------------------------------------------
#define H 64
#define NNODES 40000
#define NE 60000
#define NC5 30000
#define NC6 25000
#define E_ROWS (2 * NE)      // 120000
#define C5_ROWS (5 * NC5)    // 150000
#define C6_ROWS (6 * NC6)    // 150000
#define EPS 1e-5f

#define PAD_E  120064
#define PAD_N  40064
#define PAD_R  30080
#define PAD_F  150016

// ---------------------------------------------------------------------------
// Device scratch
// ---------------------------------------------------------------------------
__device__ float g_node64[NNODES * 66];   // node64 | cnt5 | cnt6
__device__ float g_n128_5[NNODES * 128];
__device__ float g_n128_6[NNODES * 128];
__device__ float g_b2_5[NC5 * 128];
__device__ float g_b2_6[NC6 * 128];
__device__ float g_nodeS[NNODES * 320];
__device__ float g_B[PAD_N * 128];
__device__ float g_Bm[PAD_N * 128];
__device__ float g_P5[PAD_N * 128];
__device__ float g_P6[PAD_N * 128];
__device__ float g_R5[PAD_R * 128];
__device__ float g_R6[PAD_R * 128];
__device__ __half g_Fe[PAD_E * 128];
__device__ __half g_F5[PAD_F * 128];
__device__ __half g_F6[PAD_F * 128];
__device__ __half g_he[PAD_E * 128];
__device__ __half g_h5[PAD_F * 128];
__device__ __half g_h6[PAD_F * 128];
__device__ __half g_ze[PAD_E * 64];
__device__ __half g_z5[PAD_F * 64];
__device__ __half g_z6[PAD_F * 64];
__device__ float g_wE1[704 * 128];        // tf32-rounded weights
__device__ float g_wE2[128 * 64];
__device__ float g_wC1[320 * 128];
__device__ float g_wC2[128 * 64];
__device__ float g_stats[6 * 256];        // 6 buffers: sum | sumsq

// ---------------------------------------------------------------------------
// Helpers
// ---------------------------------------------------------------------------
__device__ __forceinline__ uint32_t smem_u32(const void* p) {
    uint32_t a;
    asm("{ .reg .u64 t; cvta.to.shared.u64 t, %1; cvt.u32.u64 %0, t; }"
        : "=r"(a) : "l"(p));
    return a;
}

__device__ __forceinline__ float f2tf(float x) {
    uint32_t r;
    asm("cvt.rna.tf32.f32 %0, %1;" : "=r"(r) : "f"(x));
    return __uint_as_float(r);
}

__device__ __forceinline__ uint32_t f2tf_u(float x) {
    uint32_t r;
    asm("cvt.rna.tf32.f32 %0, %1;" : "=r"(r) : "f"(x));
    return r;
}

__device__ __forceinline__ void cp16(uint32_t dst, const void* src, int nbytes) {
    asm volatile("cp.async.ca.shared.global [%0], [%1], 16, %2;"
                 :: "r"(dst), "l"(src), "r"(nbytes) : "memory");
}
__device__ __forceinline__ void cp_commit() {
    asm volatile("cp.async.commit_group;" ::: "memory");
}
__device__ __forceinline__ void cp_wait1() {
    asm volatile("cp.async.wait_group 1;" ::: "memory");
}

__device__ __forceinline__ void mma_tf32(float* d, const uint32_t* a,
                                         const uint32_t* b) {
    asm volatile(
        "mma.sync.aligned.m16n8k8.row.col.f32.tf32.tf32.f32 "
        "{%0,%1,%2,%3}, {%4,%5,%6,%7}, {%8,%9}, {%0,%1,%2,%3};"
        : "+f"(d[0]), "+f"(d[1]), "+f"(d[2]), "+f"(d[3])
        : "r"(a[0]), "r"(a[1]), "r"(a[2]), "r"(a[3]), "r"(b[0]), "r"(b[1]));
}

// ---------------------------------------------------------------------------
// tf32 mma.sync GEMM (round-13 geometry + dtype flags).
// ---------------------------------------------------------------------------
template <int BN, bool APPLY_IN, bool EPI_STATS, bool A_HALF, bool C_HALF>
__global__ void __launch_bounds__(256)
gemm_mma(const void* __restrict__ Av, const float* __restrict__ B,
         void* __restrict__ Cv, int M, int K,
         const float* __restrict__ statsIn, const float* __restrict__ g1,
         const float* __restrict__ b1, float invM,
         float* __restrict__ statsOut) {
    constexpr int BM = 128, BK = 32;
    constexpr int A_ROWB = A_HALF ? 80 : 144;
    constexpr int ASZB = BM * A_ROWB;
    constexpr int BSZB = BK * (BN + 8) * 4;
    constexpr int STGB = ASZB + BSZB;
    constexpr int SOFFB = 1024;
    constexpr int NT = BN / 16;

    extern __shared__ float sm[];
    const int tid = threadIdx.x;
    const int warp = tid >> 5, lane = tid & 31;
    const int qr = lane >> 2, ql = lane & 3;
    const int wm = warp >> 1, wn = warp & 1;
    const int mBase = blockIdx.x * BM;
    const uint32_t smBase = smem_u32(sm);

    if (APPLY_IN && tid < 128) {
        float scale = 1.f, shift = 0.f;
        if (tid < K) {
            float m = statsIn[tid] * invM;
            float v = statsIn[128 + tid] * invM - m * m;
            v = fmaxf(v, 0.f);
            float s = g1[tid] * rsqrtf(v + EPS);
            scale = s;
            shift = b1[tid] - m * s;
        }
        sm[tid] = scale;
        sm[128 + tid] = shift;
    }

    auto issue = [&](int s, int k0) {
        const int so = SOFFB + s * STGB;
        if (A_HALF) {
            const __half* A = (const __half*)Av;
#pragma unroll
            for (int j = 0; j < 2; j++) {
                int i = tid + 256 * j;
                int row = i >> 2, ch = i & 3;
                int gr = mBase + row;
                bool ok = gr < M;
                const __half* src =
                    A + (size_t)(ok ? gr : 0) * K + k0 + ch * 8;
                uint32_t dst = smBase + (uint32_t)(so + row * 80 + ch * 16);
                cp16(dst, src, ok ? 16 : 0);
            }
        } else {
            const float* A = (const float*)Av;
#pragma unroll
            for (int j = 0; j < 4; j++) {
                int i = tid + 256 * j;
                int row = i >> 3, ch = i & 7;
                int gr = mBase + row;
                bool ok = gr < M;
                const float* src =
                    A + (size_t)(ok ? gr : 0) * K + k0 + ch * 4;
                uint32_t dst = smBase + (uint32_t)(so + row * 144 + ch * 16);
                cp16(dst, src, ok ? 16 : 0);
            }
        }
#pragma unroll
        for (int j = 0; j < BK * BN / 4 / 256; j++) {
            int i = tid + 256 * j;
            int row = i / (BN / 4), c = i % (BN / 4);
            const float* src = B + (size_t)(k0 + row) * BN + c * 4;
            uint32_t dst = smBase +
                           (uint32_t)(so + ASZB + (row * (BN + 8) + c * 4) * 4);
            cp16(dst, src, 16);
        }
    };

    float acc[2][NT][4];
#pragma unroll
    for (int t = 0; t < 2; t++)
#pragma unroll
        for (int j = 0; j < NT; j++)
#pragma unroll
            for (int r = 0; r < 4; r++) acc[t][j][r] = 0.f;

    const int nCh = K / BK;
    issue(0, 0);
    cp_commit();

    for (int c = 0; c < nCh; c++) {
        if (c + 1 < nCh) issue((c + 1) & 1, (c + 1) * BK);
        cp_commit();
        cp_wait1();
        __syncthreads();

        const char* AsmB = (const char*)sm + SOFFB + (c & 1) * STGB;
        const uint32_t* Bsm = (const uint32_t*)(AsmB + ASZB);
#pragma unroll
        for (int ks = 0; ks < 4; ks++) {
            const int k = ks * 8;
            float s0 = 1.f, h0 = 0.f, s4 = 1.f, h4 = 0.f;
            if (APPLY_IN) {
                int kc = c * 32 + k + ql;
                s0 = sm[kc];
                h0 = sm[128 + kc];
                s4 = sm[kc + 4];
                h4 = sm[128 + kc + 4];
            }
            uint32_t a[2][4];
#pragma unroll
            for (int t = 0; t < 2; t++) {
                float v0, v1, v2, v3;
                int rbase = wm * 32 + t * 16 + qr;
                if (A_HALF) {
                    const __half* p =
                        (const __half*)AsmB + rbase * 40 + k + ql;
                    v0 = __half2float(p[0]);
                    v1 = __half2float(p[8 * 40]);
                    v2 = __half2float(p[4]);
                    v3 = __half2float(p[8 * 40 + 4]);
                } else {
                    const float* p = (const float*)AsmB + rbase * 36 + k + ql;
                    v0 = p[0];
                    v1 = p[8 * 36];
                    v2 = p[4];
                    v3 = p[8 * 36 + 4];
                }
                if (APPLY_IN) {
                    v0 = fmaxf(fmaf(v0, s0, h0), 0.f);
                    v1 = fmaxf(fmaf(v1, s0, h0), 0.f);
                    v2 = fmaxf(fmaf(v2, s4, h4), 0.f);
                    v3 = fmaxf(fmaf(v3, s4, h4), 0.f);
                }
                a[t][0] = f2tf_u(v0);
                a[t][1] = f2tf_u(v1);
                a[t][2] = f2tf_u(v2);
                a[t][3] = f2tf_u(v3);
            }
            uint32_t b[NT][2];
#pragma unroll
            for (int j = 0; j < NT; j++) {
                const uint32_t* p =
                    Bsm + (k + ql) * (BN + 8) + wn * (BN / 2) + j * 8 + qr;
                b[j][0] = p[0];
                b[j][1] = p[4 * (BN + 8)];
            }
#pragma unroll
            for (int t = 0; t < 2; t++)
#pragma unroll
                for (int j = 0; j < NT; j++) mma_tf32(acc[t][j], a[t], b[j]);
        }
        __syncthreads();
    }

    // ------------------ epilogue ------------------
    float ps[2 * NT], pq[2 * NT];
    if (EPI_STATS) {
#pragma unroll
        for (int i = 0; i < 2 * NT; i++) { ps[i] = 0.f; pq[i] = 0.f; }
    }

#pragma unroll
    for (int t = 0; t < 2; t++) {
#pragma unroll
        for (int rr = 0; rr < 2; rr++) {
            int row = mBase + wm * 32 + t * 16 + 8 * rr + qr;
            bool valid = row < M;
#pragma unroll
            for (int j = 0; j < NT; j++) {
                int n0 = wn * (BN / 2) + j * 8 + 2 * ql;
                float v0 = acc[t][j][2 * rr];
                float v1 = acc[t][j][2 * rr + 1];
                if (C_HALF) {
                    *reinterpret_cast<__half2*>(
                        (__half*)Cv + (size_t)row * BN + n0) =
                        __floats2half2_rn(v0, v1);
                } else {
                    *reinterpret_cast<float2*>(
                        (float*)Cv + (size_t)row * BN + n0) =
                        make_float2(v0, v1);
                }
                if (EPI_STATS && valid) {
                    ps[2 * j] += v0;
                    pq[2 * j] += v0 * v0;
                    ps[2 * j + 1] += v1;
                    pq[2 * j + 1] += v1 * v1;
                }
            }
        }
    }

    if (EPI_STATS) {
        __syncthreads();
        for (int i = tid; i < 2 * BN; i += 256) sm[i] = 0.f;
        __syncthreads();
#pragma unroll
        for (int j = 0; j < NT; j++) {
            int n0 = wn * (BN / 2) + j * 8 + 2 * ql;
            atomicAdd(&sm[n0], ps[2 * j]);
            atomicAdd(&sm[n0 + 1], ps[2 * j + 1]);
            atomicAdd(&sm[BN + n0], pq[2 * j]);
            atomicAdd(&sm[BN + n0 + 1], pq[2 * j + 1]);
        }
        __syncthreads();
        if (tid < BN) {
            atomicAdd(&statsOut[tid], sm[tid]);
            atomicAdd(&statsOut[128 + tid], sm[BN + tid]);
        }
    }
}

// ---------------------------------------------------------------------------
// Memory-phase kernels
// ---------------------------------------------------------------------------
__global__ void zero_kernel(float* __restrict__ p, size_t n) {
    size_t i = (size_t)blockIdx.x * blockDim.x + threadIdx.x;
    if (i < n) p[i] = 0.f;
}

__global__ void count_atoms(const int* __restrict__ atoms,
                            float* __restrict__ cnt, int rows) {
    int i = blockIdx.x * blockDim.x + threadIdx.x;
    if (i < rows) atomicAdd(&cnt[atoms[i]], 1.f);
}

__global__ void scatter_add4(const float* __restrict__ src,
                             const int* __restrict__ atoms,
                             float* __restrict__ node, int rows, int C) {
    int C4 = C >> 2;
    int idx = blockIdx.x * blockDim.x + threadIdx.x;
    if (idx >= rows * C4) return;
    int r = idx / C4;
    int c = (idx - r * C4) << 2;
    float4 v = *reinterpret_cast<const float4*>(&src[(size_t)r * C + c]);
    float* dst = &node[(size_t)atoms[r] * C + c];
    atomicAdd(dst + 0, v.x);
    atomicAdd(dst + 1, v.y);
    atomicAdd(dst + 2, v.z);
    atomicAdd(dst + 3, v.w);
}

template <int G>
__global__ void bc_gather(const float* __restrict__ node,
                          const int* __restrict__ atoms,
                          float* __restrict__ out, int nCyc, int C) {
    int idx = blockIdx.x * blockDim.x + threadIdx.x;
    if (idx >= nCyc * C) return;
    int i = idx / C;
    int c = idx - i * C;
    float s = 0.f;
#pragma unroll
    for (int k = 0; k < G; k++) s += node[(size_t)atoms[i * G + k] * C + c];
    out[(size_t)i * C + c] = s;
}

template <int G>
__global__ void bc_scatter(const float* __restrict__ node64,
                           const int* __restrict__ atoms,
                           float* __restrict__ n128, int nCyc) {
    int idx = blockIdx.x * blockDim.x + threadIdx.x;
    if (idx >= nCyc * 64) return;
    int i = idx >> 6;
    int c = idx & 63;
    int a[G];
    float s = 0.f;
#pragma unroll
    for (int k = 0; k < G; k++) {
        a[k] = atoms[i * G + k];
        s += node64[(size_t)a[k] * 64 + c];
    }
#pragma unroll
    for (int k = 0; k < G; k++)
        atomicAdd(&n128[(size_t)a[k] * 128 + 64 + c], s);
}

__global__ void init_node128(const float* __restrict__ node64,
                             const float* __restrict__ cnt,
                             float* __restrict__ node128) {
    int idx = blockIdx.x * blockDim.x + threadIdx.x;
    if (idx >= NNODES * 64) return;
    int a = idx >> 6, c = idx & 63;
    float s = cnt[a];
    node128[(size_t)a * 128 + c] = s * node64[(size_t)a * 64 + c];
    node128[(size_t)a * 128 + 64 + c] = 0.f;
}

__global__ void init_nodeS(const float* __restrict__ n5,
                           const float* __restrict__ n6,
                           const float* __restrict__ c5,
                           const float* __restrict__ c6,
                           float* __restrict__ nodeS) {
    int idx = blockIdx.x * blockDim.x + threadIdx.x;
    if (idx >= NNODES * 320) return;
    int a = idx / 320, c = idx - a * 320;
    float v = 0.f;
    if (c < 128)
        v = c5[a] * n5[(size_t)a * 128 + c] + c6[a] * n6[(size_t)a * 128 + c];
    nodeS[idx] = v;
}

template <int G>
__global__ void scatter_grp4(const float* __restrict__ src,
                             const int* __restrict__ atoms,
                             float* __restrict__ dst, int rows, int C,
                             int pitch, int off) {
    int C4 = C >> 2;
    int idx = blockIdx.x * blockDim.x + threadIdx.x;
    if (idx >= rows * C4) return;
    int r = idx / C4;
    int c = (idx - r * C4) << 2;
    float4 v =
        *reinterpret_cast<const float4*>(&src[(size_t)(r / G) * C + c]);
    float* d = &dst[(size_t)atoms[r] * pitch + off + c];
    atomicAdd(d + 0, v.x);
    atomicAdd(d + 1, v.y);
    atomicAdd(d + 2, v.z);
    atomicAdd(d + 3, v.w);
}

__global__ void round_tf32(const float* __restrict__ src,
                           float* __restrict__ dst, int n) {
    int i = blockIdx.x * blockDim.x + threadIdx.x;
    if (i < n) dst[i] = f2tf(src[i]);
}

// edge compose: h[r] = F[r] + B[self] + Bm[a0] + Bm[a1] (fp16 out + stats)
__global__ void compose_edge(const __half* __restrict__ F,
                             const float* __restrict__ B,
                             const float* __restrict__ Bm,
                             const int* __restrict__ atoms,
                             __half* __restrict__ h,
                             float* __restrict__ stats) {
    int c = threadIdx.x;  // 128
    float s = 0.f, q = 0.f;
    for (int r = blockIdx.x; r < E_ROWS; r += gridDim.x) {
        int e = r >> 1;
        int a0 = atoms[2 * e], a1 = atoms[2 * e + 1];
        int self = (r & 1) ? a1 : a0;
        float v = __half2float(F[(size_t)r * 128 + c]) +
                  B[(size_t)self * 128 + c] + Bm[(size_t)a0 * 128 + c] +
                  Bm[(size_t)a1 * 128 + c];
        __half hv = __float2half_rn(v);
        h[(size_t)r * 128 + c] = hv;
        float vr = __half2float(hv);
        s += vr;
        q += vr * vr;
    }
    atomicAdd(&stats[c], s);
    atomicAdd(&stats[128 + c], q);
}

// cycle compose: h[r] = F[r] + P[atoms[r]] + R[r/G] (fp16 out + stats)
template <int G>
__global__ void compose_cyc(const __half* __restrict__ F,
                            const float* __restrict__ P,
                            const float* __restrict__ R,
                            const int* __restrict__ atoms,
                            __half* __restrict__ h, int rows,
                            float* __restrict__ stats) {
    int c = threadIdx.x;  // 128
    float s = 0.f, q = 0.f;
    for (int r = blockIdx.x; r < rows; r += gridDim.x) {
        int a = atoms[r];
        float v = __half2float(F[(size_t)r * 128 + c]) +
                  P[(size_t)a * 128 + c] + R[(size_t)(r / G) * 128 + c];
        __half hv = __float2half_rn(v);
        h[(size_t)r * 128 + c] = hv;
        float vr = __half2float(hv);
        s += vr;
        q += vr * vr;
    }
    atomicAdd(&stats[c], s);
    atomicAdd(&stats[128 + c], q);
}

// BN2 + ReLU, inline scale/shift, fp16 z input
__global__ void bn_relu_out(const __half* __restrict__ z,
                            const float* __restrict__ stats,
                            const float* __restrict__ g,
                            const float* __restrict__ b, float invM,
                            float* __restrict__ out, size_t n) {
    __shared__ float ss[128];
    int tid = threadIdx.x;
    if (tid < 64) {
        float m = stats[tid] * invM;
        float v = stats[128 + tid] * invM - m * m;
        v = fmaxf(v, 0.f);
        float s = g[tid] * rsqrtf(v + EPS);
        ss[tid] = s;
        ss[64 + tid] = b[tid] - m * s;
    }
    __syncthreads();
    size_t idx = (size_t)blockIdx.x * blockDim.x + tid;
    if (idx >= n) return;
    int c = (int)(idx & 63);
    out[idx] = fmaxf(__half2float(z[idx]) * ss[c] + ss[64 + c], 0.f);
}

// ---------------------------------------------------------------------------
// Host orchestration
// ---------------------------------------------------------------------------
static inline int cdiv(int a, int b) { return (a + b - 1) / b; }

static void* sym_addr(const void* s) {
    void* p = nullptr;
    cudaGetSymbolAddress(&p, s);
    return p;
}

static const int SMEM_F32_128 = 1024 + 2 * (128 * 144 + 32 * 136 * 4);  // 72704
static const int SMEM_F16_64 = 1024 + 2 * (128 * 80 + 32 * 72 * 4);     // 39936

extern "C" void kernel_launch(void* const* d_in, const int* in_sizes, int n_in,
                              void* d_out, int out_size) {
    static bool init_done = false;
    static cudaStream_t s1, s2;
    static cudaEvent_t evW, ev5, ev6, evD1, evD2;
    if (!init_done) {
        cudaFuncSetAttribute(gemm_mma<128, false, false, false, true>,
                             cudaFuncAttributeMaxDynamicSharedMemorySize,
                             SMEM_F32_128);
        cudaFuncSetAttribute(gemm_mma<128, false, false, false, false>,
                             cudaFuncAttributeMaxDynamicSharedMemorySize,
                             SMEM_F32_128);
        cudaFuncSetAttribute(gemm_mma<64, true, true, true, true>,
                             cudaFuncAttributeMaxDynamicSharedMemorySize,
                             SMEM_F16_64);
        cudaStreamCreateWithFlags(&s1, cudaStreamNonBlocking);
        cudaStreamCreateWithFlags(&s2, cudaStreamNonBlocking);
        cudaEventCreateWithFlags(&evW, cudaEventDisableTiming);
        cudaEventCreateWithFlags(&ev5, cudaEventDisableTiming);
        cudaEventCreateWithFlags(&ev6, cudaEventDisableTiming);
        cudaEventCreateWithFlags(&evD1, cudaEventDisableTiming);
        cudaEventCreateWithFlags(&evD2, cudaEventDisableTiming);
        init_done = true;
    }

    const float* edge_feats = (const float*)d_in[0];
    const float* c5_feats = (const float*)d_in[1];
    const float* c6_feats = (const float*)d_in[2];
    const int* e_atoms = (const int*)d_in[3];
    const int* c5_atoms = (const int*)d_in[4];
    const int* c6_atoms = (const int*)d_in[5];
    const float* eW1 = (const float*)d_in[6];
    const float* eg1 = (const float*)d_in[7];
    const float* eb1 = (const float*)d_in[8];
    const float* eW2 = (const float*)d_in[9];
    const float* eg2 = (const float*)d_in[10];
    const float* eb2 = (const float*)d_in[11];
    const float* cW1 = (const float*)d_in[12];
    const float* cg1 = (const float*)d_in[13];
    const float* cb1 = (const float*)d_in[14];
    const float* cW2 = (const float*)d_in[15];
    const float* cg2 = (const float*)d_in[16];
    const float* cb2 = (const float*)d_in[17];

    float* out_edge = (float*)d_out;
    float* out_c5 = out_edge + (size_t)E_ROWS * H;
    float* out_c6 = out_c5 + (size_t)C5_ROWS * H;

    float* node64 = (float*)sym_addr(g_node64);
    float* cnt5 = node64 + NNODES * 64;
    float* cnt6 = node64 + NNODES * 65;
    float* n128_5 = (float*)sym_addr(g_n128_5);
    float* n128_6 = (float*)sym_addr(g_n128_6);
    float* b2_5 = (float*)sym_addr(g_b2_5);
    float* b2_6 = (float*)sym_addr(g_b2_6);
    float* nodeS = (float*)sym_addr(g_nodeS);
    float* Bt = (float*)sym_addr(g_B);
    float* Bm = (float*)sym_addr(g_Bm);
    float* P5 = (float*)sym_addr(g_P5);
    float* P6 = (float*)sym_addr(g_P6);
    float* R5 = (float*)sym_addr(g_R5);
    float* R6 = (float*)sym_addr(g_R6);
    __half* Fe = (__half*)sym_addr(g_Fe);
    __half* F5 = (__half*)sym_addr(g_F5);
    __half* F6 = (__half*)sym_addr(g_F6);
    __half* he = (__half*)sym_addr(g_he);
    __half* h5 = (__half*)sym_addr(g_h5);
    __half* h6 = (__half*)sym_addr(g_h6);
    __half* ze = (__half*)sym_addr(g_ze);
    __half* z5 = (__half*)sym_addr(g_z5);
    __half* z6 = (__half*)sym_addr(g_z6);
    float* wE1 = (float*)sym_addr(g_wE1);
    float* wE2 = (float*)sym_addr(g_wE2);
    float* wC1 = (float*)sym_addr(g_wC1);
    float* wC2 = (float*)sym_addr(g_wC2);
    float* stats = (float*)sym_addr(g_stats);
    float* stE1 = stats;
    float* stE2 = stats + 256;
    float* st51 = stats + 512;
    float* st52 = stats + 768;
    float* st61 = stats + 1024;
    float* st62 = stats + 1280;

    const int TB = 256;

    // ---- main: weight rounding + stats zero ----
    round_tf32<<<cdiv(704 * 128, TB), TB>>>(eW1, wE1, 704 * 128);
    round_tf32<<<cdiv(320 * 128, TB), TB>>>(cW1, wC1, 320 * 128);
    round_tf32<<<cdiv(128 * 64, TB), TB>>>(eW2, wE2, 128 * 64);
    round_tf32<<<cdiv(128 * 64, TB), TB>>>(cW2, wC2, 128 * 64);
    zero_kernel<<<cdiv(6 * 256, TB), TB>>>(stats, 6 * 256);

    // ---- fork: cycle F GEMMs run on s1/s2 concurrently with main ----
    cudaEventRecord(evW, 0);
    cudaStreamWaitEvent(s1, evW, 0);
    cudaStreamWaitEvent(s2, evW, 0);
    gemm_mma<128, false, false, false, true>
        <<<cdiv(C5_ROWS, 128), 256, SMEM_F32_128, s1>>>(
            c5_feats, wC1 + 256 * 128, F5, C5_ROWS, 64, nullptr, nullptr,
            nullptr, 0.f, nullptr);
    gemm_mma<128, false, false, false, true>
        <<<cdiv(C6_ROWS, 128), 256, SMEM_F32_128, s2>>>(
            c6_feats, wC1 + 256 * 128, F6, C6_ROWS, 64, nullptr, nullptr,
            nullptr, 0.f, nullptr);

    // ---- main: edge F GEMM + scatter chain ----
    gemm_mma<128, false, false, false, true>
        <<<cdiv(E_ROWS, 128), 256, SMEM_F32_128>>>(
            edge_feats, wE1, Fe, E_ROWS, 64, nullptr, nullptr, nullptr, 0.f,
            nullptr);
    zero_kernel<<<cdiv(NNODES * 66, TB), TB>>>(node64, (size_t)NNODES * 66);
    scatter_add4<<<cdiv(E_ROWS * 16, TB), TB>>>(edge_feats, e_atoms, node64,
                                                E_ROWS, 64);
    count_atoms<<<cdiv(C5_ROWS, TB), TB>>>(c5_atoms, cnt5, C5_ROWS);
    count_atoms<<<cdiv(C6_ROWS, TB), TB>>>(c6_atoms, cnt6, C6_ROWS);

    init_node128<<<cdiv(NNODES * 64, TB), TB>>>(node64, cnt5, n128_5);
    bc_scatter<5><<<cdiv(NC5 * 64, TB), TB>>>(node64, c5_atoms, n128_5, NC5);
    bc_gather<5><<<cdiv(NC5 * 128, TB), TB>>>(n128_5, c5_atoms, b2_5, NC5, 128);
    cudaEventRecord(ev5, 0);

    init_node128<<<cdiv(NNODES * 64, TB), TB>>>(node64, cnt6, n128_6);
    bc_scatter<6><<<cdiv(NC6 * 64, TB), TB>>>(node64, c6_atoms, n128_6, NC6);
    bc_gather<6><<<cdiv(NC6 * 128, TB), TB>>>(n128_6, c6_atoms, b2_6, NC6, 128);
    cudaEventRecord(ev6, 0);

    // ---- s1: cycle5 MLP ----
    cudaStreamWaitEvent(s1, ev5, 0);
    gemm_mma<128, false, false, false, false>
        <<<cdiv(NNODES, 128), 256, SMEM_F32_128, s1>>>(
            n128_5, wC1, P5, NNODES, 128, nullptr, nullptr, nullptr, 0.f,
            nullptr);
    gemm_mma<128, false, false, false, false>
        <<<cdiv(NC5, 128), 256, SMEM_F32_128, s1>>>(
            b2_5, wC1 + 128 * 128, R5, NC5, 128, nullptr, nullptr, nullptr,
            0.f, nullptr);
    compose_cyc<5><<<2048, 128, 0, s1>>>(F5, P5, R5, c5_atoms, h5, C5_ROWS,
                                         st51);
    gemm_mma<64, true, true, true, true>
        <<<cdiv(C5_ROWS, 128), 256, SMEM_F16_64, s1>>>(
            h5, wC2, z5, C5_ROWS, 128, st51, cg1, cb1, 1.f / C5_ROWS, st52);
    bn_relu_out<<<cdiv(C5_ROWS * 64, TB), TB, 0, s1>>>(
        z5, st52, cg2, cb2, 1.f / C5_ROWS, out_c5, (size_t)C5_ROWS * 64);
    cudaEventRecord(evD1, s1);

    // ---- s2: cycle6 MLP ----
    cudaStreamWaitEvent(s2, ev6, 0);
    gemm_mma<128, false, false, false, false>
        <<<cdiv(NNODES, 128), 256, SMEM_F32_128, s2>>>(
            n128_6, wC1, P6, NNODES, 128, nullptr, nullptr, nullptr, 0.f,
            nullptr);
    gemm_mma<128, false, false, false, false>
        <<<cdiv(NC6, 128), 256, SMEM_F32_128, s2>>>(
            b2_6, wC1 + 128 * 128, R6, NC6, 128, nullptr, nullptr, nullptr,
            0.f, nullptr);
    compose_cyc<6><<<2048, 128, 0, s2>>>(F6, P6, R6, c6_atoms, h6, C6_ROWS,
                                         st61);
    gemm_mma<64, true, true, true, true>
        <<<cdiv(C6_ROWS, 128), 256, SMEM_F16_64, s2>>>(
            h6, wC2, z6, C6_ROWS, 128, st61, cg1, cb1, 1.f / C6_ROWS, st62);
    bn_relu_out<<<cdiv(C6_ROWS * 64, TB), TB, 0, s2>>>(
        z6, st62, cg2, cb2, 1.f / C6_ROWS, out_c6, (size_t)C6_ROWS * 64);
    cudaEventRecord(evD2, s2);

    // ---- main: nodeS + edge MLP ----
    init_nodeS<<<cdiv(NNODES * 320, TB), TB>>>(n128_5, n128_6, cnt5, cnt6,
                                               nodeS);
    scatter_grp4<5><<<cdiv(C5_ROWS * 32, TB), TB>>>(b2_5, c5_atoms, nodeS,
                                                    C5_ROWS, 128, 320, 128);
    scatter_grp4<6><<<cdiv(C6_ROWS * 32, TB), TB>>>(b2_6, c6_atoms, nodeS,
                                                    C6_ROWS, 128, 320, 128);
    scatter_grp4<1><<<cdiv(C5_ROWS * 16, TB), TB>>>(c5_feats, c5_atoms, nodeS,
                                                    C5_ROWS, 64, 320, 256);
    scatter_grp4<1><<<cdiv(C6_ROWS * 16, TB), TB>>>(c6_feats, c6_atoms, nodeS,
                                                    C6_ROWS, 64, 320, 256);
    gemm_mma<128, false, false, false, false>
        <<<cdiv(NNODES, 128), 256, SMEM_F32_128>>>(
            nodeS, wE1 + 64 * 128, Bt, NNODES, 320, nullptr, nullptr, nullptr,
            0.f, nullptr);
    gemm_mma<128, false, false, false, false>
        <<<cdiv(NNODES, 128), 256, SMEM_F32_128>>>(
            nodeS, wE1 + 384 * 128, Bm, NNODES, 320, nullptr, nullptr,
            nullptr, 0.f, nullptr);
    compose_edge<<<2048, 128>>>(Fe, Bt, Bm, e_atoms, he, stE1);
    gemm_mma<64, true, true, true, true>
        <<<cdiv(E_ROWS, 128), 256, SMEM_F16_64>>>(
            he, wE2, ze, E_ROWS, 128, stE1, eg1, eb1, 1.f / E_ROWS, stE2);
    bn_relu_out<<<cdiv(E_ROWS * 64, TB), TB>>>(ze, stE2, eg2, eb2,
                                               1.f / E_ROWS, out_edge,
                                               (size_t)E_ROWS * 64);

    // ---- join ----
    cudaStreamWaitEvent(0, evD1, 0);
    cudaStreamWaitEvent(0, evD2, 0);

    (void)in_sizes;
    (void)n_in;
    (void)out_size;
}

// round 15
// speedup vs baseline: 1.2768x; 1.0461x over previous
#include <cuda_runtime.h>
#include <cuda_fp16.h>
#include <cstdint>

// ---------------------------------------------------------------------------
// Problem constants
// ---------------------------------------------------------------------------
#define H 64
#define NNODES 40000
#define NE 60000
#define NC5 30000
#define NC6 25000
#define E_ROWS (2 * NE)      // 120000
#define C5_ROWS (5 * NC5)    // 150000
#define C6_ROWS (6 * NC6)    // 150000
#define EPS 1e-5f

#define PAD_E  120064
#define PAD_N  40064
#define PAD_R  30080
#define PAD_F  150016

// ---------------------------------------------------------------------------
// Device scratch
// ---------------------------------------------------------------------------
__device__ float g_node64[NNODES * 66];   // node64 | cnt5 | cnt6
__device__ float g_n128_5[NNODES * 128];
__device__ float g_n128_6[NNODES * 128];
__device__ float g_b2_5[NC5 * 128];
__device__ float g_b2_6[NC6 * 128];
__device__ float g_nodeS[NNODES * 320];
__device__ float g_B[PAD_N * 128];
__device__ float g_Bm[PAD_N * 128];
__device__ float g_P5[PAD_N * 128];
__device__ float g_P6[PAD_N * 128];
__device__ float g_R5[PAD_R * 128];
__device__ float g_R6[PAD_R * 128];
__device__ __half g_Fe[PAD_E * 128];
__device__ __half g_F5[PAD_F * 128];
__device__ __half g_F6[PAD_F * 128];
__device__ __half g_he[PAD_E * 128];
__device__ __half g_h5[PAD_F * 128];
__device__ __half g_h6[PAD_F * 128];
__device__ __half g_ze[PAD_E * 64];
__device__ __half g_z5[PAD_F * 64];
__device__ __half g_z6[PAD_F * 64];
__device__ float g_wE1[704 * 128];        // tf32-rounded weights
__device__ float g_wE2[128 * 64];
__device__ float g_wC1[320 * 128];
__device__ float g_wC2[128 * 64];
__device__ float g_stats[6 * 256];

// ---------------------------------------------------------------------------
// Helpers
// ---------------------------------------------------------------------------
__device__ __forceinline__ uint32_t smem_u32(const void* p) {
    uint32_t a;
    asm("{ .reg .u64 t; cvta.to.shared.u64 t, %1; cvt.u32.u64 %0, t; }"
        : "=r"(a) : "l"(p));
    return a;
}

__device__ __forceinline__ float f2tf(float x) {
    uint32_t r;
    asm("cvt.rna.tf32.f32 %0, %1;" : "=r"(r) : "f"(x));
    return __uint_as_float(r);
}

__device__ __forceinline__ uint32_t f2tf_u(float x) {
    uint32_t r;
    asm("cvt.rna.tf32.f32 %0, %1;" : "=r"(r) : "f"(x));
    return r;
}

__device__ __forceinline__ void cp16(uint32_t dst, const void* src, int nbytes) {
    asm volatile("cp.async.ca.shared.global [%0], [%1], 16, %2;"
                 :: "r"(dst), "l"(src), "r"(nbytes) : "memory");
}
__device__ __forceinline__ void cp_commit() {
    asm volatile("cp.async.commit_group;" ::: "memory");
}
__device__ __forceinline__ void cp_wait1() {
    asm volatile("cp.async.wait_group 1;" ::: "memory");
}

__device__ __forceinline__ void mma_tf32(float* d, const uint32_t* a,
                                         const uint32_t* b) {
    asm volatile(
        "mma.sync.aligned.m16n8k8.row.col.f32.tf32.tf32.f32 "
        "{%0,%1,%2,%3}, {%4,%5,%6,%7}, {%8,%9}, {%0,%1,%2,%3};"
        : "+f"(d[0]), "+f"(d[1]), "+f"(d[2]), "+f"(d[3])
        : "r"(a[0]), "r"(a[1]), "r"(a[2]), "r"(a[3]), "r"(b[0]), "r"(b[1]));
}

// ---------------------------------------------------------------------------
// tf32 mma.sync GEMM (round-13 geometry + dtype flags).
// ---------------------------------------------------------------------------
template <int BN, bool APPLY_IN, bool EPI_STATS, bool A_HALF, bool C_HALF>
__global__ void __launch_bounds__(256)
gemm_mma(const void* __restrict__ Av, const float* __restrict__ B,
         void* __restrict__ Cv, int M, int K,
         const float* __restrict__ statsIn, const float* __restrict__ g1,
         const float* __restrict__ b1, float invM,
         float* __restrict__ statsOut) {
    constexpr int BM = 128, BK = 32;
    constexpr int A_ROWB = A_HALF ? 80 : 144;
    constexpr int ASZB = BM * A_ROWB;
    constexpr int BSZB = BK * (BN + 8) * 4;
    constexpr int STGB = ASZB + BSZB;
    constexpr int SOFFB = 1024;
    constexpr int NT = BN / 16;

    extern __shared__ float sm[];
    const int tid = threadIdx.x;
    const int warp = tid >> 5, lane = tid & 31;
    const int qr = lane >> 2, ql = lane & 3;
    const int wm = warp >> 1, wn = warp & 1;
    const int mBase = blockIdx.x * BM;
    const uint32_t smBase = smem_u32(sm);

    if (APPLY_IN && tid < 128) {
        float scale = 1.f, shift = 0.f;
        if (tid < K) {
            float m = statsIn[tid] * invM;
            float v = statsIn[128 + tid] * invM - m * m;
            v = fmaxf(v, 0.f);
            float s = g1[tid] * rsqrtf(v + EPS);
            scale = s;
            shift = b1[tid] - m * s;
        }
        sm[tid] = scale;
        sm[128 + tid] = shift;
    }

    auto issue = [&](int s, int k0) {
        const int so = SOFFB + s * STGB;
        if (A_HALF) {
            const __half* A = (const __half*)Av;
#pragma unroll
            for (int j = 0; j < 2; j++) {
                int i = tid + 256 * j;
                int row = i >> 2, ch = i & 3;
                int gr = mBase + row;
                bool ok = gr < M;
                const __half* src =
                    A + (size_t)(ok ? gr : 0) * K + k0 + ch * 8;
                uint32_t dst = smBase + (uint32_t)(so + row * 80 + ch * 16);
                cp16(dst, src, ok ? 16 : 0);
            }
        } else {
            const float* A = (const float*)Av;
#pragma unroll
            for (int j = 0; j < 4; j++) {
                int i = tid + 256 * j;
                int row = i >> 3, ch = i & 7;
                int gr = mBase + row;
                bool ok = gr < M;
                const float* src =
                    A + (size_t)(ok ? gr : 0) * K + k0 + ch * 4;
                uint32_t dst = smBase + (uint32_t)(so + row * 144 + ch * 16);
                cp16(dst, src, ok ? 16 : 0);
            }
        }
#pragma unroll
        for (int j = 0; j < BK * BN / 4 / 256; j++) {
            int i = tid + 256 * j;
            int row = i / (BN / 4), c = i % (BN / 4);
            const float* src = B + (size_t)(k0 + row) * BN + c * 4;
            uint32_t dst = smBase +
                           (uint32_t)(so + ASZB + (row * (BN + 8) + c * 4) * 4);
            cp16(dst, src, 16);
        }
    };

    float acc[2][NT][4];
#pragma unroll
    for (int t = 0; t < 2; t++)
#pragma unroll
        for (int j = 0; j < NT; j++)
#pragma unroll
            for (int r = 0; r < 4; r++) acc[t][j][r] = 0.f;

    const int nCh = K / BK;
    issue(0, 0);
    cp_commit();

    for (int c = 0; c < nCh; c++) {
        if (c + 1 < nCh) issue((c + 1) & 1, (c + 1) * BK);
        cp_commit();
        cp_wait1();
        __syncthreads();

        const char* AsmB = (const char*)sm + SOFFB + (c & 1) * STGB;
        const uint32_t* Bsm = (const uint32_t*)(AsmB + ASZB);
#pragma unroll
        for (int ks = 0; ks < 4; ks++) {
            const int k = ks * 8;
            float s0 = 1.f, h0 = 0.f, s4 = 1.f, h4 = 0.f;
            if (APPLY_IN) {
                int kc = c * 32 + k + ql;
                s0 = sm[kc];
                h0 = sm[128 + kc];
                s4 = sm[kc + 4];
                h4 = sm[128 + kc + 4];
            }
            uint32_t a[2][4];
#pragma unroll
            for (int t = 0; t < 2; t++) {
                float v0, v1, v2, v3;
                int rbase = wm * 32 + t * 16 + qr;
                if (A_HALF) {
                    const __half* p =
                        (const __half*)AsmB + rbase * 40 + k + ql;
                    v0 = __half2float(p[0]);
                    v1 = __half2float(p[8 * 40]);
                    v2 = __half2float(p[4]);
                    v3 = __half2float(p[8 * 40 + 4]);
                } else {
                    const float* p = (const float*)AsmB + rbase * 36 + k + ql;
                    v0 = p[0];
                    v1 = p[8 * 36];
                    v2 = p[4];
                    v3 = p[8 * 36 + 4];
                }
                if (APPLY_IN) {
                    v0 = fmaxf(fmaf(v0, s0, h0), 0.f);
                    v1 = fmaxf(fmaf(v1, s0, h0), 0.f);
                    v2 = fmaxf(fmaf(v2, s4, h4), 0.f);
                    v3 = fmaxf(fmaf(v3, s4, h4), 0.f);
                }
                a[t][0] = f2tf_u(v0);
                a[t][1] = f2tf_u(v1);
                a[t][2] = f2tf_u(v2);
                a[t][3] = f2tf_u(v3);
            }
            uint32_t b[NT][2];
#pragma unroll
            for (int j = 0; j < NT; j++) {
                const uint32_t* p =
                    Bsm + (k + ql) * (BN + 8) + wn * (BN / 2) + j * 8 + qr;
                b[j][0] = p[0];
                b[j][1] = p[4 * (BN + 8)];
            }
#pragma unroll
            for (int t = 0; t < 2; t++)
#pragma unroll
                for (int j = 0; j < NT; j++) mma_tf32(acc[t][j], a[t], b[j]);
        }
        __syncthreads();
    }

    // ------------------ epilogue ------------------
    float ps[2 * NT], pq[2 * NT];
    if (EPI_STATS) {
#pragma unroll
        for (int i = 0; i < 2 * NT; i++) { ps[i] = 0.f; pq[i] = 0.f; }
    }

#pragma unroll
    for (int t = 0; t < 2; t++) {
#pragma unroll
        for (int rr = 0; rr < 2; rr++) {
            int row = mBase + wm * 32 + t * 16 + 8 * rr + qr;
            bool valid = row < M;
#pragma unroll
            for (int j = 0; j < NT; j++) {
                int n0 = wn * (BN / 2) + j * 8 + 2 * ql;
                float v0 = acc[t][j][2 * rr];
                float v1 = acc[t][j][2 * rr + 1];
                if (C_HALF) {
                    *reinterpret_cast<__half2*>(
                        (__half*)Cv + (size_t)row * BN + n0) =
                        __floats2half2_rn(v0, v1);
                } else {
                    *reinterpret_cast<float2*>(
                        (float*)Cv + (size_t)row * BN + n0) =
                        make_float2(v0, v1);
                }
                if (EPI_STATS && valid) {
                    ps[2 * j] += v0;
                    pq[2 * j] += v0 * v0;
                    ps[2 * j + 1] += v1;
                    pq[2 * j + 1] += v1 * v1;
                }
            }
        }
    }

    if (EPI_STATS) {
        __syncthreads();
        for (int i = tid; i < 2 * BN; i += 256) sm[i] = 0.f;
        __syncthreads();
#pragma unroll
        for (int j = 0; j < NT; j++) {
            int n0 = wn * (BN / 2) + j * 8 + 2 * ql;
            atomicAdd(&sm[n0], ps[2 * j]);
            atomicAdd(&sm[n0 + 1], ps[2 * j + 1]);
            atomicAdd(&sm[BN + n0], pq[2 * j]);
            atomicAdd(&sm[BN + n0 + 1], pq[2 * j + 1]);
        }
        __syncthreads();
        if (tid < BN) {
            atomicAdd(&statsOut[tid], sm[tid]);
            atomicAdd(&statsOut[128 + tid], sm[BN + tid]);
        }
    }
}

// ---------------------------------------------------------------------------
// Memory-phase kernels
// ---------------------------------------------------------------------------
__global__ void zero_kernel(float* __restrict__ p, size_t n) {
    size_t i = (size_t)blockIdx.x * blockDim.x + threadIdx.x;
    if (i < n) p[i] = 0.f;
}

// zero nodeS columns [128, 320) (strided region)
__global__ void zero_nodeS_tail(float* __restrict__ nodeS) {
    int idx = blockIdx.x * blockDim.x + threadIdx.x;
    if (idx >= NNODES * 192) return;
    int a = idx / 192, c = idx - a * 192 + 128;
    nodeS[(size_t)a * 320 + c] = 0.f;
}

__global__ void count_atoms(const int* __restrict__ atoms,
                            float* __restrict__ cnt, int rows) {
    int i = blockIdx.x * blockDim.x + threadIdx.x;
    if (i < rows) atomicAdd(&cnt[atoms[i]], 1.f);
}

__global__ void scatter_add4(const float* __restrict__ src,
                             const int* __restrict__ atoms,
                             float* __restrict__ node, int rows, int C) {
    int C4 = C >> 2;
    int idx = blockIdx.x * blockDim.x + threadIdx.x;
    if (idx >= rows * C4) return;
    int r = idx / C4;
    int c = (idx - r * C4) << 2;
    float4 v = *reinterpret_cast<const float4*>(&src[(size_t)r * C + c]);
    float* dst = &node[(size_t)atoms[r] * C + c];
    atomicAdd(dst + 0, v.x);
    atomicAdd(dst + 1, v.y);
    atomicAdd(dst + 2, v.z);
    atomicAdd(dst + 3, v.w);
}

template <int G>
__global__ void bc_gather(const float* __restrict__ node,
                          const int* __restrict__ atoms,
                          float* __restrict__ out, int nCyc, int C) {
    int idx = blockIdx.x * blockDim.x + threadIdx.x;
    if (idx >= nCyc * C) return;
    int i = idx / C;
    int c = idx - i * C;
    float s = 0.f;
#pragma unroll
    for (int k = 0; k < G; k++) s += node[(size_t)atoms[i * G + k] * C + c];
    out[(size_t)i * C + c] = s;
}

template <int G>
__global__ void bc_scatter(const float* __restrict__ node64,
                           const int* __restrict__ atoms,
                           float* __restrict__ n128, int nCyc) {
    int idx = blockIdx.x * blockDim.x + threadIdx.x;
    if (idx >= nCyc * 64) return;
    int i = idx >> 6;
    int c = idx & 63;
    int a[G];
    float s = 0.f;
#pragma unroll
    for (int k = 0; k < G; k++) {
        a[k] = atoms[i * G + k];
        s += node64[(size_t)a[k] * 64 + c];
    }
#pragma unroll
    for (int k = 0; k < G; k++)
        atomicAdd(&n128[(size_t)a[k] * 128 + 64 + c], s);
}

__global__ void init_node128(const float* __restrict__ node64,
                             const float* __restrict__ cnt,
                             float* __restrict__ node128) {
    int idx = blockIdx.x * blockDim.x + threadIdx.x;
    if (idx >= NNODES * 64) return;
    int a = idx >> 6, c = idx & 63;
    float s = cnt[a];
    node128[(size_t)a * 128 + c] = s * node64[(size_t)a * 64 + c];
    node128[(size_t)a * 128 + 64 + c] = 0.f;
}

// nodeS cols [0,128) = cnt5*n5 + cnt6*n6 (write; tail pre-zeroed)
__global__ void add_nodeS(const float* __restrict__ n5,
                          const float* __restrict__ n6,
                          const float* __restrict__ c5,
                          const float* __restrict__ c6,
                          float* __restrict__ nodeS) {
    int idx = blockIdx.x * blockDim.x + threadIdx.x;
    if (idx >= NNODES * 128) return;
    int a = idx >> 7, c = idx & 127;
    nodeS[(size_t)a * 320 + c] =
        c5[a] * n5[(size_t)a * 128 + c] + c6[a] * n6[(size_t)a * 128 + c];
}

template <int G>
__global__ void scatter_grp4(const float* __restrict__ src,
                             const int* __restrict__ atoms,
                             float* __restrict__ dst, int rows, int C,
                             int pitch, int off) {
    int C4 = C >> 2;
    int idx = blockIdx.x * blockDim.x + threadIdx.x;
    if (idx >= rows * C4) return;
    int r = idx / C4;
    int c = (idx - r * C4) << 2;
    float4 v =
        *reinterpret_cast<const float4*>(&src[(size_t)(r / G) * C + c]);
    float* d = &dst[(size_t)atoms[r] * pitch + off + c];
    atomicAdd(d + 0, v.x);
    atomicAdd(d + 1, v.y);
    atomicAdd(d + 2, v.z);
    atomicAdd(d + 3, v.w);
}

__global__ void round_tf32(const float* __restrict__ src,
                           float* __restrict__ dst, int n) {
    int i = blockIdx.x * blockDim.x + threadIdx.x;
    if (i < n) dst[i] = f2tf(src[i]);
}

__global__ void compose_edge(const __half* __restrict__ F,
                             const float* __restrict__ B,
                             const float* __restrict__ Bm,
                             const int* __restrict__ atoms,
                             __half* __restrict__ h,
                             float* __restrict__ stats) {
    int c = threadIdx.x;  // 128
    float s = 0.f, q = 0.f;
    for (int r = blockIdx.x; r < E_ROWS; r += gridDim.x) {
        int e = r >> 1;
        int a0 = atoms[2 * e], a1 = atoms[2 * e + 1];
        int self = (r & 1) ? a1 : a0;
        float v = __half2float(F[(size_t)r * 128 + c]) +
                  B[(size_t)self * 128 + c] + Bm[(size_t)a0 * 128 + c] +
                  Bm[(size_t)a1 * 128 + c];
        __half hv = __float2half_rn(v);
        h[(size_t)r * 128 + c] = hv;
        float vr = __half2float(hv);
        s += vr;
        q += vr * vr;
    }
    atomicAdd(&stats[c], s);
    atomicAdd(&stats[128 + c], q);
}

template <int G>
__global__ void compose_cyc(const __half* __restrict__ F,
                            const float* __restrict__ P,
                            const float* __restrict__ R,
                            const int* __restrict__ atoms,
                            __half* __restrict__ h, int rows,
                            float* __restrict__ stats) {
    int c = threadIdx.x;  // 128
    float s = 0.f, q = 0.f;
    for (int r = blockIdx.x; r < rows; r += gridDim.x) {
        int a = atoms[r];
        float v = __half2float(F[(size_t)r * 128 + c]) +
                  P[(size_t)a * 128 + c] + R[(size_t)(r / G) * 128 + c];
        __half hv = __float2half_rn(v);
        h[(size_t)r * 128 + c] = hv;
        float vr = __half2float(hv);
        s += vr;
        q += vr * vr;
    }
    atomicAdd(&stats[c], s);
    atomicAdd(&stats[128 + c], q);
}

__global__ void bn_relu_out(const __half* __restrict__ z,
                            const float* __restrict__ stats,
                            const float* __restrict__ g,
                            const float* __restrict__ b, float invM,
                            float* __restrict__ out, size_t n) {
    __shared__ float ss[128];
    int tid = threadIdx.x;
    if (tid < 64) {
        float m = stats[tid] * invM;
        float v = stats[128 + tid] * invM - m * m;
        v = fmaxf(v, 0.f);
        float s = g[tid] * rsqrtf(v + EPS);
        ss[tid] = s;
        ss[64 + tid] = b[tid] - m * s;
    }
    __syncthreads();
    size_t idx = (size_t)blockIdx.x * blockDim.x + tid;
    if (idx >= n) return;
    int c = (int)(idx & 63);
    out[idx] = fmaxf(__half2float(z[idx]) * ss[c] + ss[64 + c], 0.f);
}

// ---------------------------------------------------------------------------
// Host orchestration
// ---------------------------------------------------------------------------
static inline int cdiv(int a, int b) { return (a + b - 1) / b; }

static void* sym_addr(const void* s) {
    void* p = nullptr;
    cudaGetSymbolAddress(&p, s);
    return p;
}

static const int SMEM_F32_128 = 1024 + 2 * (128 * 144 + 32 * 136 * 4);  // 72704
static const int SMEM_F16_64 = 1024 + 2 * (128 * 80 + 32 * 72 * 4);     // 39936

extern "C" void kernel_launch(void* const* d_in, const int* in_sizes, int n_in,
                              void* d_out, int out_size) {
    static bool init_done = false;
    static cudaStream_t s1, s2;
    static cudaEvent_t evW, evNZ, evCnt, ev5, ev6, evD1, evD2;
    if (!init_done) {
        cudaFuncSetAttribute(gemm_mma<128, false, false, false, true>,
                             cudaFuncAttributeMaxDynamicSharedMemorySize,
                             SMEM_F32_128);
        cudaFuncSetAttribute(gemm_mma<128, false, false, false, false>,
                             cudaFuncAttributeMaxDynamicSharedMemorySize,
                             SMEM_F32_128);
        cudaFuncSetAttribute(gemm_mma<64, true, true, true, true>,
                             cudaFuncAttributeMaxDynamicSharedMemorySize,
                             SMEM_F16_64);
        cudaStreamCreateWithFlags(&s1, cudaStreamNonBlocking);
        cudaStreamCreateWithFlags(&s2, cudaStreamNonBlocking);
        cudaEventCreateWithFlags(&evW, cudaEventDisableTiming);
        cudaEventCreateWithFlags(&evNZ, cudaEventDisableTiming);
        cudaEventCreateWithFlags(&evCnt, cudaEventDisableTiming);
        cudaEventCreateWithFlags(&ev5, cudaEventDisableTiming);
        cudaEventCreateWithFlags(&ev6, cudaEventDisableTiming);
        cudaEventCreateWithFlags(&evD1, cudaEventDisableTiming);
        cudaEventCreateWithFlags(&evD2, cudaEventDisableTiming);
        init_done = true;
    }

    const float* edge_feats = (const float*)d_in[0];
    const float* c5_feats = (const float*)d_in[1];
    const float* c6_feats = (const float*)d_in[2];
    const int* e_atoms = (const int*)d_in[3];
    const int* c5_atoms = (const int*)d_in[4];
    const int* c6_atoms = (const int*)d_in[5];
    const float* eW1 = (const float*)d_in[6];
    const float* eg1 = (const float*)d_in[7];
    const float* eb1 = (const float*)d_in[8];
    const float* eW2 = (const float*)d_in[9];
    const float* eg2 = (const float*)d_in[10];
    const float* eb2 = (const float*)d_in[11];
    const float* cW1 = (const float*)d_in[12];
    const float* cg1 = (const float*)d_in[13];
    const float* cb1 = (const float*)d_in[14];
    const float* cW2 = (const float*)d_in[15];
    const float* cg2 = (const float*)d_in[16];
    const float* cb2 = (const float*)d_in[17];

    float* out_edge = (float*)d_out;
    float* out_c5 = out_edge + (size_t)E_ROWS * H;
    float* out_c6 = out_c5 + (size_t)C5_ROWS * H;

    float* node64 = (float*)sym_addr(g_node64);
    float* cnt5 = node64 + NNODES * 64;
    float* cnt6 = node64 + NNODES * 65;
    float* n128_5 = (float*)sym_addr(g_n128_5);
    float* n128_6 = (float*)sym_addr(g_n128_6);
    float* b2_5 = (float*)sym_addr(g_b2_5);
    float* b2_6 = (float*)sym_addr(g_b2_6);
    float* nodeS = (float*)sym_addr(g_nodeS);
    float* Bt = (float*)sym_addr(g_B);
    float* Bm = (float*)sym_addr(g_Bm);
    float* P5 = (float*)sym_addr(g_P5);
    float* P6 = (float*)sym_addr(g_P6);
    float* R5 = (float*)sym_addr(g_R5);
    float* R6 = (float*)sym_addr(g_R6);
    __half* Fe = (__half*)sym_addr(g_Fe);
    __half* F5 = (__half*)sym_addr(g_F5);
    __half* F6 = (__half*)sym_addr(g_F6);
    __half* he = (__half*)sym_addr(g_he);
    __half* h5 = (__half*)sym_addr(g_h5);
    __half* h6 = (__half*)sym_addr(g_h6);
    __half* ze = (__half*)sym_addr(g_ze);
    __half* z5 = (__half*)sym_addr(g_z5);
    __half* z6 = (__half*)sym_addr(g_z6);
    float* wE1 = (float*)sym_addr(g_wE1);
    float* wE2 = (float*)sym_addr(g_wE2);
    float* wC1 = (float*)sym_addr(g_wC1);
    float* wC2 = (float*)sym_addr(g_wC2);
    float* stats = (float*)sym_addr(g_stats);
    float* stE1 = stats;
    float* stE2 = stats + 256;
    float* st51 = stats + 512;
    float* st52 = stats + 768;
    float* st61 = stats + 1024;
    float* st62 = stats + 1280;

    const int TB = 256;

    // ---- main prologue ----
    round_tf32<<<cdiv(704 * 128, TB), TB>>>(eW1, wE1, 704 * 128);
    round_tf32<<<cdiv(320 * 128, TB), TB>>>(cW1, wC1, 320 * 128);
    round_tf32<<<cdiv(128 * 64, TB), TB>>>(eW2, wE2, 128 * 64);
    round_tf32<<<cdiv(128 * 64, TB), TB>>>(cW2, wC2, 128 * 64);
    cudaEventRecord(evW, 0);
    zero_kernel<<<cdiv(6 * 256, TB), TB>>>(stats, 6 * 256);
    zero_nodeS_tail<<<cdiv(NNODES * 192, TB), TB>>>(nodeS);
    cudaEventRecord(evNZ, 0);
    zero_kernel<<<cdiv(NNODES * 66, TB), TB>>>(node64, (size_t)NNODES * 66);
    scatter_add4<<<cdiv(E_ROWS * 16, TB), TB>>>(edge_feats, e_atoms, node64,
                                                E_ROWS, 64);
    count_atoms<<<cdiv(C5_ROWS, TB), TB>>>(c5_atoms, cnt5, C5_ROWS);
    count_atoms<<<cdiv(C6_ROWS, TB), TB>>>(c6_atoms, cnt6, C6_ROWS);
    cudaEventRecord(evCnt, 0);

    // ---- s1: cycle5 pipeline ----
    cudaStreamWaitEvent(s1, evW, 0);
    gemm_mma<128, false, false, false, true>
        <<<cdiv(C5_ROWS, 128), 256, SMEM_F32_128, s1>>>(
            c5_feats, wC1 + 256 * 128, F5, C5_ROWS, 64, nullptr, nullptr,
            nullptr, 0.f, nullptr);
    cudaStreamWaitEvent(s1, evNZ, 0);
    scatter_grp4<1><<<cdiv(C5_ROWS * 16, TB), TB, 0, s1>>>(
        c5_feats, c5_atoms, nodeS, C5_ROWS, 64, 320, 256);
    cudaStreamWaitEvent(s1, evCnt, 0);
    init_node128<<<cdiv(NNODES * 64, TB), TB, 0, s1>>>(node64, cnt5, n128_5);
    bc_scatter<5><<<cdiv(NC5 * 64, TB), TB, 0, s1>>>(node64, c5_atoms,
                                                     n128_5, NC5);
    bc_gather<5><<<cdiv(NC5 * 128, TB), TB, 0, s1>>>(n128_5, c5_atoms, b2_5,
                                                     NC5, 128);
    cudaEventRecord(ev5, s1);
    gemm_mma<128, false, false, false, false>
        <<<cdiv(NNODES, 128), 256, SMEM_F32_128, s1>>>(
            n128_5, wC1, P5, NNODES, 128, nullptr, nullptr, nullptr, 0.f,
            nullptr);
    gemm_mma<128, false, false, false, false>
        <<<cdiv(NC5, 128), 256, SMEM_F32_128, s1>>>(
            b2_5, wC1 + 128 * 128, R5, NC5, 128, nullptr, nullptr, nullptr,
            0.f, nullptr);
    compose_cyc<5><<<2048, 128, 0, s1>>>(F5, P5, R5, c5_atoms, h5, C5_ROWS,
                                         st51);
    gemm_mma<64, true, true, true, true>
        <<<cdiv(C5_ROWS, 128), 256, SMEM_F16_64, s1>>>(
            h5, wC2, z5, C5_ROWS, 128, st51, cg1, cb1, 1.f / C5_ROWS, st52);
    bn_relu_out<<<cdiv(C5_ROWS * 64, TB), TB, 0, s1>>>(
        z5, st52, cg2, cb2, 1.f / C5_ROWS, out_c5, (size_t)C5_ROWS * 64);
    cudaEventRecord(evD1, s1);

    // ---- s2: cycle6 pipeline ----
    cudaStreamWaitEvent(s2, evW, 0);
    gemm_mma<128, false, false, false, true>
        <<<cdiv(C6_ROWS, 128), 256, SMEM_F32_128, s2>>>(
            c6_feats, wC1 + 256 * 128, F6, C6_ROWS, 64, nullptr, nullptr,
            nullptr, 0.f, nullptr);
    cudaStreamWaitEvent(s2, evNZ, 0);
    scatter_grp4<1><<<cdiv(C6_ROWS * 16, TB), TB, 0, s2>>>(
        c6_feats, c6_atoms, nodeS, C6_ROWS, 64, 320, 256);
    cudaStreamWaitEvent(s2, evCnt, 0);
    init_node128<<<cdiv(NNODES * 64, TB), TB, 0, s2>>>(node64, cnt6, n128_6);
    bc_scatter<6><<<cdiv(NC6 * 64, TB), TB, 0, s2>>>(node64, c6_atoms,
                                                     n128_6, NC6);
    bc_gather<6><<<cdiv(NC6 * 128, TB), TB, 0, s2>>>(n128_6, c6_atoms, b2_6,
                                                     NC6, 128);
    cudaEventRecord(ev6, s2);
    gemm_mma<128, false, false, false, false>
        <<<cdiv(NNODES, 128), 256, SMEM_F32_128, s2>>>(
            n128_6, wC1, P6, NNODES, 128, nullptr, nullptr, nullptr, 0.f,
            nullptr);
    gemm_mma<128, false, false, false, false>
        <<<cdiv(NC6, 128), 256, SMEM_F32_128, s2>>>(
            b2_6, wC1 + 128 * 128, R6, NC6, 128, nullptr, nullptr, nullptr,
            0.f, nullptr);
    compose_cyc<6><<<2048, 128, 0, s2>>>(F6, P6, R6, c6_atoms, h6, C6_ROWS,
                                         st61);
    gemm_mma<64, true, true, true, true>
        <<<cdiv(C6_ROWS, 128), 256, SMEM_F16_64, s2>>>(
            h6, wC2, z6, C6_ROWS, 128, st61, cg1, cb1, 1.f / C6_ROWS, st62);
    bn_relu_out<<<cdiv(C6_ROWS * 64, TB), TB, 0, s2>>>(
        z6, st62, cg2, cb2, 1.f / C6_ROWS, out_c6, (size_t)C6_ROWS * 64);
    cudaEventRecord(evD2, s2);

    // ---- main: edge path ----
    gemm_mma<128, false, false, false, true>
        <<<cdiv(E_ROWS, 128), 256, SMEM_F32_128>>>(
            edge_feats, wE1, Fe, E_ROWS, 64, nullptr, nullptr, nullptr, 0.f,
            nullptr);
    cudaStreamWaitEvent(0, ev5, 0);
    cudaStreamWaitEvent(0, ev6, 0);
    add_nodeS<<<cdiv(NNODES * 128, TB), TB>>>(n128_5, n128_6, cnt5, cnt6,
                                              nodeS);
    scatter_grp4<5><<<cdiv(C5_ROWS * 32, TB), TB>>>(b2_5, c5_atoms, nodeS,
                                                    C5_ROWS, 128, 320, 128);
    scatter_grp4<6><<<cdiv(C6_ROWS * 32, TB), TB>>>(b2_6, c6_atoms, nodeS,
                                                    C6_ROWS, 128, 320, 128);
    gemm_mma<128, false, false, false, false>
        <<<cdiv(NNODES, 128), 256, SMEM_F32_128>>>(
            nodeS, wE1 + 64 * 128, Bt, NNODES, 320, nullptr, nullptr, nullptr,
            0.f, nullptr);
    gemm_mma<128, false, false, false, false>
        <<<cdiv(NNODES, 128), 256, SMEM_F32_128>>>(
            nodeS, wE1 + 384 * 128, Bm, NNODES, 320, nullptr, nullptr,
            nullptr, 0.f, nullptr);
    compose_edge<<<2048, 128>>>(Fe, Bt, Bm, e_atoms, he, stE1);
    gemm_mma<64, true, true, true, true>
        <<<cdiv(E_ROWS, 128), 256, SMEM_F16_64>>>(
            he, wE2, ze, E_ROWS, 128, stE1, eg1, eb1, 1.f / E_ROWS, stE2);
    bn_relu_out<<<cdiv(E_ROWS * 64, TB), TB>>>(ze, stE2, eg2, eb2,
                                               1.f / E_ROWS, out_edge,
                                               (size_t)E_ROWS * 64);

    // ---- join ----
    cudaStreamWaitEvent(0, evD1, 0);
    cudaStreamWaitEvent(0, evD2, 0);

    (void)in_sizes;
    (void)n_in;
    (void)out_size;
}

// round 16
// speedup vs baseline: 1.2940x; 1.0134x over previous
#include <cuda_runtime.h>
#include <cuda_fp16.h>
#include <cstdint>

// ---------------------------------------------------------------------------
// Problem constants
// ---------------------------------------------------------------------------
#define H 64
#define NNODES 40000
#define NE 60000
#define NC5 30000
#define NC6 25000
#define E_ROWS (2 * NE)      // 120000
#define C5_ROWS (5 * NC5)    // 150000
#define C6_ROWS (6 * NC6)    // 150000
#define EPS 1e-5f

#define PAD_E  120064
#define PAD_N  40064
#define PAD_R  30080
#define PAD_F  150016

// ---------------------------------------------------------------------------
// Device scratch
// ---------------------------------------------------------------------------
__device__ float g_node64[NNODES * 66];   // node64 | cnt5 | cnt6
__device__ float g_n128_5[NNODES * 128];
__device__ float g_n128_6[NNODES * 128];
__device__ float g_b2_5[NC5 * 128];
__device__ float g_b2_6[NC6 * 128];
__device__ float g_nodeS[NNODES * 320];
__device__ float g_B[PAD_N * 128];
__device__ float g_Bm[PAD_N * 128];
__device__ float g_P5[PAD_N * 128];
__device__ float g_P6[PAD_N * 128];
__device__ float g_R5[PAD_R * 128];
__device__ float g_R6[PAD_R * 128];
__device__ __half g_Fe[PAD_E * 128];
__device__ __half g_F5[PAD_F * 128];
__device__ __half g_F6[PAD_F * 128];
__device__ __half g_he[PAD_E * 128];
__device__ __half g_h5[PAD_F * 128];
__device__ __half g_h6[PAD_F * 128];
__device__ __half g_ze[PAD_E * 64];
__device__ __half g_z5[PAD_F * 64];
__device__ __half g_z6[PAD_F * 64];
__device__ float g_wE1[704 * 128];        // tf32-rounded weights
__device__ float g_wE2[128 * 64];
__device__ float g_wC1[320 * 128];
__device__ float g_wC2[128 * 64];
__device__ float g_stats[6 * 256];

// ---------------------------------------------------------------------------
// Helpers
// ---------------------------------------------------------------------------
__device__ __forceinline__ uint32_t smem_u32(const void* p) {
    uint32_t a;
    asm("{ .reg .u64 t; cvta.to.shared.u64 t, %1; cvt.u32.u64 %0, t; }"
        : "=r"(a) : "l"(p));
    return a;
}

__device__ __forceinline__ float f2tf(float x) {
    uint32_t r;
    asm("cvt.rna.tf32.f32 %0, %1;" : "=r"(r) : "f"(x));
    return __uint_as_float(r);
}

__device__ __forceinline__ uint32_t f2tf_u(float x) {
    uint32_t r;
    asm("cvt.rna.tf32.f32 %0, %1;" : "=r"(r) : "f"(x));
    return r;
}

__device__ __forceinline__ void cp16(uint32_t dst, const void* src, int nbytes) {
    asm volatile("cp.async.ca.shared.global [%0], [%1], 16, %2;"
                 :: "r"(dst), "l"(src), "r"(nbytes) : "memory");
}
__device__ __forceinline__ void cp_commit() {
    asm volatile("cp.async.commit_group;" ::: "memory");
}
__device__ __forceinline__ void cp_wait1() {
    asm volatile("cp.async.wait_group 1;" ::: "memory");
}

__device__ __forceinline__ void mma_tf32(float* d, const uint32_t* a,
                                         const uint32_t* b) {
    asm volatile(
        "mma.sync.aligned.m16n8k8.row.col.f32.tf32.tf32.f32 "
        "{%0,%1,%2,%3}, {%4,%5,%6,%7}, {%8,%9}, {%0,%1,%2,%3};"
        : "+f"(d[0]), "+f"(d[1]), "+f"(d[2]), "+f"(d[3])
        : "r"(a[0]), "r"(a[1]), "r"(a[2]), "r"(a[3]), "r"(b[0]), "r"(b[1]));
}

// ---------------------------------------------------------------------------
// tf32 mma.sync GEMM (round-13 geometry + dtype flags).
// ---------------------------------------------------------------------------
template <int BN, bool APPLY_IN, bool EPI_STATS, bool A_HALF, bool C_HALF>
__global__ void __launch_bounds__(256)
gemm_mma(const void* __restrict__ Av, const float* __restrict__ B,
         void* __restrict__ Cv, int M, int K,
         const float* __restrict__ statsIn, const float* __restrict__ g1,
         const float* __restrict__ b1, float invM,
         float* __restrict__ statsOut) {
    constexpr int BM = 128, BK = 32;
    constexpr int A_ROWB = A_HALF ? 80 : 144;
    constexpr int ASZB = BM * A_ROWB;
    constexpr int BSZB = BK * (BN + 8) * 4;
    constexpr int STGB = ASZB + BSZB;
    constexpr int SOFFB = 1024;
    constexpr int NT = BN / 16;

    extern __shared__ float sm[];
    const int tid = threadIdx.x;
    const int warp = tid >> 5, lane = tid & 31;
    const int qr = lane >> 2, ql = lane & 3;
    const int wm = warp >> 1, wn = warp & 1;
    const int mBase = blockIdx.x * BM;
    const uint32_t smBase = smem_u32(sm);

    if (APPLY_IN && tid < 128) {
        float scale = 1.f, shift = 0.f;
        if (tid < K) {
            float m = statsIn[tid] * invM;
            float v = statsIn[128 + tid] * invM - m * m;
            v = fmaxf(v, 0.f);
            float s = g1[tid] * rsqrtf(v + EPS);
            scale = s;
            shift = b1[tid] - m * s;
        }
        sm[tid] = scale;
        sm[128 + tid] = shift;
    }

    auto issue = [&](int s, int k0) {
        const int so = SOFFB + s * STGB;
        if (A_HALF) {
            const __half* A = (const __half*)Av;
#pragma unroll
            for (int j = 0; j < 2; j++) {
                int i = tid + 256 * j;
                int row = i >> 2, ch = i & 3;
                int gr = mBase + row;
                bool ok = gr < M;
                const __half* src =
                    A + (size_t)(ok ? gr : 0) * K + k0 + ch * 8;
                uint32_t dst = smBase + (uint32_t)(so + row * 80 + ch * 16);
                cp16(dst, src, ok ? 16 : 0);
            }
        } else {
            const float* A = (const float*)Av;
#pragma unroll
            for (int j = 0; j < 4; j++) {
                int i = tid + 256 * j;
                int row = i >> 3, ch = i & 7;
                int gr = mBase + row;
                bool ok = gr < M;
                const float* src =
                    A + (size_t)(ok ? gr : 0) * K + k0 + ch * 4;
                uint32_t dst = smBase + (uint32_t)(so + row * 144 + ch * 16);
                cp16(dst, src, ok ? 16 : 0);
            }
        }
#pragma unroll
        for (int j = 0; j < BK * BN / 4 / 256; j++) {
            int i = tid + 256 * j;
            int row = i / (BN / 4), c = i % (BN / 4);
            const float* src = B + (size_t)(k0 + row) * BN + c * 4;
            uint32_t dst = smBase +
                           (uint32_t)(so + ASZB + (row * (BN + 8) + c * 4) * 4);
            cp16(dst, src, 16);
        }
    };

    float acc[2][NT][4];
#pragma unroll
    for (int t = 0; t < 2; t++)
#pragma unroll
        for (int j = 0; j < NT; j++)
#pragma unroll
            for (int r = 0; r < 4; r++) acc[t][j][r] = 0.f;

    const int nCh = K / BK;
    issue(0, 0);
    cp_commit();

    for (int c = 0; c < nCh; c++) {
        if (c + 1 < nCh) issue((c + 1) & 1, (c + 1) * BK);
        cp_commit();
        cp_wait1();
        __syncthreads();

        const char* AsmB = (const char*)sm + SOFFB + (c & 1) * STGB;
        const uint32_t* Bsm = (const uint32_t*)(AsmB + ASZB);
#pragma unroll
        for (int ks = 0; ks < 4; ks++) {
            const int k = ks * 8;
            float s0 = 1.f, h0 = 0.f, s4 = 1.f, h4 = 0.f;
            if (APPLY_IN) {
                int kc = c * 32 + k + ql;
                s0 = sm[kc];
                h0 = sm[128 + kc];
                s4 = sm[kc + 4];
                h4 = sm[128 + kc + 4];
            }
            uint32_t a[2][4];
#pragma unroll
            for (int t = 0; t < 2; t++) {
                float v0, v1, v2, v3;
                int rbase = wm * 32 + t * 16 + qr;
                if (A_HALF) {
                    const __half* p =
                        (const __half*)AsmB + rbase * 40 + k + ql;
                    v0 = __half2float(p[0]);
                    v1 = __half2float(p[8 * 40]);
                    v2 = __half2float(p[4]);
                    v3 = __half2float(p[8 * 40 + 4]);
                } else {
                    const float* p = (const float*)AsmB + rbase * 36 + k + ql;
                    v0 = p[0];
                    v1 = p[8 * 36];
                    v2 = p[4];
                    v3 = p[8 * 36 + 4];
                }
                if (APPLY_IN) {
                    v0 = fmaxf(fmaf(v0, s0, h0), 0.f);
                    v1 = fmaxf(fmaf(v1, s0, h0), 0.f);
                    v2 = fmaxf(fmaf(v2, s4, h4), 0.f);
                    v3 = fmaxf(fmaf(v3, s4, h4), 0.f);
                }
                a[t][0] = f2tf_u(v0);
                a[t][1] = f2tf_u(v1);
                a[t][2] = f2tf_u(v2);
                a[t][3] = f2tf_u(v3);
            }
            uint32_t b[NT][2];
#pragma unroll
            for (int j = 0; j < NT; j++) {
                const uint32_t* p =
                    Bsm + (k + ql) * (BN + 8) + wn * (BN / 2) + j * 8 + qr;
                b[j][0] = p[0];
                b[j][1] = p[4 * (BN + 8)];
            }
#pragma unroll
            for (int t = 0; t < 2; t++)
#pragma unroll
                for (int j = 0; j < NT; j++) mma_tf32(acc[t][j], a[t], b[j]);
        }
        __syncthreads();
    }

    // ------------------ epilogue ------------------
    float ps[2 * NT], pq[2 * NT];
    if (EPI_STATS) {
#pragma unroll
        for (int i = 0; i < 2 * NT; i++) { ps[i] = 0.f; pq[i] = 0.f; }
    }

#pragma unroll
    for (int t = 0; t < 2; t++) {
#pragma unroll
        for (int rr = 0; rr < 2; rr++) {
            int row = mBase + wm * 32 + t * 16 + 8 * rr + qr;
            bool valid = row < M;
#pragma unroll
            for (int j = 0; j < NT; j++) {
                int n0 = wn * (BN / 2) + j * 8 + 2 * ql;
                float v0 = acc[t][j][2 * rr];
                float v1 = acc[t][j][2 * rr + 1];
                if (C_HALF) {
                    *reinterpret_cast<__half2*>(
                        (__half*)Cv + (size_t)row * BN + n0) =
                        __floats2half2_rn(v0, v1);
                } else {
                    *reinterpret_cast<float2*>(
                        (float*)Cv + (size_t)row * BN + n0) =
                        make_float2(v0, v1);
                }
                if (EPI_STATS && valid) {
                    ps[2 * j] += v0;
                    pq[2 * j] += v0 * v0;
                    ps[2 * j + 1] += v1;
                    pq[2 * j + 1] += v1 * v1;
                }
            }
        }
    }

    if (EPI_STATS) {
        __syncthreads();
        for (int i = tid; i < 2 * BN; i += 256) sm[i] = 0.f;
        __syncthreads();
#pragma unroll
        for (int j = 0; j < NT; j++) {
            int n0 = wn * (BN / 2) + j * 8 + 2 * ql;
            atomicAdd(&sm[n0], ps[2 * j]);
            atomicAdd(&sm[n0 + 1], ps[2 * j + 1]);
            atomicAdd(&sm[BN + n0], pq[2 * j]);
            atomicAdd(&sm[BN + n0 + 1], pq[2 * j + 1]);
        }
        __syncthreads();
        if (tid < BN) {
            atomicAdd(&statsOut[tid], sm[tid]);
            atomicAdd(&statsOut[128 + tid], sm[BN + tid]);
        }
    }
}

// ---------------------------------------------------------------------------
// Memory-phase kernels
// ---------------------------------------------------------------------------
__global__ void zero_kernel(float* __restrict__ p, size_t n) {
    size_t i = (size_t)blockIdx.x * blockDim.x + threadIdx.x;
    if (i < n) p[i] = 0.f;
}

__global__ void zero_nodeS_tail(float* __restrict__ nodeS) {
    int idx = blockIdx.x * blockDim.x + threadIdx.x;
    if (idx >= NNODES * 192) return;
    int a = idx / 192, c = idx - a * 192 + 128;
    nodeS[(size_t)a * 320 + c] = 0.f;
}

// merged tf32 rounding of all 4 weight matrices in one launch
__global__ void round_all_w(const float* __restrict__ w0, float* __restrict__ d0,
                            const float* __restrict__ w1, float* __restrict__ d1,
                            const float* __restrict__ w2, float* __restrict__ d2,
                            const float* __restrict__ w3, float* __restrict__ d3) {
    const int N0 = 704 * 128, N1 = 320 * 128, N2 = 128 * 64, N3 = 128 * 64;
    int i = blockIdx.x * blockDim.x + threadIdx.x;
    if (i < N0) {
        d0[i] = f2tf(w0[i]);
    } else if (i < N0 + N1) {
        int j = i - N0;
        d1[j] = f2tf(w1[j]);
    } else if (i < N0 + N1 + N2) {
        int j = i - N0 - N1;
        d2[j] = f2tf(w2[j]);
    } else if (i < N0 + N1 + N2 + N3) {
        int j = i - N0 - N1 - N2;
        d3[j] = f2tf(w3[j]);
    }
}

__global__ void count_atoms(const int* __restrict__ atoms,
                            float* __restrict__ cnt, int rows) {
    int i = blockIdx.x * blockDim.x + threadIdx.x;
    if (i < rows) atomicAdd(&cnt[atoms[i]], 1.f);
}

__global__ void scatter_add4(const float* __restrict__ src,
                             const int* __restrict__ atoms,
                             float* __restrict__ node, int rows, int C) {
    int C4 = C >> 2;
    int idx = blockIdx.x * blockDim.x + threadIdx.x;
    if (idx >= rows * C4) return;
    int r = idx / C4;
    int c = (idx - r * C4) << 2;
    float4 v = *reinterpret_cast<const float4*>(&src[(size_t)r * C + c]);
    float* dst = &node[(size_t)atoms[r] * C + c];
    atomicAdd(dst + 0, v.x);
    atomicAdd(dst + 1, v.y);
    atomicAdd(dst + 2, v.z);
    atomicAdd(dst + 3, v.w);
}

template <int G>
__global__ void bc_gather(const float* __restrict__ node,
                          const int* __restrict__ atoms,
                          float* __restrict__ out, int nCyc, int C) {
    int idx = blockIdx.x * blockDim.x + threadIdx.x;
    if (idx >= nCyc * C) return;
    int i = idx / C;
    int c = idx - i * C;
    float s = 0.f;
#pragma unroll
    for (int k = 0; k < G; k++) s += node[(size_t)atoms[i * G + k] * C + c];
    out[(size_t)i * C + c] = s;
}

template <int G>
__global__ void bc_scatter(const float* __restrict__ node64,
                           const int* __restrict__ atoms,
                           float* __restrict__ n128, int nCyc) {
    int idx = blockIdx.x * blockDim.x + threadIdx.x;
    if (idx >= nCyc * 64) return;
    int i = idx >> 6;
    int c = idx & 63;
    int a[G];
    float s = 0.f;
#pragma unroll
    for (int k = 0; k < G; k++) {
        a[k] = atoms[i * G + k];
        s += node64[(size_t)a[k] * 64 + c];
    }
#pragma unroll
    for (int k = 0; k < G; k++)
        atomicAdd(&n128[(size_t)a[k] * 128 + 64 + c], s);
}

__global__ void init_node128(const float* __restrict__ node64,
                             const float* __restrict__ cnt,
                             float* __restrict__ node128) {
    int idx = blockIdx.x * blockDim.x + threadIdx.x;
    if (idx >= NNODES * 64) return;
    int a = idx >> 6, c = idx & 63;
    float s = cnt[a];
    node128[(size_t)a * 128 + c] = s * node64[(size_t)a * 64 + c];
    node128[(size_t)a * 128 + 64 + c] = 0.f;
}

__global__ void add_nodeS(const float* __restrict__ n5,
                          const float* __restrict__ n6,
                          const float* __restrict__ c5,
                          const float* __restrict__ c6,
                          float* __restrict__ nodeS) {
    int idx = blockIdx.x * blockDim.x + threadIdx.x;
    if (idx >= NNODES * 128) return;
    int a = idx >> 7, c = idx & 127;
    nodeS[(size_t)a * 320 + c] =
        c5[a] * n5[(size_t)a * 128 + c] + c6[a] * n6[(size_t)a * 128 + c];
}

template <int G>
__global__ void scatter_grp4(const float* __restrict__ src,
                             const int* __restrict__ atoms,
                             float* __restrict__ dst, int rows, int C,
                             int pitch, int off) {
    int C4 = C >> 2;
    int idx = blockIdx.x * blockDim.x + threadIdx.x;
    if (idx >= rows * C4) return;
    int r = idx / C4;
    int c = (idx - r * C4) << 2;
    float4 v =
        *reinterpret_cast<const float4*>(&src[(size_t)(r / G) * C + c]);
    float* d = &dst[(size_t)atoms[r] * pitch + off + c];
    atomicAdd(d + 0, v.x);
    atomicAdd(d + 1, v.y);
    atomicAdd(d + 2, v.z);
    atomicAdd(d + 3, v.w);
}

__global__ void compose_edge(const __half* __restrict__ F,
                             const float* __restrict__ B,
                             const float* __restrict__ Bm,
                             const int* __restrict__ atoms,
                             __half* __restrict__ h,
                             float* __restrict__ stats) {
    int c = threadIdx.x;  // 128
    float s = 0.f, q = 0.f;
    for (int r = blockIdx.x; r < E_ROWS; r += gridDim.x) {
        int e = r >> 1;
        int a0 = atoms[2 * e], a1 = atoms[2 * e + 1];
        int self = (r & 1) ? a1 : a0;
        float v = __half2float(F[(size_t)r * 128 + c]) +
                  B[(size_t)self * 128 + c] + Bm[(size_t)a0 * 128 + c] +
                  Bm[(size_t)a1 * 128 + c];
        __half hv = __float2half_rn(v);
        h[(size_t)r * 128 + c] = hv;
        float vr = __half2float(hv);
        s += vr;
        q += vr * vr;
    }
    atomicAdd(&stats[c], s);
    atomicAdd(&stats[128 + c], q);
}

template <int G>
__global__ void compose_cyc(const __half* __restrict__ F,
                            const float* __restrict__ P,
                            const float* __restrict__ R,
                            const int* __restrict__ atoms,
                            __half* __restrict__ h, int rows,
                            float* __restrict__ stats) {
    int c = threadIdx.x;  // 128
    float s = 0.f, q = 0.f;
    for (int r = blockIdx.x; r < rows; r += gridDim.x) {
        int a = atoms[r];
        float v = __half2float(F[(size_t)r * 128 + c]) +
                  P[(size_t)a * 128 + c] + R[(size_t)(r / G) * 128 + c];
        __half hv = __float2half_rn(v);
        h[(size_t)r * 128 + c] = hv;
        float vr = __half2float(hv);
        s += vr;
        q += vr * vr;
    }
    atomicAdd(&stats[c], s);
    atomicAdd(&stats[128 + c], q);
}

__global__ void bn_relu_out(const __half* __restrict__ z,
                            const float* __restrict__ stats,
                            const float* __restrict__ g,
                            const float* __restrict__ b, float invM,
                            float* __restrict__ out, size_t n) {
    __shared__ float ss[128];
    int tid = threadIdx.x;
    if (tid < 64) {
        float m = stats[tid] * invM;
        float v = stats[128 + tid] * invM - m * m;
        v = fmaxf(v, 0.f);
        float s = g[tid] * rsqrtf(v + EPS);
        ss[tid] = s;
        ss[64 + tid] = b[tid] - m * s;
    }
    __syncthreads();
    size_t idx = (size_t)blockIdx.x * blockDim.x + tid;
    if (idx >= n) return;
    int c = (int)(idx & 63);
    out[idx] = fmaxf(__half2float(z[idx]) * ss[c] + ss[64 + c], 0.f);
}

// ---------------------------------------------------------------------------
// Host orchestration
// ---------------------------------------------------------------------------
static inline int cdiv(int a, int b) { return (a + b - 1) / b; }

static void* sym_addr(const void* s) {
    void* p = nullptr;
    cudaGetSymbolAddress(&p, s);
    return p;
}

static const int SMEM_F32_128 = 1024 + 2 * (128 * 144 + 32 * 136 * 4);  // 72704
static const int SMEM_F16_64 = 1024 + 2 * (128 * 80 + 32 * 72 * 4);     // 39936

extern "C" void kernel_launch(void* const* d_in, const int* in_sizes, int n_in,
                              void* d_out, int out_size) {
    static bool init_done = false;
    static cudaStream_t s1, s2;
    static cudaEvent_t evW, evNZ, evCnt, ev5, ev6, evD1, evD2;
    if (!init_done) {
        cudaFuncSetAttribute(gemm_mma<128, false, false, false, true>,
                             cudaFuncAttributeMaxDynamicSharedMemorySize,
                             SMEM_F32_128);
        cudaFuncSetAttribute(gemm_mma<128, false, false, false, false>,
                             cudaFuncAttributeMaxDynamicSharedMemorySize,
                             SMEM_F32_128);
        cudaFuncSetAttribute(gemm_mma<64, true, true, true, true>,
                             cudaFuncAttributeMaxDynamicSharedMemorySize,
                             SMEM_F16_64);
        cudaStreamCreateWithFlags(&s1, cudaStreamNonBlocking);
        cudaStreamCreateWithFlags(&s2, cudaStreamNonBlocking);
        cudaEventCreateWithFlags(&evW, cudaEventDisableTiming);
        cudaEventCreateWithFlags(&evNZ, cudaEventDisableTiming);
        cudaEventCreateWithFlags(&evCnt, cudaEventDisableTiming);
        cudaEventCreateWithFlags(&ev5, cudaEventDisableTiming);
        cudaEventCreateWithFlags(&ev6, cudaEventDisableTiming);
        cudaEventCreateWithFlags(&evD1, cudaEventDisableTiming);
        cudaEventCreateWithFlags(&evD2, cudaEventDisableTiming);
        init_done = true;
    }

    const float* edge_feats = (const float*)d_in[0];
    const float* c5_feats = (const float*)d_in[1];
    const float* c6_feats = (const float*)d_in[2];
    const int* e_atoms = (const int*)d_in[3];
    const int* c5_atoms = (const int*)d_in[4];
    const int* c6_atoms = (const int*)d_in[5];
    const float* eW1 = (const float*)d_in[6];
    const float* eg1 = (const float*)d_in[7];
    const float* eb1 = (const float*)d_in[8];
    const float* eW2 = (const float*)d_in[9];
    const float* eg2 = (const float*)d_in[10];
    const float* eb2 = (const float*)d_in[11];
    const float* cW1 = (const float*)d_in[12];
    const float* cg1 = (const float*)d_in[13];
    const float* cb1 = (const float*)d_in[14];
    const float* cW2 = (const float*)d_in[15];
    const float* cg2 = (const float*)d_in[16];
    const float* cb2 = (const float*)d_in[17];

    float* out_edge = (float*)d_out;
    float* out_c5 = out_edge + (size_t)E_ROWS * H;
    float* out_c6 = out_c5 + (size_t)C5_ROWS * H;

    float* node64 = (float*)sym_addr(g_node64);
    float* cnt5 = node64 + NNODES * 64;
    float* cnt6 = node64 + NNODES * 65;
    float* n128_5 = (float*)sym_addr(g_n128_5);
    float* n128_6 = (float*)sym_addr(g_n128_6);
    float* b2_5 = (float*)sym_addr(g_b2_5);
    float* b2_6 = (float*)sym_addr(g_b2_6);
    float* nodeS = (float*)sym_addr(g_nodeS);
    float* Bt = (float*)sym_addr(g_B);
    float* Bm = (float*)sym_addr(g_Bm);
    float* P5 = (float*)sym_addr(g_P5);
    float* P6 = (float*)sym_addr(g_P6);
    float* R5 = (float*)sym_addr(g_R5);
    float* R6 = (float*)sym_addr(g_R6);
    __half* Fe = (__half*)sym_addr(g_Fe);
    __half* F5 = (__half*)sym_addr(g_F5);
    __half* F6 = (__half*)sym_addr(g_F6);
    __half* he = (__half*)sym_addr(g_he);
    __half* h5 = (__half*)sym_addr(g_h5);
    __half* h6 = (__half*)sym_addr(g_h6);
    __half* ze = (__half*)sym_addr(g_ze);
    __half* z5 = (__half*)sym_addr(g_z5);
    __half* z6 = (__half*)sym_addr(g_z6);
    float* wE1 = (float*)sym_addr(g_wE1);
    float* wE2 = (float*)sym_addr(g_wE2);
    float* wC1 = (float*)sym_addr(g_wC1);
    float* wC2 = (float*)sym_addr(g_wC2);
    float* stats = (float*)sym_addr(g_stats);
    float* stE1 = stats;
    float* stE2 = stats + 256;
    float* st51 = stats + 512;
    float* st52 = stats + 768;
    float* st61 = stats + 1024;
    float* st62 = stats + 1280;

    const int TB = 256;

    // ---- main prologue ----
    round_all_w<<<cdiv(704 * 128 + 320 * 128 + 2 * 128 * 64, TB), TB>>>(
        eW1, wE1, cW1, wC1, eW2, wE2, cW2, wC2);
    cudaEventRecord(evW, 0);
    zero_kernel<<<cdiv(6 * 256, TB), TB>>>(stats, 6 * 256);
    zero_nodeS_tail<<<cdiv(NNODES * 192, TB), TB>>>(nodeS);
    cudaEventRecord(evNZ, 0);
    zero_kernel<<<cdiv(NNODES * 66, TB), TB>>>(node64, (size_t)NNODES * 66);
    scatter_add4<<<cdiv(E_ROWS * 16, TB), TB>>>(edge_feats, e_atoms, node64,
                                                E_ROWS, 64);
    count_atoms<<<cdiv(C5_ROWS, TB), TB>>>(c5_atoms, cnt5, C5_ROWS);
    count_atoms<<<cdiv(C6_ROWS, TB), TB>>>(c6_atoms, cnt6, C6_ROWS);
    cudaEventRecord(evCnt, 0);

    // ---- s1: cycle5 pipeline ----
    cudaStreamWaitEvent(s1, evW, 0);
    gemm_mma<128, false, false, false, true>
        <<<cdiv(C5_ROWS, 128), 256, SMEM_F32_128, s1>>>(
            c5_feats, wC1 + 256 * 128, F5, C5_ROWS, 64, nullptr, nullptr,
            nullptr, 0.f, nullptr);
    cudaStreamWaitEvent(s1, evNZ, 0);
    scatter_grp4<1><<<cdiv(C5_ROWS * 16, TB), TB, 0, s1>>>(
        c5_feats, c5_atoms, nodeS, C5_ROWS, 64, 320, 256);
    cudaStreamWaitEvent(s1, evCnt, 0);
    init_node128<<<cdiv(NNODES * 64, TB), TB, 0, s1>>>(node64, cnt5, n128_5);
    bc_scatter<5><<<cdiv(NC5 * 64, TB), TB, 0, s1>>>(node64, c5_atoms,
                                                     n128_5, NC5);
    bc_gather<5><<<cdiv(NC5 * 128, TB), TB, 0, s1>>>(n128_5, c5_atoms, b2_5,
                                                     NC5, 128);
    scatter_grp4<5><<<cdiv(C5_ROWS * 32, TB), TB, 0, s1>>>(
        b2_5, c5_atoms, nodeS, C5_ROWS, 128, 320, 128);
    cudaEventRecord(ev5, s1);
    gemm_mma<128, false, false, false, false>
        <<<cdiv(NNODES, 128), 256, SMEM_F32_128, s1>>>(
            n128_5, wC1, P5, NNODES, 128, nullptr, nullptr, nullptr, 0.f,
            nullptr);
    gemm_mma<128, false, false, false, false>
        <<<cdiv(NC5, 128), 256, SMEM_F32_128, s1>>>(
            b2_5, wC1 + 128 * 128, R5, NC5, 128, nullptr, nullptr, nullptr,
            0.f, nullptr);
    compose_cyc<5><<<2048, 128, 0, s1>>>(F5, P5, R5, c5_atoms, h5, C5_ROWS,
                                         st51);
    gemm_mma<64, true, true, true, true>
        <<<cdiv(C5_ROWS, 128), 256, SMEM_F16_64, s1>>>(
            h5, wC2, z5, C5_ROWS, 128, st51, cg1, cb1, 1.f / C5_ROWS, st52);
    bn_relu_out<<<cdiv(C5_ROWS * 64, TB), TB, 0, s1>>>(
        z5, st52, cg2, cb2, 1.f / C5_ROWS, out_c5, (size_t)C5_ROWS * 64);
    cudaEventRecord(evD1, s1);

    // ---- s2: cycle6 pipeline ----
    cudaStreamWaitEvent(s2, evW, 0);
    gemm_mma<128, false, false, false, true>
        <<<cdiv(C6_ROWS, 128), 256, SMEM_F32_128, s2>>>(
            c6_feats, wC1 + 256 * 128, F6, C6_ROWS, 64, nullptr, nullptr,
            nullptr, 0.f, nullptr);
    cudaStreamWaitEvent(s2, evNZ, 0);
    scatter_grp4<1><<<cdiv(C6_ROWS * 16, TB), TB, 0, s2>>>(
        c6_feats, c6_atoms, nodeS, C6_ROWS, 64, 320, 256);
    cudaStreamWaitEvent(s2, evCnt, 0);
    init_node128<<<cdiv(NNODES * 64, TB), TB, 0, s2>>>(node64, cnt6, n128_6);
    bc_scatter<6><<<cdiv(NC6 * 64, TB), TB, 0, s2>>>(node64, c6_atoms,
                                                     n128_6, NC6);
    bc_gather<6><<<cdiv(NC6 * 128, TB), TB, 0, s2>>>(n128_6, c6_atoms, b2_6,
                                                     NC6, 128);
    scatter_grp4<6><<<cdiv(C6_ROWS * 32, TB), TB, 0, s2>>>(
        b2_6, c6_atoms, nodeS, C6_ROWS, 128, 320, 128);
    cudaEventRecord(ev6, s2);
    gemm_mma<128, false, false, false, false>
        <<<cdiv(NNODES, 128), 256, SMEM_F32_128, s2>>>(
            n128_6, wC1, P6, NNODES, 128, nullptr, nullptr, nullptr, 0.f,
            nullptr);
    gemm_mma<128, false, false, false, false>
        <<<cdiv(NC6, 128), 256, SMEM_F32_128, s2>>>(
            b2_6, wC1 + 128 * 128, R6, NC6, 128, nullptr, nullptr, nullptr,
            0.f, nullptr);
    compose_cyc<6><<<2048, 128, 0, s2>>>(F6, P6, R6, c6_atoms, h6, C6_ROWS,
                                         st61);
    gemm_mma<64, true, true, true, true>
        <<<cdiv(C6_ROWS, 128), 256, SMEM_F16_64, s2>>>(
            h6, wC2, z6, C6_ROWS, 128, st61, cg1, cb1, 1.f / C6_ROWS, st62);
    bn_relu_out<<<cdiv(C6_ROWS * 64, TB), TB, 0, s2>>>(
        z6, st62, cg2, cb2, 1.f / C6_ROWS, out_c6, (size_t)C6_ROWS * 64);
    cudaEventRecord(evD2, s2);

    // ---- main: edge path ----
    gemm_mma<128, false, false, false, true>
        <<<cdiv(E_ROWS, 128), 256, SMEM_F32_128>>>(
            edge_feats, wE1, Fe, E_ROWS, 64, nullptr, nullptr, nullptr, 0.f,
            nullptr);
    cudaStreamWaitEvent(0, ev5, 0);
    cudaStreamWaitEvent(0, ev6, 0);
    add_nodeS<<<cdiv(NNODES * 128, TB), TB>>>(n128_5, n128_6, cnt5, cnt6,
                                              nodeS);
    gemm_mma<128, false, false, false, false>
        <<<cdiv(NNODES, 128), 256, SMEM_F32_128>>>(
            nodeS, wE1 + 64 * 128, Bt, NNODES, 320, nullptr, nullptr, nullptr,
            0.f, nullptr);
    gemm_mma<128, false, false, false, false>
        <<<cdiv(NNODES, 128), 256, SMEM_F32_128>>>(
            nodeS, wE1 + 384 * 128, Bm, NNODES, 320, nullptr, nullptr,
            nullptr, 0.f, nullptr);
    compose_edge<<<2048, 128>>>(Fe, Bt, Bm, e_atoms, he, stE1);
    gemm_mma<64, true, true, true, true>
        <<<cdiv(E_ROWS, 128), 256, SMEM_F16_64>>>(
            he, wE2, ze, E_ROWS, 128, stE1, eg1, eb1, 1.f / E_ROWS, stE2);
    bn_relu_out<<<cdiv(E_ROWS * 64, TB), TB>>>(ze, stE2, eg2, eb2,
                                               1.f / E_ROWS, out_edge,
                                               (size_t)E_ROWS * 64);

    // ---- join ----
    cudaStreamWaitEvent(0, evD1, 0);
    cudaStreamWaitEvent(0, evD2, 0);

    (void)in_sizes;
    (void)n_in;
    (void)out_size;
}

// round 17
// speedup vs baseline: 1.3136x; 1.0151x over previous
#include <cuda_runtime.h>
#include <cuda_fp16.h>
#include <cstdint>

// ---------------------------------------------------------------------------
// Problem constants
// ---------------------------------------------------------------------------
#define H 64
#define NNODES 40000
#define NE 60000
#define NC5 30000
#define NC6 25000
#define E_ROWS (2 * NE)      // 120000
#define C5_ROWS (5 * NC5)    // 150000
#define C6_ROWS (6 * NC6)    // 150000
#define EPS 1e-5f

#define PAD_E  120064
#define PAD_N  40064
#define PAD_R  30080
#define PAD_F  150016

// ---------------------------------------------------------------------------
// Device scratch
// ---------------------------------------------------------------------------
__device__ float g_node64[NNODES * 66];   // node64 | cnt5 | cnt6
__device__ float g_n128_5[NNODES * 128];
__device__ float g_n128_6[NNODES * 128];
__device__ float g_b2_5[NC5 * 128];
__device__ float g_b2_6[NC6 * 128];
__device__ float g_nodeS[NNODES * 320];
__device__ __half g_B[PAD_N * 128];       // fp16 tables (compose-only)
__device__ __half g_Bm[PAD_N * 128];
__device__ __half g_P5[PAD_N * 128];
__device__ __half g_P6[PAD_N * 128];
__device__ __half g_R5[PAD_R * 128];
__device__ __half g_R6[PAD_R * 128];
__device__ __half g_Fe[PAD_E * 128];
__device__ __half g_F5[PAD_F * 128];
__device__ __half g_F6[PAD_F * 128];
__device__ __half g_he[PAD_E * 128];
__device__ __half g_h5[PAD_F * 128];
__device__ __half g_h6[PAD_F * 128];
__device__ __half g_ze[PAD_E * 64];
__device__ __half g_z5[PAD_F * 64];
__device__ __half g_z6[PAD_F * 64];
__device__ float g_wE1[704 * 128];        // tf32-rounded weights
__device__ float g_wE2[128 * 64];
__device__ float g_wC1[320 * 128];
__device__ float g_wC2[128 * 64];
__device__ float g_stats[6 * 256];

// ---------------------------------------------------------------------------
// Helpers
// ---------------------------------------------------------------------------
__device__ __forceinline__ uint32_t smem_u32(const void* p) {
    uint32_t a;
    asm("{ .reg .u64 t; cvta.to.shared.u64 t, %1; cvt.u32.u64 %0, t; }"
        : "=r"(a) : "l"(p));
    return a;
}

__device__ __forceinline__ float f2tf(float x) {
    uint32_t r;
    asm("cvt.rna.tf32.f32 %0, %1;" : "=r"(r) : "f"(x));
    return __uint_as_float(r);
}

__device__ __forceinline__ uint32_t f2tf_u(float x) {
    uint32_t r;
    asm("cvt.rna.tf32.f32 %0, %1;" : "=r"(r) : "f"(x));
    return r;
}

__device__ __forceinline__ void cp16(uint32_t dst, const void* src, int nbytes) {
    asm volatile("cp.async.ca.shared.global [%0], [%1], 16, %2;"
                 :: "r"(dst), "l"(src), "r"(nbytes) : "memory");
}
__device__ __forceinline__ void cp_commit() {
    asm volatile("cp.async.commit_group;" ::: "memory");
}
__device__ __forceinline__ void cp_wait1() {
    asm volatile("cp.async.wait_group 1;" ::: "memory");
}

__device__ __forceinline__ void mma_tf32(float* d, const uint32_t* a,
                                         const uint32_t* b) {
    asm volatile(
        "mma.sync.aligned.m16n8k8.row.col.f32.tf32.tf32.f32 "
        "{%0,%1,%2,%3}, {%4,%5,%6,%7}, {%8,%9}, {%0,%1,%2,%3};"
        : "+f"(d[0]), "+f"(d[1]), "+f"(d[2]), "+f"(d[3])
        : "r"(a[0]), "r"(a[1]), "r"(a[2]), "r"(a[3]), "r"(b[0]), "r"(b[1]));
}

// ---------------------------------------------------------------------------
// tf32 mma.sync GEMM (round-13 geometry + dtype flags).
// ---------------------------------------------------------------------------
template <int BN, bool APPLY_IN, bool EPI_STATS, bool A_HALF, bool C_HALF>
__global__ void __launch_bounds__(256)
gemm_mma(const void* __restrict__ Av, const float* __restrict__ B,
         void* __restrict__ Cv, int M, int K,
         const float* __restrict__ statsIn, const float* __restrict__ g1,
         const float* __restrict__ b1, float invM,
         float* __restrict__ statsOut) {
    constexpr int BM = 128, BK = 32;
    constexpr int A_ROWB = A_HALF ? 80 : 144;
    constexpr int ASZB = BM * A_ROWB;
    constexpr int BSZB = BK * (BN + 8) * 4;
    constexpr int STGB = ASZB + BSZB;
    constexpr int SOFFB = 1024;
    constexpr int NT = BN / 16;

    extern __shared__ float sm[];
    const int tid = threadIdx.x;
    const int warp = tid >> 5, lane = tid & 31;
    const int qr = lane >> 2, ql = lane & 3;
    const int wm = warp >> 1, wn = warp & 1;
    const int mBase = blockIdx.x * BM;
    const uint32_t smBase = smem_u32(sm);

    if (APPLY_IN && tid < 128) {
        float scale = 1.f, shift = 0.f;
        if (tid < K) {
            float m = statsIn[tid] * invM;
            float v = statsIn[128 + tid] * invM - m * m;
            v = fmaxf(v, 0.f);
            float s = g1[tid] * rsqrtf(v + EPS);
            scale = s;
            shift = b1[tid] - m * s;
        }
        sm[tid] = scale;
        sm[128 + tid] = shift;
    }

    auto issue = [&](int s, int k0) {
        const int so = SOFFB + s * STGB;
        if (A_HALF) {
            const __half* A = (const __half*)Av;
#pragma unroll
            for (int j = 0; j < 2; j++) {
                int i = tid + 256 * j;
                int row = i >> 2, ch = i & 3;
                int gr = mBase + row;
                bool ok = gr < M;
                const __half* src =
                    A + (size_t)(ok ? gr : 0) * K + k0 + ch * 8;
                uint32_t dst = smBase + (uint32_t)(so + row * 80 + ch * 16);
                cp16(dst, src, ok ? 16 : 0);
            }
        } else {
            const float* A = (const float*)Av;
#pragma unroll
            for (int j = 0; j < 4; j++) {
                int i = tid + 256 * j;
                int row = i >> 3, ch = i & 7;
                int gr = mBase + row;
                bool ok = gr < M;
                const float* src =
                    A + (size_t)(ok ? gr : 0) * K + k0 + ch * 4;
                uint32_t dst = smBase + (uint32_t)(so + row * 144 + ch * 16);
                cp16(dst, src, ok ? 16 : 0);
            }
        }
#pragma unroll
        for (int j = 0; j < BK * BN / 4 / 256; j++) {
            int i = tid + 256 * j;
            int row = i / (BN / 4), c = i % (BN / 4);
            const float* src = B + (size_t)(k0 + row) * BN + c * 4;
            uint32_t dst = smBase +
                           (uint32_t)(so + ASZB + (row * (BN + 8) + c * 4) * 4);
            cp16(dst, src, 16);
        }
    };

    float acc[2][NT][4];
#pragma unroll
    for (int t = 0; t < 2; t++)
#pragma unroll
        for (int j = 0; j < NT; j++)
#pragma unroll
            for (int r = 0; r < 4; r++) acc[t][j][r] = 0.f;

    const int nCh = K / BK;
    issue(0, 0);
    cp_commit();

    for (int c = 0; c < nCh; c++) {
        if (c + 1 < nCh) issue((c + 1) & 1, (c + 1) * BK);
        cp_commit();
        cp_wait1();
        __syncthreads();

        const char* AsmB = (const char*)sm + SOFFB + (c & 1) * STGB;
        const uint32_t* Bsm = (const uint32_t*)(AsmB + ASZB);
#pragma unroll
        for (int ks = 0; ks < 4; ks++) {
            const int k = ks * 8;
            float s0 = 1.f, h0 = 0.f, s4 = 1.f, h4 = 0.f;
            if (APPLY_IN) {
                int kc = c * 32 + k + ql;
                s0 = sm[kc];
                h0 = sm[128 + kc];
                s4 = sm[kc + 4];
                h4 = sm[128 + kc + 4];
            }
            uint32_t a[2][4];
#pragma unroll
            for (int t = 0; t < 2; t++) {
                float v0, v1, v2, v3;
                int rbase = wm * 32 + t * 16 + qr;
                if (A_HALF) {
                    const __half* p =
                        (const __half*)AsmB + rbase * 40 + k + ql;
                    v0 = __half2float(p[0]);
                    v1 = __half2float(p[8 * 40]);
                    v2 = __half2float(p[4]);
                    v3 = __half2float(p[8 * 40 + 4]);
                } else {
                    const float* p = (const float*)AsmB + rbase * 36 + k + ql;
                    v0 = p[0];
                    v1 = p[8 * 36];
                    v2 = p[4];
                    v3 = p[8 * 36 + 4];
                }
                if (APPLY_IN) {
                    v0 = fmaxf(fmaf(v0, s0, h0), 0.f);
                    v1 = fmaxf(fmaf(v1, s0, h0), 0.f);
                    v2 = fmaxf(fmaf(v2, s4, h4), 0.f);
                    v3 = fmaxf(fmaf(v3, s4, h4), 0.f);
                }
                a[t][0] = f2tf_u(v0);
                a[t][1] = f2tf_u(v1);
                a[t][2] = f2tf_u(v2);
                a[t][3] = f2tf_u(v3);
            }
            uint32_t b[NT][2];
#pragma unroll
            for (int j = 0; j < NT; j++) {
                const uint32_t* p =
                    Bsm + (k + ql) * (BN + 8) + wn * (BN / 2) + j * 8 + qr;
                b[j][0] = p[0];
                b[j][1] = p[4 * (BN + 8)];
            }
#pragma unroll
            for (int t = 0; t < 2; t++)
#pragma unroll
                for (int j = 0; j < NT; j++) mma_tf32(acc[t][j], a[t], b[j]);
        }
        __syncthreads();
    }

    // ------------------ epilogue ------------------
    float ps[2 * NT], pq[2 * NT];
    if (EPI_STATS) {
#pragma unroll
        for (int i = 0; i < 2 * NT; i++) { ps[i] = 0.f; pq[i] = 0.f; }
    }

#pragma unroll
    for (int t = 0; t < 2; t++) {
#pragma unroll
        for (int rr = 0; rr < 2; rr++) {
            int row = mBase + wm * 32 + t * 16 + 8 * rr + qr;
            bool valid = row < M;
#pragma unroll
            for (int j = 0; j < NT; j++) {
                int n0 = wn * (BN / 2) + j * 8 + 2 * ql;
                float v0 = acc[t][j][2 * rr];
                float v1 = acc[t][j][2 * rr + 1];
                if (C_HALF) {
                    *reinterpret_cast<__half2*>(
                        (__half*)Cv + (size_t)row * BN + n0) =
                        __floats2half2_rn(v0, v1);
                } else {
                    *reinterpret_cast<float2*>(
                        (float*)Cv + (size_t)row * BN + n0) =
                        make_float2(v0, v1);
                }
                if (EPI_STATS && valid) {
                    ps[2 * j] += v0;
                    pq[2 * j] += v0 * v0;
                    ps[2 * j + 1] += v1;
                    pq[2 * j + 1] += v1 * v1;
                }
            }
        }
    }

    if (EPI_STATS) {
        __syncthreads();
        for (int i = tid; i < 2 * BN; i += 256) sm[i] = 0.f;
        __syncthreads();
#pragma unroll
        for (int j = 0; j < NT; j++) {
            int n0 = wn * (BN / 2) + j * 8 + 2 * ql;
            atomicAdd(&sm[n0], ps[2 * j]);
            atomicAdd(&sm[n0 + 1], ps[2 * j + 1]);
            atomicAdd(&sm[BN + n0], pq[2 * j]);
            atomicAdd(&sm[BN + n0 + 1], pq[2 * j + 1]);
        }
        __syncthreads();
        if (tid < BN) {
            atomicAdd(&statsOut[tid], sm[tid]);
            atomicAdd(&statsOut[128 + tid], sm[BN + tid]);
        }
    }
}

// ---------------------------------------------------------------------------
// Memory-phase kernels
// ---------------------------------------------------------------------------
__global__ void zero_kernel(float* __restrict__ p, size_t n) {
    size_t i = (size_t)blockIdx.x * blockDim.x + threadIdx.x;
    if (i < n) p[i] = 0.f;
}

__global__ void zero_nodeS_tail(float* __restrict__ nodeS) {
    int idx = blockIdx.x * blockDim.x + threadIdx.x;
    if (idx >= NNODES * 192) return;
    int a = idx / 192, c = idx - a * 192 + 128;
    nodeS[(size_t)a * 320 + c] = 0.f;
}

__global__ void round_all_w(const float* __restrict__ w0, float* __restrict__ d0,
                            const float* __restrict__ w1, float* __restrict__ d1,
                            const float* __restrict__ w2, float* __restrict__ d2,
                            const float* __restrict__ w3, float* __restrict__ d3) {
    const int N0 = 704 * 128, N1 = 320 * 128, N2 = 128 * 64, N3 = 128 * 64;
    int i = blockIdx.x * blockDim.x + threadIdx.x;
    if (i < N0) {
        d0[i] = f2tf(w0[i]);
    } else if (i < N0 + N1) {
        int j = i - N0;
        d1[j] = f2tf(w1[j]);
    } else if (i < N0 + N1 + N2) {
        int j = i - N0 - N1;
        d2[j] = f2tf(w2[j]);
    } else if (i < N0 + N1 + N2 + N3) {
        int j = i - N0 - N1 - N2;
        d3[j] = f2tf(w3[j]);
    }
}

__global__ void count_atoms(const int* __restrict__ atoms,
                            float* __restrict__ cnt, int rows) {
    int i = blockIdx.x * blockDim.x + threadIdx.x;
    if (i < rows) atomicAdd(&cnt[atoms[i]], 1.f);
}

__global__ void scatter_add4(const float* __restrict__ src,
                             const int* __restrict__ atoms,
                             float* __restrict__ node, int rows, int C) {
    int C4 = C >> 2;
    int idx = blockIdx.x * blockDim.x + threadIdx.x;
    if (idx >= rows * C4) return;
    int r = idx / C4;
    int c = (idx - r * C4) << 2;
    float4 v = *reinterpret_cast<const float4*>(&src[(size_t)r * C + c]);
    float* dst = &node[(size_t)atoms[r] * C + c];
    atomicAdd(dst + 0, v.x);
    atomicAdd(dst + 1, v.y);
    atomicAdd(dst + 2, v.z);
    atomicAdd(dst + 3, v.w);
}

template <int G>
__global__ void bc_gather(const float* __restrict__ node,
                          const int* __restrict__ atoms,
                          float* __restrict__ out, int nCyc, int C) {
    int idx = blockIdx.x * blockDim.x + threadIdx.x;
    if (idx >= nCyc * C) return;
    int i = idx / C;
    int c = idx - i * C;
    float s = 0.f;
#pragma unroll
    for (int k = 0; k < G; k++) s += node[(size_t)atoms[i * G + k] * C + c];
    out[(size_t)i * C + c] = s;
}

template <int G>
__global__ void bc_scatter(const float* __restrict__ node64,
                           const int* __restrict__ atoms,
                           float* __restrict__ n128, int nCyc) {
    int idx = blockIdx.x * blockDim.x + threadIdx.x;
    if (idx >= nCyc * 64) return;
    int i = idx >> 6;
    int c = idx & 63;
    int a[G];
    float s = 0.f;
#pragma unroll
    for (int k = 0; k < G; k++) {
        a[k] = atoms[i * G + k];
        s += node64[(size_t)a[k] * 64 + c];
    }
#pragma unroll
    for (int k = 0; k < G; k++)
        atomicAdd(&n128[(size_t)a[k] * 128 + 64 + c], s);
}

__global__ void init_node128(const float* __restrict__ node64,
                             const float* __restrict__ cnt,
                             float* __restrict__ node128) {
    int idx = blockIdx.x * blockDim.x + threadIdx.x;
    if (idx >= NNODES * 64) return;
    int a = idx >> 6, c = idx & 63;
    float s = cnt[a];
    node128[(size_t)a * 128 + c] = s * node64[(size_t)a * 64 + c];
    node128[(size_t)a * 128 + 64 + c] = 0.f;
}

__global__ void add_nodeS(const float* __restrict__ n5,
                          const float* __restrict__ n6,
                          const float* __restrict__ c5,
                          const float* __restrict__ c6,
                          float* __restrict__ nodeS) {
    int idx = blockIdx.x * blockDim.x + threadIdx.x;
    if (idx >= NNODES * 128) return;
    int a = idx >> 7, c = idx & 127;
    nodeS[(size_t)a * 320 + c] =
        c5[a] * n5[(size_t)a * 128 + c] + c6[a] * n6[(size_t)a * 128 + c];
}

template <int G>
__global__ void scatter_grp4(const float* __restrict__ src,
                             const int* __restrict__ atoms,
                             float* __restrict__ dst, int rows, int C,
                             int pitch, int off) {
    int C4 = C >> 2;
    int idx = blockIdx.x * blockDim.x + threadIdx.x;
    if (idx >= rows * C4) return;
    int r = idx / C4;
    int c = (idx - r * C4) << 2;
    float4 v =
        *reinterpret_cast<const float4*>(&src[(size_t)(r / G) * C + c]);
    float* d = &dst[(size_t)atoms[r] * pitch + off + c];
    atomicAdd(d + 0, v.x);
    atomicAdd(d + 1, v.y);
    atomicAdd(d + 2, v.z);
    atomicAdd(d + 3, v.w);
}

// composes (fp16 tables)
__global__ void compose_edge(const __half* __restrict__ F,
                             const __half* __restrict__ B,
                             const __half* __restrict__ Bm,
                             const int* __restrict__ atoms,
                             __half* __restrict__ h,
                             float* __restrict__ stats) {
    int c = threadIdx.x;  // 128
    float s = 0.f, q = 0.f;
    for (int r = blockIdx.x; r < E_ROWS; r += gridDim.x) {
        int e = r >> 1;
        int a0 = atoms[2 * e], a1 = atoms[2 * e + 1];
        int self = (r & 1) ? a1 : a0;
        float v = __half2float(F[(size_t)r * 128 + c]) +
                  __half2float(B[(size_t)self * 128 + c]) +
                  __half2float(Bm[(size_t)a0 * 128 + c]) +
                  __half2float(Bm[(size_t)a1 * 128 + c]);
        __half hv = __float2half_rn(v);
        h[(size_t)r * 128 + c] = hv;
        float vr = __half2float(hv);
        s += vr;
        q += vr * vr;
    }
    atomicAdd(&stats[c], s);
    atomicAdd(&stats[128 + c], q);
}

template <int G>
__global__ void compose_cyc(const __half* __restrict__ F,
                            const __half* __restrict__ P,
                            const __half* __restrict__ R,
                            const int* __restrict__ atoms,
                            __half* __restrict__ h, int rows,
                            float* __restrict__ stats) {
    int c = threadIdx.x;  // 128
    float s = 0.f, q = 0.f;
    for (int r = blockIdx.x; r < rows; r += gridDim.x) {
        int a = atoms[r];
        float v = __half2float(F[(size_t)r * 128 + c]) +
                  __half2float(P[(size_t)a * 128 + c]) +
                  __half2float(R[(size_t)(r / G) * 128 + c]);
        __half hv = __float2half_rn(v);
        h[(size_t)r * 128 + c] = hv;
        float vr = __half2float(hv);
        s += vr;
        q += vr * vr;
    }
    atomicAdd(&stats[c], s);
    atomicAdd(&stats[128 + c], q);
}

__global__ void bn_relu_out(const __half* __restrict__ z,
                            const float* __restrict__ stats,
                            const float* __restrict__ g,
                            const float* __restrict__ b, float invM,
                            float* __restrict__ out, size_t n) {
    __shared__ float ss[128];
    int tid = threadIdx.x;
    if (tid < 64) {
        float m = stats[tid] * invM;
        float v = stats[128 + tid] * invM - m * m;
        v = fmaxf(v, 0.f);
        float s = g[tid] * rsqrtf(v + EPS);
        ss[tid] = s;
        ss[64 + tid] = b[tid] - m * s;
    }
    __syncthreads();
    size_t idx = (size_t)blockIdx.x * blockDim.x + tid;
    if (idx >= n) return;
    int c = (int)(idx & 63);
    out[idx] = fmaxf(__half2float(z[idx]) * ss[c] + ss[64 + c], 0.f);
}

// ---------------------------------------------------------------------------
// Host orchestration
// ---------------------------------------------------------------------------
static inline int cdiv(int a, int b) { return (a + b - 1) / b; }

static void* sym_addr(const void* s) {
    void* p = nullptr;
    cudaGetSymbolAddress(&p, s);
    return p;
}

static const int SMEM_F32_128 = 1024 + 2 * (128 * 144 + 32 * 136 * 4);  // 72704
static const int SMEM_F16_64 = 1024 + 2 * (128 * 80 + 32 * 72 * 4);     // 39936

extern "C" void kernel_launch(void* const* d_in, const int* in_sizes, int n_in,
                              void* d_out, int out_size) {
    static bool init_done = false;
    static cudaStream_t s1, s2;
    static cudaEvent_t evW, evNZ, evCnt, ev5, ev6, evD1, evD2;
    if (!init_done) {
        cudaFuncSetAttribute(gemm_mma<128, false, false, false, true>,
                             cudaFuncAttributeMaxDynamicSharedMemorySize,
                             SMEM_F32_128);
        cudaFuncSetAttribute(gemm_mma<64, true, true, true, true>,
                             cudaFuncAttributeMaxDynamicSharedMemorySize,
                             SMEM_F16_64);
        cudaStreamCreateWithFlags(&s1, cudaStreamNonBlocking);
        cudaStreamCreateWithFlags(&s2, cudaStreamNonBlocking);
        cudaEventCreateWithFlags(&evW, cudaEventDisableTiming);
        cudaEventCreateWithFlags(&evNZ, cudaEventDisableTiming);
        cudaEventCreateWithFlags(&evCnt, cudaEventDisableTiming);
        cudaEventCreateWithFlags(&ev5, cudaEventDisableTiming);
        cudaEventCreateWithFlags(&ev6, cudaEventDisableTiming);
        cudaEventCreateWithFlags(&evD1, cudaEventDisableTiming);
        cudaEventCreateWithFlags(&evD2, cudaEventDisableTiming);
        init_done = true;
    }

    const float* edge_feats = (const float*)d_in[0];
    const float* c5_feats = (const float*)d_in[1];
    const float* c6_feats = (const float*)d_in[2];
    const int* e_atoms = (const int*)d_in[3];
    const int* c5_atoms = (const int*)d_in[4];
    const int* c6_atoms = (const int*)d_in[5];
    const float* eW1 = (const float*)d_in[6];
    const float* eg1 = (const float*)d_in[7];
    const float* eb1 = (const float*)d_in[8];
    const float* eW2 = (const float*)d_in[9];
    const float* eg2 = (const float*)d_in[10];
    const float* eb2 = (const float*)d_in[11];
    const float* cW1 = (const float*)d_in[12];
    const float* cg1 = (const float*)d_in[13];
    const float* cb1 = (const float*)d_in[14];
    const float* cW2 = (const float*)d_in[15];
    const float* cg2 = (const float*)d_in[16];
    const float* cb2 = (const float*)d_in[17];

    float* out_edge = (float*)d_out;
    float* out_c5 = out_edge + (size_t)E_ROWS * H;
    float* out_c6 = out_c5 + (size_t)C5_ROWS * H;

    float* node64 = (float*)sym_addr(g_node64);
    float* cnt5 = node64 + NNODES * 64;
    float* cnt6 = node64 + NNODES * 65;
    float* n128_5 = (float*)sym_addr(g_n128_5);
    float* n128_6 = (float*)sym_addr(g_n128_6);
    float* b2_5 = (float*)sym_addr(g_b2_5);
    float* b2_6 = (float*)sym_addr(g_b2_6);
    float* nodeS = (float*)sym_addr(g_nodeS);
    __half* Bt = (__half*)sym_addr(g_B);
    __half* Bm = (__half*)sym_addr(g_Bm);
    __half* P5 = (__half*)sym_addr(g_P5);
    __half* P6 = (__half*)sym_addr(g_P6);
    __half* R5 = (__half*)sym_addr(g_R5);
    __half* R6 = (__half*)sym_addr(g_R6);
    __half* Fe = (__half*)sym_addr(g_Fe);
    __half* F5 = (__half*)sym_addr(g_F5);
    __half* F6 = (__half*)sym_addr(g_F6);
    __half* he = (__half*)sym_addr(g_he);
    __half* h5 = (__half*)sym_addr(g_h5);
    __half* h6 = (__half*)sym_addr(g_h6);
    __half* ze = (__half*)sym_addr(g_ze);
    __half* z5 = (__half*)sym_addr(g_z5);
    __half* z6 = (__half*)sym_addr(g_z6);
    float* wE1 = (float*)sym_addr(g_wE1);
    float* wE2 = (float*)sym_addr(g_wE2);
    float* wC1 = (float*)sym_addr(g_wC1);
    float* wC2 = (float*)sym_addr(g_wC2);
    float* stats = (float*)sym_addr(g_stats);
    float* stE1 = stats;
    float* stE2 = stats + 256;
    float* st51 = stats + 512;
    float* st52 = stats + 768;
    float* st61 = stats + 1024;
    float* st62 = stats + 1280;

    const int TB = 256;

    // ---- main prologue ----
    round_all_w<<<cdiv(704 * 128 + 320 * 128 + 2 * 128 * 64, TB), TB>>>(
        eW1, wE1, cW1, wC1, eW2, wE2, cW2, wC2);
    cudaEventRecord(evW, 0);
    zero_kernel<<<cdiv(6 * 256, TB), TB>>>(stats, 6 * 256);
    zero_nodeS_tail<<<cdiv(NNODES * 192, TB), TB>>>(nodeS);
    cudaEventRecord(evNZ, 0);
    zero_kernel<<<cdiv(NNODES * 66, TB), TB>>>(node64, (size_t)NNODES * 66);
    scatter_add4<<<cdiv(E_ROWS * 16, TB), TB>>>(edge_feats, e_atoms, node64,
                                                E_ROWS, 64);
    count_atoms<<<cdiv(C5_ROWS, TB), TB>>>(c5_atoms, cnt5, C5_ROWS);
    count_atoms<<<cdiv(C6_ROWS, TB), TB>>>(c6_atoms, cnt6, C6_ROWS);
    cudaEventRecord(evCnt, 0);

    // ---- s1: cycle5 pipeline ----
    cudaStreamWaitEvent(s1, evW, 0);
    gemm_mma<128, false, false, false, true>
        <<<cdiv(C5_ROWS, 128), 256, SMEM_F32_128, s1>>>(
            c5_feats, wC1 + 256 * 128, F5, C5_ROWS, 64, nullptr, nullptr,
            nullptr, 0.f, nullptr);
    cudaStreamWaitEvent(s1, evNZ, 0);
    scatter_grp4<1><<<cdiv(C5_ROWS * 16, TB), TB, 0, s1>>>(
        c5_feats, c5_atoms, nodeS, C5_ROWS, 64, 320, 256);
    cudaStreamWaitEvent(s1, evCnt, 0);
    init_node128<<<cdiv(NNODES * 64, TB), TB, 0, s1>>>(node64, cnt5, n128_5);
    bc_scatter<5><<<cdiv(NC5 * 64, TB), TB, 0, s1>>>(node64, c5_atoms,
                                                     n128_5, NC5);
    bc_gather<5><<<cdiv(NC5 * 128, TB), TB, 0, s1>>>(n128_5, c5_atoms, b2_5,
                                                     NC5, 128);
    scatter_grp4<5><<<cdiv(C5_ROWS * 32, TB), TB, 0, s1>>>(
        b2_5, c5_atoms, nodeS, C5_ROWS, 128, 320, 128);
    cudaEventRecord(ev5, s1);
    gemm_mma<128, false, false, false, true>
        <<<cdiv(NNODES, 128), 256, SMEM_F32_128, s1>>>(
            n128_5, wC1, P5, NNODES, 128, nullptr, nullptr, nullptr, 0.f,
            nullptr);
    gemm_mma<128, false, false, false, true>
        <<<cdiv(NC5, 128), 256, SMEM_F32_128, s1>>>(
            b2_5, wC1 + 128 * 128, R5, NC5, 128, nullptr, nullptr, nullptr,
            0.f, nullptr);
    compose_cyc<5><<<2048, 128, 0, s1>>>(F5, P5, R5, c5_atoms, h5, C5_ROWS,
                                         st51);
    gemm_mma<64, true, true, true, true>
        <<<cdiv(C5_ROWS, 128), 256, SMEM_F16_64, s1>>>(
            h5, wC2, z5, C5_ROWS, 128, st51, cg1, cb1, 1.f / C5_ROWS, st52);
    bn_relu_out<<<cdiv(C5_ROWS * 64, TB), TB, 0, s1>>>(
        z5, st52, cg2, cb2, 1.f / C5_ROWS, out_c5, (size_t)C5_ROWS * 64);
    cudaEventRecord(evD1, s1);

    // ---- s2: cycle6 pipeline ----
    cudaStreamWaitEvent(s2, evW, 0);
    gemm_mma<128, false, false, false, true>
        <<<cdiv(C6_ROWS, 128), 256, SMEM_F32_128, s2>>>(
            c6_feats, wC1 + 256 * 128, F6, C6_ROWS, 64, nullptr, nullptr,
            nullptr, 0.f, nullptr);
    cudaStreamWaitEvent(s2, evNZ, 0);
    scatter_grp4<1><<<cdiv(C6_ROWS * 16, TB), TB, 0, s2>>>(
        c6_feats, c6_atoms, nodeS, C6_ROWS, 64, 320, 256);
    cudaStreamWaitEvent(s2, evCnt, 0);
    init_node128<<<cdiv(NNODES * 64, TB), TB, 0, s2>>>(node64, cnt6, n128_6);
    bc_scatter<6><<<cdiv(NC6 * 64, TB), TB, 0, s2>>>(node64, c6_atoms,
                                                     n128_6, NC6);
    bc_gather<6><<<cdiv(NC6 * 128, TB), TB, 0, s2>>>(n128_6, c6_atoms, b2_6,
                                                     NC6, 128);
    scatter_grp4<6><<<cdiv(C6_ROWS * 32, TB), TB, 0, s2>>>(
        b2_6, c6_atoms, nodeS, C6_ROWS, 128, 320, 128);
    cudaEventRecord(ev6, s2);
    gemm_mma<128, false, false, false, true>
        <<<cdiv(NNODES, 128), 256, SMEM_F32_128, s2>>>(
            n128_6, wC1, P6, NNODES, 128, nullptr, nullptr, nullptr, 0.f,
            nullptr);
    gemm_mma<128, false, false, false, true>
        <<<cdiv(NC6, 128), 256, SMEM_F32_128, s2>>>(
            b2_6, wC1 + 128 * 128, R6, NC6, 128, nullptr, nullptr, nullptr,
            0.f, nullptr);
    compose_cyc<6><<<2048, 128, 0, s2>>>(F6, P6, R6, c6_atoms, h6, C6_ROWS,
                                         st61);
    gemm_mma<64, true, true, true, true>
        <<<cdiv(C6_ROWS, 128), 256, SMEM_F16_64, s2>>>(
            h6, wC2, z6, C6_ROWS, 128, st61, cg1, cb1, 1.f / C6_ROWS, st62);
    bn_relu_out<<<cdiv(C6_ROWS * 64, TB), TB, 0, s2>>>(
        z6, st62, cg2, cb2, 1.f / C6_ROWS, out_c6, (size_t)C6_ROWS * 64);
    cudaEventRecord(evD2, s2);

    // ---- main: edge path ----
    gemm_mma<128, false, false, false, true>
        <<<cdiv(E_ROWS, 128), 256, SMEM_F32_128>>>(
            edge_feats, wE1, Fe, E_ROWS, 64, nullptr, nullptr, nullptr, 0.f,
            nullptr);
    cudaStreamWaitEvent(0, ev5, 0);
    cudaStreamWaitEvent(0, ev6, 0);
    add_nodeS<<<cdiv(NNODES * 128, TB), TB>>>(n128_5, n128_6, cnt5, cnt6,
                                              nodeS);
    gemm_mma<128, false, false, false, true>
        <<<cdiv(NNODES, 128), 256, SMEM_F32_128>>>(
            nodeS, wE1 + 64 * 128, Bt, NNODES, 320, nullptr, nullptr, nullptr,
            0.f, nullptr);
    gemm_mma<128, false, false, false, true>
        <<<cdiv(NNODES, 128), 256, SMEM_F32_128>>>(
            nodeS, wE1 + 384 * 128, Bm, NNODES, 320, nullptr, nullptr,
            nullptr, 0.f, nullptr);
    compose_edge<<<2048, 128>>>(Fe, Bt, Bm, e_atoms, he, stE1);
    gemm_mma<64, true, true, true, true>
        <<<cdiv(E_ROWS, 128), 256, SMEM_F16_64>>>(
            he, wE2, ze, E_ROWS, 128, stE1, eg1, eb1, 1.f / E_ROWS, stE2);
    bn_relu_out<<<cdiv(E_ROWS * 64, TB), TB>>>(ze, stE2, eg2, eb2,
                                               1.f / E_ROWS, out_edge,
                                               (size_t)E_ROWS * 64);

    // ---- join ----
    cudaStreamWaitEvent(0, evD1, 0);
    cudaStreamWaitEvent(0, evD2, 0);

    (void)in_sizes;
    (void)n_in;
    (void)out_size;
}